// round 4
// baseline (speedup 1.0000x reference)
#include <cuda_runtime.h>
#include <math.h>
#include <stdint.h>

// ---------------- problem constants ----------------
#define BATCH 8
#define L1 2048
#define L2 2048
#define D1 1024
#define D2 768
#define EDIM 1024
#define ROWS1 (BATCH * L1)          // 16384
#define ROWS2 (BATCH * L2)          // 16384

// ---------------- scratch (device globals; no allocation) ----------------
__device__ float g_x1[ROWS1 * D1];
__device__ float g_x2[ROWS2 * D2];
__device__ float g_q[ROWS1 * EDIM];
__device__ float g_k[ROWS2 * EDIM];
__device__ float g_vT[(size_t)EDIM * ROWS2];     // [E, 16384] row pitch 16384
__device__ float g_s[(size_t)BATCH * L1 * L2];   // scores / attn
__device__ float g_ctx[ROWS1 * EDIM];
__device__ float g_wqT[EDIM * D1];
__device__ float g_wkT[EDIM * D2];
__device__ float g_wvT[EDIM * D2];
__device__ float g_woT[D1 * EDIM];

// ---------------- helpers ----------------
static __device__ __forceinline__ uint32_t smem_u32(const void* p) {
    uint32_t a;
    asm("{ .reg .u64 t; cvta.to.shared.u64 t, %1; cvt.u32.u64 %0, t; }" : "=r"(a) : "l"(p));
    return a;
}
static __device__ __forceinline__ float f2tf32f(float x) {
    uint32_t y; asm("cvt.rna.tf32.f32 %0, %1;" : "=r"(y) : "f"(x));
    return __uint_as_float(y);
}
static __device__ __forceinline__ void cp_async16(uint32_t saddr, const void* gptr) {
    asm volatile("cp.async.cg.shared.global [%0], [%1], 16;" :: "r"(saddr), "l"(gptr));
}
static __device__ __forceinline__ void cp_commit() {
    asm volatile("cp.async.commit_group;" ::: "memory");
}
template<int N>
static __device__ __forceinline__ void cp_wait() {
    asm volatile("cp.async.wait_group %0;" :: "n"(N) : "memory");
}

#define MMA_TF32(d, a, b) \
    asm volatile("mma.sync.aligned.m16n8k8.row.col.f32.tf32.tf32.f32 " \
        "{%0,%1,%2,%3}, {%4,%5,%6,%7}, {%8,%9}, {%0,%1,%2,%3};" \
        : "+f"((d)[0]), "+f"((d)[1]), "+f"((d)[2]), "+f"((d)[3]) \
        : "r"((a)[0]), "r"((a)[1]), "r"((a)[2]), "r"((a)[3]), \
          "r"((b)[0]), "r"((b)[1]))

// ================= tf32 mma.sync GEMM =================
// C[M,N] = scale*(A[M,K] @ B[N,K]^T) + bias;  A,B K-major with pitches ldA/ldB.
// BM=128, BN=256, BK=16. 256 threads = 8 warps (2M x 4N), warp tile 64x64.
// Smem row stride 20 words -> conflict-free LDS.32 fragments. 4-stage cp.async.
#define STAGES 4
#define AW 2560                     // words per A stage (128*20)
#define BW 5120                     // words per B stage (256*20)
#define STW (AW + BW)               // 7680
#define GSMEM (STAGES * STW * 4)    // 122880 bytes

static __device__ __forceinline__ void load_stage(
    uint32_t sb, const float* __restrict__ A, const float* __restrict__ B,
    int ldA, int ldB, int k0, int st, int tid) {
    const int r = tid >> 2, c4 = (tid & 3) * 4;
    const uint32_t base = sb + (uint32_t)(st * STW) * 4;
    #pragma unroll
    for (int f = 0; f < 2; f++) {
        int row = r + f * 64;
        cp_async16(base + (uint32_t)(row * 20 + c4) * 4, A + (size_t)row * ldA + k0 + c4);
    }
    #pragma unroll
    for (int f = 0; f < 4; f++) {
        int row = r + f * 64;
        cp_async16(base + (uint32_t)(AW + row * 20 + c4) * 4, B + (size_t)row * ldB + k0 + c4);
    }
}

__global__ void __launch_bounds__(256, 1)
gemm_mma(const float* __restrict__ A, const float* __restrict__ B,
         const float* __restrict__ bias, float* __restrict__ C,
         int K, int ldA, int ldB, int ldC,
         float scale, int round_out, int bias_mode,
         long long sA, long long sB, long long sC) {
    extern __shared__ uint32_t sm[];
    const uint32_t sb = smem_u32(sm);
    const int tid = threadIdx.x;
    const int lane = tid & 31, warp = tid >> 5;
    const int g = lane >> 2, t = lane & 3;
    const int m0 = (warp >> 2) * 64;       // warp M offset (0,64)
    const int n0 = (warp & 3) * 64;        // warp N offset (0..192)

    A += (long long)blockIdx.z * sA + (size_t)blockIdx.y * 128 * ldA;
    B += (long long)blockIdx.z * sB + (size_t)blockIdx.x * 256 * ldB;
    C += (long long)blockIdx.z * sC;

    float acc[4][8][4];
    #pragma unroll
    for (int i = 0; i < 4; i++)
        #pragma unroll
        for (int j = 0; j < 8; j++)
            #pragma unroll
            for (int e = 0; e < 4; e++) acc[i][j][e] = 0.f;

    const int nch = K >> 4;

    #pragma unroll
    for (int s = 0; s < STAGES - 1; s++) {
        load_stage(sb, A, B, ldA, ldB, s * 16, s, tid);
        cp_commit();
    }

    for (int i = 0; i < nch; i++) {
        cp_wait<STAGES - 2>();
        __syncthreads();

        {
            const int ic = i + STAGES - 1;
            if (ic < nch)
                load_stage(sb, A, B, ldA, ldB, ic * 16, ic % STAGES, tid);
            cp_commit();
        }

        const uint32_t* __restrict__ smA = sm + (i % STAGES) * STW;
        const uint32_t* __restrict__ smB = smA + AW;
        #pragma unroll
        for (int ks = 0; ks < 2; ks++) {
            const int kk = ks * 8;
            uint32_t af[4][4], bf[8][2];
            #pragma unroll
            for (int ii = 0; ii < 4; ii++) {
                const int mr = m0 + ii * 16 + g;
                af[ii][0] = smA[mr * 20 + kk + t];
                af[ii][1] = smA[(mr + 8) * 20 + kk + t];
                af[ii][2] = smA[mr * 20 + kk + t + 4];
                af[ii][3] = smA[(mr + 8) * 20 + kk + t + 4];
            }
            #pragma unroll
            for (int jj = 0; jj < 8; jj++) {
                const int nr = n0 + jj * 8 + g;
                bf[jj][0] = smB[nr * 20 + kk + t];
                bf[jj][1] = smB[nr * 20 + kk + t + 4];
            }
            #pragma unroll
            for (int ii = 0; ii < 4; ii++)
                #pragma unroll
                for (int jj = 0; jj < 8; jj++)
                    MMA_TF32(acc[ii][jj], af[ii], bf[jj]);
        }
        __syncthreads();
    }

    // epilogue
    const int row_base = blockIdx.y * 128 + m0 + g;
    const int col_base = blockIdx.x * 256 + n0 + t * 2;
    #pragma unroll
    for (int ii = 0; ii < 4; ii++) {
        const int r0 = row_base + ii * 16;
        float rb0 = 0.f, rb1 = 0.f;
        if (bias_mode == 2) { rb0 = __ldg(bias + r0); rb1 = __ldg(bias + r0 + 8); }
        #pragma unroll
        for (int jj = 0; jj < 8; jj++) {
            const int col = col_base + jj * 8;
            float bx0, by0, bx1, by1;
            if (bias_mode == 1) {
                float cb0 = __ldg(bias + col), cb1 = __ldg(bias + col + 1);
                bx0 = cb0; by0 = cb1; bx1 = cb0; by1 = cb1;
            } else {
                bx0 = rb0; by0 = rb0; bx1 = rb1; by1 = rb1;
            }
            float2 v0, v1;
            v0.x = acc[ii][jj][0] * scale + bx0;
            v0.y = acc[ii][jj][1] * scale + by0;
            v1.x = acc[ii][jj][2] * scale + bx1;
            v1.y = acc[ii][jj][3] * scale + by1;
            if (round_out) {
                v0.x = f2tf32f(v0.x); v0.y = f2tf32f(v0.y);
                v1.x = f2tf32f(v1.x); v1.y = f2tf32f(v1.y);
            }
            *(float2*)(C + (size_t)r0 * ldC + col) = v0;
            *(float2*)(C + (size_t)(r0 + 8) * ldC + col) = v1;
        }
    }
}

// ================= layernorm / softmax / transpose =================
static __device__ __forceinline__ float blockReduceSum256(float v) {
    __shared__ float sh[8];
    int lane = threadIdx.x & 31, w = threadIdx.x >> 5;
    #pragma unroll
    for (int o = 16; o > 0; o >>= 1) v += __shfl_xor_sync(0xffffffffu, v, o);
    __syncthreads();
    if (lane == 0) sh[w] = v;
    __syncthreads();
    if (w == 0) {
        v = (lane < 8) ? sh[lane] : 0.f;
        #pragma unroll
        for (int o = 4; o > 0; o >>= 1) v += __shfl_xor_sync(0xffffffffu, v, o);
        if (lane == 0) sh[0] = v;
    }
    __syncthreads();
    return sh[0];
}
static __device__ __forceinline__ float blockReduceMax256(float v) {
    __shared__ float sh[8];
    int lane = threadIdx.x & 31, w = threadIdx.x >> 5;
    #pragma unroll
    for (int o = 16; o > 0; o >>= 1) v = fmaxf(v, __shfl_xor_sync(0xffffffffu, v, o));
    __syncthreads();
    if (lane == 0) sh[w] = v;
    __syncthreads();
    if (w == 0) {
        v = (lane < 8) ? sh[lane] : -INFINITY;
        #pragma unroll
        for (int o = 4; o > 0; o >>= 1) v = fmaxf(v, __shfl_xor_sync(0xffffffffu, v, o));
        if (lane == 0) sh[0] = v;
    }
    __syncthreads();
    return sh[0];
}

template<int NV>
__global__ __launch_bounds__(256)
void layernorm_kernel(const float* __restrict__ x, const float* __restrict__ g,
                      const float* __restrict__ b, float* __restrict__ y, int D) {
    const size_t row = blockIdx.x;
    const float* xr = x + row * (size_t)D;
    float*       yr = y + row * (size_t)D;
    float v[NV];
    float s = 0.f;
    #pragma unroll
    for (int j = 0; j < NV; j++) { v[j] = xr[threadIdx.x + j * 256]; s += v[j]; }
    const float mu = blockReduceSum256(s) * (1.f / (float)D);
    float sq = 0.f;
    #pragma unroll
    for (int j = 0; j < NV; j++) { float d = v[j] - mu; sq += d * d; }
    const float rstd = rsqrtf(blockReduceSum256(sq) * (1.f / (float)D) + 1e-5f);
    #pragma unroll
    for (int j = 0; j < NV; j++) {
        int idx = threadIdx.x + j * 256;
        yr[idx] = f2tf32f((v[j] - mu) * rstd * g[idx] + b[idx]);
    }
}

__global__ __launch_bounds__(256)
void softmax_kernel(float* __restrict__ s) {
    const size_t row = blockIdx.x;
    float4* p = (float4*)(s + row * (size_t)L2);
    float4 a = p[threadIdx.x];
    float4 b = p[threadIdx.x + 256];
    float m = fmaxf(fmaxf(fmaxf(a.x, a.y), fmaxf(a.z, a.w)),
                    fmaxf(fmaxf(b.x, b.y), fmaxf(b.z, b.w)));
    m = blockReduceMax256(m);
    a.x = __expf(a.x - m); a.y = __expf(a.y - m);
    a.z = __expf(a.z - m); a.w = __expf(a.w - m);
    b.x = __expf(b.x - m); b.y = __expf(b.y - m);
    b.z = __expf(b.z - m); b.w = __expf(b.w - m);
    float sum = (a.x + a.y + a.z + a.w) + (b.x + b.y + b.z + b.w);
    const float inv = 1.f / blockReduceSum256(sum);
    a.x = f2tf32f(a.x * inv); a.y = f2tf32f(a.y * inv);
    a.z = f2tf32f(a.z * inv); a.w = f2tf32f(a.w * inv);
    b.x = f2tf32f(b.x * inv); b.y = f2tf32f(b.y * inv);
    b.z = f2tf32f(b.z * inv); b.w = f2tf32f(b.w * inv);
    p[threadIdx.x] = a;
    p[threadIdx.x + 256] = b;
}

// out[C,R] = in[R,C]^T (tf32-rounded) — weights only (small)
__global__ __launch_bounds__(256)
void transpose_kernel(const float* __restrict__ in, float* __restrict__ out,
                      int R, int C) {
    __shared__ float tb[32][33];
    const int r0 = blockIdx.y * 32, c0 = blockIdx.x * 32;
    const int tx = threadIdx.x & 31, ty = threadIdx.x >> 5;
    #pragma unroll
    for (int k = 0; k < 32; k += 8)
        tb[ty + k][tx] = in[(size_t)(r0 + ty + k) * C + c0 + tx];
    __syncthreads();
    #pragma unroll
    for (int k = 0; k < 32; k += 8)
        out[(size_t)(c0 + ty + k) * R + r0 + tx] = f2tf32f(tb[tx][ty + k]);
}

// ================= launch =================
extern "C" void kernel_launch(void* const* d_in, const int* in_sizes, int n_in,
                              void* d_out, int out_size) {
    const float* modality1 = (const float*)d_in[0];
    const float* modality2 = (const float*)d_in[1];
    const float* ln1_g = (const float*)d_in[2];
    const float* ln1_b = (const float*)d_in[3];
    const float* ln2_g = (const float*)d_in[4];
    const float* ln2_b = (const float*)d_in[5];
    const float* Wq = (const float*)d_in[6];
    const float* bq = (const float*)d_in[7];
    const float* Wk = (const float*)d_in[8];
    const float* bk = (const float*)d_in[9];
    const float* Wv = (const float*)d_in[10];
    const float* bv = (const float*)d_in[11];
    const float* Wo = (const float*)d_in[12];
    const float* bo = (const float*)d_in[13];
    float* out = (float*)d_out;

    float *x1, *x2, *q, *k, *vT, *s, *ctx, *wqT, *wkT, *wvT, *woT;
    cudaGetSymbolAddress((void**)&x1, g_x1);
    cudaGetSymbolAddress((void**)&x2, g_x2);
    cudaGetSymbolAddress((void**)&q, g_q);
    cudaGetSymbolAddress((void**)&k, g_k);
    cudaGetSymbolAddress((void**)&vT, g_vT);
    cudaGetSymbolAddress((void**)&s, g_s);
    cudaGetSymbolAddress((void**)&ctx, g_ctx);
    cudaGetSymbolAddress((void**)&wqT, g_wqT);
    cudaGetSymbolAddress((void**)&wkT, g_wkT);
    cudaGetSymbolAddress((void**)&wvT, g_wvT);
    cudaGetSymbolAddress((void**)&woT, g_woT);

    cudaFuncSetAttribute(gemm_mma, cudaFuncAttributeMaxDynamicSharedMemorySize, GSMEM);

    const float scaling = 1.0f / 32.0f;   // E^-0.5

    // 1) layernorms (tf32-rounded outputs)
    layernorm_kernel<4><<<ROWS1, 256>>>(modality1, ln1_g, ln1_b, x1, D1);
    layernorm_kernel<3><<<ROWS2, 256>>>(modality2, ln2_g, ln2_b, x2, D2);

    // 2) weight transposes -> K-major [N,K], tf32-rounded
    transpose_kernel<<<dim3(EDIM / 32, D1 / 32), 256>>>(Wq, wqT, D1, EDIM);
    transpose_kernel<<<dim3(EDIM / 32, D2 / 32), 256>>>(Wk, wkT, D2, EDIM);
    transpose_kernel<<<dim3(EDIM / 32, D2 / 32), 256>>>(Wv, wvT, D2, EDIM);
    transpose_kernel<<<dim3(D1 / 32, EDIM / 32), 256>>>(Wo, woT, EDIM, D1);

    // 3) Q/K projections: C[M,N]=A@B^T, N=E
    gemm_mma<<<dim3(EDIM / 256, ROWS1 / 128), 256, GSMEM>>>(
        x1, wqT, bq, q, D1, D1, D1, EDIM, 1.f, 1, 1, 0, 0, 0);
    gemm_mma<<<dim3(EDIM / 256, ROWS2 / 128), 256, GSMEM>>>(
        x2, wkT, bk, k, D2, D2, D2, EDIM, 1.f, 1, 1, 0, 0, 0);

    // 3b) vT[E, 16384] = Wv^T @ x2^T + bv (row bias) — replaces V proj + transpose
    gemm_mma<<<dim3(ROWS2 / 256, EDIM / 128), 256, GSMEM>>>(
        wvT, x2, bv, vT, D2, D2, D2, ROWS2, 1.f, 1, 2, 0, 0, 0);

    // 4) scores = scaling * Q @ K^T (batched)
    gemm_mma<<<dim3(L2 / 256, L1 / 128, BATCH), 256, GSMEM>>>(
        q, k, nullptr, s, EDIM, EDIM, EDIM, L2, scaling, 0, 0,
        (long long)L1 * EDIM, (long long)L2 * EDIM, (long long)L1 * L2);

    // 5) softmax rows (tf32-rounded output)
    softmax_kernel<<<BATCH * L1, 256>>>(s);

    // 6) ctx = attn @ V  (B = vT slice per batch, pitch 16384)
    gemm_mma<<<dim3(EDIM / 256, L1 / 128, BATCH), 256, GSMEM>>>(
        s, vT, nullptr, ctx, L2, L2, ROWS2, EDIM, 1.f, 1, 0,
        (long long)L1 * L2, (long long)L2, (long long)L1 * EDIM);

    // 7) out = ctx @ Wo + bo (fp32 output)
    gemm_mma<<<dim3(D1 / 256, ROWS1 / 128), 256, GSMEM>>>(
        ctx, woT, bo, out, EDIM, EDIM, EDIM, D1, 1.f, 0, 1, 0, 0, 0);
}

// round 5
// speedup vs baseline: 1.1124x; 1.1124x over previous
#include <cuda_runtime.h>
#include <math.h>
#include <stdint.h>

// ---------------- problem constants ----------------
#define BATCH 8
#define L1 2048
#define L2 2048
#define D1 1024
#define D2 768
#define EDIM 1024
#define ROWS1 (BATCH * L1)          // 16384
#define ROWS2 (BATCH * L2)          // 16384

// ---------------- scratch (device globals; no allocation) ----------------
__device__ float g_x1[ROWS1 * D1];
__device__ float g_x2[ROWS2 * D2];
__device__ float g_q[ROWS1 * EDIM];
__device__ float g_k[ROWS2 * EDIM];
__device__ float g_vT[(size_t)EDIM * ROWS2];     // [E, 16384] row pitch 16384
__device__ float g_s[(size_t)BATCH * L1 * L2];   // scores / attn
__device__ float g_ctx[ROWS1 * EDIM];
__device__ float g_wqT[EDIM * D1];
__device__ float g_wkT[EDIM * D2];
__device__ float g_wvT[EDIM * D2];
__device__ float g_woT[D1 * EDIM];

// ---------------- helpers ----------------
static __device__ __forceinline__ uint32_t smem_u32(const void* p) {
    uint32_t a;
    asm("{ .reg .u64 t; cvta.to.shared.u64 t, %1; cvt.u32.u64 %0, t; }" : "=r"(a) : "l"(p));
    return a;
}
static __device__ __forceinline__ float f2tf32f(float x) {
    uint32_t y; asm("cvt.rna.tf32.f32 %0, %1;" : "=r"(y) : "f"(x));
    return __uint_as_float(y);
}
static __device__ __forceinline__ void cp_async16(uint32_t saddr, const void* gptr) {
    asm volatile("cp.async.cg.shared.global [%0], [%1], 16;" :: "r"(saddr), "l"(gptr));
}
static __device__ __forceinline__ void cp_commit() {
    asm volatile("cp.async.commit_group;" ::: "memory");
}
template<int N>
static __device__ __forceinline__ void cp_wait() {
    asm volatile("cp.async.wait_group %0;" :: "n"(N) : "memory");
}

#define MMA_TF32(d, a, b) \
    asm volatile("mma.sync.aligned.m16n8k8.row.col.f32.tf32.tf32.f32 " \
        "{%0,%1,%2,%3}, {%4,%5,%6,%7}, {%8,%9}, {%0,%1,%2,%3};" \
        : "+f"((d)[0]), "+f"((d)[1]), "+f"((d)[2]), "+f"((d)[3]) \
        : "r"((a)[0]), "r"((a)[1]), "r"((a)[2]), "r"((a)[3]), \
          "r"((b)[0]), "r"((b)[1]))

// ================= tf32 mma.sync GEMM (R3 engine, generalized pitches) =================
// C[M,N] = scale*(A[M,K] @ B[N,K]^T) + bias;  A,B K-major with pitches ldA/ldB.
// BM=128, BN=128, BK=16. 128 threads = 4 warps (2x2), warp tile 64x64.
// Smem row stride 20 words -> conflict-free LDS.32 fragments. 3-stage, 2 CTAs/SM.
#define STAGES 3
#define AW 2560                    // words per A stage (128*20)
#define STW 5120                   // words per stage (A+B)
#define GSMEM (STAGES * STW * 4)   // 61440 bytes

__global__ void __launch_bounds__(128, 2)
gemm_mma(const float* __restrict__ A, const float* __restrict__ B,
         const float* __restrict__ bias, float* __restrict__ C,
         int K, int ldA, int ldB, int ldC,
         float scale, int round_out, int bias_mode,
         long long sA, long long sB, long long sC) {
    extern __shared__ uint32_t sm[];
    const uint32_t sb = smem_u32(sm);
    const int tid = threadIdx.x;
    const int lane = tid & 31, warp = tid >> 5;
    const int g = lane >> 2, t = lane & 3;
    const int m0 = (warp >> 1) * 64;       // warp M offset in tile
    const int n0 = (warp & 1) * 64;        // warp N offset in tile

    A += (long long)blockIdx.z * sA + (size_t)blockIdx.y * 128 * ldA;
    B += (long long)blockIdx.z * sB + (size_t)blockIdx.x * 128 * ldB;
    C += (long long)blockIdx.z * sC;

    const int r_ld = tid >> 2;             // base row (0..31), +32 per f
    const int c_ld = (tid & 3) * 4;        // word offset in K

    float acc[4][8][4];
    #pragma unroll
    for (int i = 0; i < 4; i++)
        #pragma unroll
        for (int j = 0; j < 8; j++)
            #pragma unroll
            for (int e = 0; e < 4; e++) acc[i][j][e] = 0.f;

    const int nch = K >> 4;

    #pragma unroll
    for (int s = 0; s < STAGES - 1; s++) {
        const int k0 = s * 16;
        #pragma unroll
        for (int f = 0; f < 4; f++) {
            int row = r_ld + f * 32;
            cp_async16(sb + (s * STW + row * 20 + c_ld) * 4,
                       A + (size_t)row * ldA + k0 + c_ld);
            cp_async16(sb + (s * STW + AW + row * 20 + c_ld) * 4,
                       B + (size_t)row * ldB + k0 + c_ld);
        }
        cp_commit();
    }

    for (int i = 0; i < nch; i++) {
        cp_wait<STAGES - 2>();
        __syncthreads();

        {
            const int ic = i + STAGES - 1;
            if (ic < nch) {
                const int st = ic % STAGES;
                const int k0 = ic * 16;
                #pragma unroll
                for (int f = 0; f < 4; f++) {
                    int row = r_ld + f * 32;
                    cp_async16(sb + (st * STW + row * 20 + c_ld) * 4,
                               A + (size_t)row * ldA + k0 + c_ld);
                    cp_async16(sb + (st * STW + AW + row * 20 + c_ld) * 4,
                               B + (size_t)row * ldB + k0 + c_ld);
                }
            }
            cp_commit();
        }

        const uint32_t* __restrict__ smA = sm + (i % STAGES) * STW;
        const uint32_t* __restrict__ smB = smA + AW;
        #pragma unroll
        for (int ks = 0; ks < 2; ks++) {
            const int kk = ks * 8;
            uint32_t af[4][4], bf[8][2];
            #pragma unroll
            for (int ii = 0; ii < 4; ii++) {
                const int mr = m0 + ii * 16 + g;
                af[ii][0] = smA[mr * 20 + kk + t];
                af[ii][1] = smA[(mr + 8) * 20 + kk + t];
                af[ii][2] = smA[mr * 20 + kk + t + 4];
                af[ii][3] = smA[(mr + 8) * 20 + kk + t + 4];
            }
            #pragma unroll
            for (int jj = 0; jj < 8; jj++) {
                const int nr = n0 + jj * 8 + g;
                bf[jj][0] = smB[nr * 20 + kk + t];
                bf[jj][1] = smB[nr * 20 + kk + t + 4];
            }
            #pragma unroll
            for (int ii = 0; ii < 4; ii++)
                #pragma unroll
                for (int jj = 0; jj < 8; jj++)
                    MMA_TF32(acc[ii][jj], af[ii], bf[jj]);
        }
        __syncthreads();
    }

    // epilogue
    const int row_base = blockIdx.y * 128 + m0 + g;
    const int col_base = blockIdx.x * 128 + n0 + t * 2;
    #pragma unroll
    for (int ii = 0; ii < 4; ii++) {
        const int r0 = row_base + ii * 16;
        float rb0 = 0.f, rb1 = 0.f;
        if (bias_mode == 2) { rb0 = __ldg(bias + r0); rb1 = __ldg(bias + r0 + 8); }
        #pragma unroll
        for (int jj = 0; jj < 8; jj++) {
            const int col = col_base + jj * 8;
            float bx0, by0, bx1, by1;
            if (bias_mode == 1) {
                float cb0 = __ldg(bias + col), cb1 = __ldg(bias + col + 1);
                bx0 = cb0; by0 = cb1; bx1 = cb0; by1 = cb1;
            } else {
                bx0 = rb0; by0 = rb0; bx1 = rb1; by1 = rb1;
            }
            float2 v0, v1;
            v0.x = acc[ii][jj][0] * scale + bx0;
            v0.y = acc[ii][jj][1] * scale + by0;
            v1.x = acc[ii][jj][2] * scale + bx1;
            v1.y = acc[ii][jj][3] * scale + by1;
            if (round_out) {
                v0.x = f2tf32f(v0.x); v0.y = f2tf32f(v0.y);
                v1.x = f2tf32f(v1.x); v1.y = f2tf32f(v1.y);
            }
            *(float2*)(C + (size_t)r0 * ldC + col) = v0;
            *(float2*)(C + (size_t)(r0 + 8) * ldC + col) = v1;
        }
    }
}

// ================= layernorm / softmax / transpose =================
static __device__ __forceinline__ float blockReduceSum256(float v) {
    __shared__ float sh[8];
    int lane = threadIdx.x & 31, w = threadIdx.x >> 5;
    #pragma unroll
    for (int o = 16; o > 0; o >>= 1) v += __shfl_xor_sync(0xffffffffu, v, o);
    __syncthreads();
    if (lane == 0) sh[w] = v;
    __syncthreads();
    if (w == 0) {
        v = (lane < 8) ? sh[lane] : 0.f;
        #pragma unroll
        for (int o = 4; o > 0; o >>= 1) v += __shfl_xor_sync(0xffffffffu, v, o);
        if (lane == 0) sh[0] = v;
    }
    __syncthreads();
    return sh[0];
}
static __device__ __forceinline__ float blockReduceMax256(float v) {
    __shared__ float sh[8];
    int lane = threadIdx.x & 31, w = threadIdx.x >> 5;
    #pragma unroll
    for (int o = 16; o > 0; o >>= 1) v = fmaxf(v, __shfl_xor_sync(0xffffffffu, v, o));
    __syncthreads();
    if (lane == 0) sh[w] = v;
    __syncthreads();
    if (w == 0) {
        v = (lane < 8) ? sh[lane] : -INFINITY;
        #pragma unroll
        for (int o = 4; o > 0; o >>= 1) v = fmaxf(v, __shfl_xor_sync(0xffffffffu, v, o));
        if (lane == 0) sh[0] = v;
    }
    __syncthreads();
    return sh[0];
}

template<int NV>
__global__ __launch_bounds__(256)
void layernorm_kernel(const float* __restrict__ x, const float* __restrict__ g,
                      const float* __restrict__ b, float* __restrict__ y, int D) {
    const size_t row = blockIdx.x;
    const float* xr = x + row * (size_t)D;
    float*       yr = y + row * (size_t)D;
    float v[NV];
    float s = 0.f;
    #pragma unroll
    for (int j = 0; j < NV; j++) { v[j] = xr[threadIdx.x + j * 256]; s += v[j]; }
    const float mu = blockReduceSum256(s) * (1.f / (float)D);
    float sq = 0.f;
    #pragma unroll
    for (int j = 0; j < NV; j++) { float d = v[j] - mu; sq += d * d; }
    const float rstd = rsqrtf(blockReduceSum256(sq) * (1.f / (float)D) + 1e-5f);
    #pragma unroll
    for (int j = 0; j < NV; j++) {
        int idx = threadIdx.x + j * 256;
        yr[idx] = f2tf32f((v[j] - mu) * rstd * g[idx] + b[idx]);
    }
}

__global__ __launch_bounds__(256)
void softmax_kernel(float* __restrict__ s) {
    const size_t row = blockIdx.x;
    float4* p = (float4*)(s + row * (size_t)L2);
    float4 a = p[threadIdx.x];
    float4 b = p[threadIdx.x + 256];
    float m = fmaxf(fmaxf(fmaxf(a.x, a.y), fmaxf(a.z, a.w)),
                    fmaxf(fmaxf(b.x, b.y), fmaxf(b.z, b.w)));
    m = blockReduceMax256(m);
    a.x = __expf(a.x - m); a.y = __expf(a.y - m);
    a.z = __expf(a.z - m); a.w = __expf(a.w - m);
    b.x = __expf(b.x - m); b.y = __expf(b.y - m);
    b.z = __expf(b.z - m); b.w = __expf(b.w - m);
    float sum = (a.x + a.y + a.z + a.w) + (b.x + b.y + b.z + b.w);
    const float inv = 1.f / blockReduceSum256(sum);
    a.x = f2tf32f(a.x * inv); a.y = f2tf32f(a.y * inv);
    a.z = f2tf32f(a.z * inv); a.w = f2tf32f(a.w * inv);
    b.x = f2tf32f(b.x * inv); b.y = f2tf32f(b.y * inv);
    b.z = f2tf32f(b.z * inv); b.w = f2tf32f(b.w * inv);
    p[threadIdx.x] = a;
    p[threadIdx.x + 256] = b;
}

// out[C,R] = in[R,C]^T (tf32-rounded) — weights only (small)
__global__ __launch_bounds__(256)
void transpose_kernel(const float* __restrict__ in, float* __restrict__ out,
                      int R, int C) {
    __shared__ float tb[32][33];
    const int r0 = blockIdx.y * 32, c0 = blockIdx.x * 32;
    const int tx = threadIdx.x & 31, ty = threadIdx.x >> 5;
    #pragma unroll
    for (int k = 0; k < 32; k += 8)
        tb[ty + k][tx] = in[(size_t)(r0 + ty + k) * C + c0 + tx];
    __syncthreads();
    #pragma unroll
    for (int k = 0; k < 32; k += 8)
        out[(size_t)(c0 + ty + k) * R + r0 + tx] = f2tf32f(tb[tx][ty + k]);
}

// ================= launch =================
extern "C" void kernel_launch(void* const* d_in, const int* in_sizes, int n_in,
                              void* d_out, int out_size) {
    const float* modality1 = (const float*)d_in[0];
    const float* modality2 = (const float*)d_in[1];
    const float* ln1_g = (const float*)d_in[2];
    const float* ln1_b = (const float*)d_in[3];
    const float* ln2_g = (const float*)d_in[4];
    const float* ln2_b = (const float*)d_in[5];
    const float* Wq = (const float*)d_in[6];
    const float* bq = (const float*)d_in[7];
    const float* Wk = (const float*)d_in[8];
    const float* bk = (const float*)d_in[9];
    const float* Wv = (const float*)d_in[10];
    const float* bv = (const float*)d_in[11];
    const float* Wo = (const float*)d_in[12];
    const float* bo = (const float*)d_in[13];
    float* out = (float*)d_out;

    float *x1, *x2, *q, *k, *vT, *s, *ctx, *wqT, *wkT, *wvT, *woT;
    cudaGetSymbolAddress((void**)&x1, g_x1);
    cudaGetSymbolAddress((void**)&x2, g_x2);
    cudaGetSymbolAddress((void**)&q, g_q);
    cudaGetSymbolAddress((void**)&k, g_k);
    cudaGetSymbolAddress((void**)&vT, g_vT);
    cudaGetSymbolAddress((void**)&s, g_s);
    cudaGetSymbolAddress((void**)&ctx, g_ctx);
    cudaGetSymbolAddress((void**)&wqT, g_wqT);
    cudaGetSymbolAddress((void**)&wkT, g_wkT);
    cudaGetSymbolAddress((void**)&wvT, g_wvT);
    cudaGetSymbolAddress((void**)&woT, g_woT);

    cudaFuncSetAttribute(gemm_mma, cudaFuncAttributeMaxDynamicSharedMemorySize, GSMEM);

    const float scaling = 1.0f / 32.0f;   // E^-0.5

    // 1) layernorms (tf32-rounded outputs)
    layernorm_kernel<4><<<ROWS1, 256>>>(modality1, ln1_g, ln1_b, x1, D1);
    layernorm_kernel<3><<<ROWS2, 256>>>(modality2, ln2_g, ln2_b, x2, D2);

    // 2) weight transposes -> K-major [N,K], tf32-rounded
    transpose_kernel<<<dim3(EDIM / 32, D1 / 32), 256>>>(Wq, wqT, D1, EDIM);
    transpose_kernel<<<dim3(EDIM / 32, D2 / 32), 256>>>(Wk, wkT, D2, EDIM);
    transpose_kernel<<<dim3(EDIM / 32, D2 / 32), 256>>>(Wv, wvT, D2, EDIM);
    transpose_kernel<<<dim3(D1 / 32, EDIM / 32), 256>>>(Wo, woT, EDIM, D1);

    // 3) Q/K projections
    gemm_mma<<<dim3(EDIM / 128, ROWS1 / 128), 128, GSMEM>>>(
        x1, wqT, bq, q, D1, D1, D1, EDIM, 1.f, 1, 1, 0, 0, 0);
    gemm_mma<<<dim3(EDIM / 128, ROWS2 / 128), 128, GSMEM>>>(
        x2, wkT, bk, k, D2, D2, D2, EDIM, 1.f, 1, 1, 0, 0, 0);

    // 3b) vT[E, 16384] = Wv^T @ x2^T + bv (row bias) — replaces V proj + transpose
    gemm_mma<<<dim3(ROWS2 / 128, EDIM / 128), 128, GSMEM>>>(
        wvT, x2, bv, vT, D2, D2, D2, ROWS2, 1.f, 1, 2, 0, 0, 0);

    // 4) scores = scaling * Q @ K^T (batched)
    gemm_mma<<<dim3(L2 / 128, L1 / 128, BATCH), 128, GSMEM>>>(
        q, k, nullptr, s, EDIM, EDIM, EDIM, L2, scaling, 0, 0,
        (long long)L1 * EDIM, (long long)L2 * EDIM, (long long)L1 * L2);

    // 5) softmax rows (tf32-rounded output)
    softmax_kernel<<<BATCH * L1, 256>>>(s);

    // 6) ctx = attn @ V  (B = vT slice per batch, pitch 16384)
    gemm_mma<<<dim3(EDIM / 128, L1 / 128, BATCH), 128, GSMEM>>>(
        s, vT, nullptr, ctx, L2, L2, ROWS2, EDIM, 1.f, 1, 0,
        (long long)L1 * L2, (long long)L2, (long long)L1 * EDIM);

    // 7) out = ctx @ Wo + bo (fp32 output)
    gemm_mma<<<dim3(D1 / 128, ROWS1 / 128), 128, GSMEM>>>(
        ctx, woT, bo, out, EDIM, EDIM, EDIM, D1, 1.f, 0, 1, 0, 0, 0);
}

// round 6
// speedup vs baseline: 1.1199x; 1.0068x over previous
#include <cuda_runtime.h>
#include <math.h>
#include <stdint.h>

// ---------------- problem constants ----------------
#define BATCH 8
#define L1 2048
#define L2 2048
#define D1 1024
#define D2 768
#define EDIM 1024
#define ROWS1 (BATCH * L1)          // 16384
#define ROWS2 (BATCH * L2)          // 16384

// ---------------- scratch (device globals; no allocation) ----------------
__device__ float g_x1[ROWS1 * D1];
__device__ float g_x2[ROWS2 * D2];
__device__ float g_q[ROWS1 * EDIM];
__device__ float g_k[ROWS2 * EDIM];
__device__ float g_vT[(size_t)BATCH * EDIM * L2];  // [B][E][L2] pitch 2048
__device__ float g_s[(size_t)BATCH * L1 * L2];     // scores / attn
__device__ float g_ctx[ROWS1 * EDIM];
__device__ float g_wqT[EDIM * D1];
__device__ float g_wkT[EDIM * D2];
__device__ float g_wvT[EDIM * D2];
__device__ float g_woT[D1 * EDIM];

// ---------------- helpers ----------------
static __device__ __forceinline__ uint32_t smem_u32(const void* p) {
    uint32_t a;
    asm("{ .reg .u64 t; cvta.to.shared.u64 t, %1; cvt.u32.u64 %0, t; }" : "=r"(a) : "l"(p));
    return a;
}
static __device__ __forceinline__ float f2tf32f(float x) {
    uint32_t y; asm("cvt.rna.tf32.f32 %0, %1;" : "=r"(y) : "f"(x));
    return __uint_as_float(y);
}
static __device__ __forceinline__ void cp_async16(uint32_t saddr, const void* gptr) {
    asm volatile("cp.async.cg.shared.global [%0], [%1], 16;" :: "r"(saddr), "l"(gptr));
}
static __device__ __forceinline__ void cp_commit() {
    asm volatile("cp.async.commit_group;" ::: "memory");
}
template<int N>
static __device__ __forceinline__ void cp_wait() {
    asm volatile("cp.async.wait_group %0;" :: "n"(N) : "memory");
}

#define MMA_TF32(d, a, b) \
    asm volatile("mma.sync.aligned.m16n8k8.row.col.f32.tf32.tf32.f32 " \
        "{%0,%1,%2,%3}, {%4,%5,%6,%7}, {%8,%9}, {%0,%1,%2,%3};" \
        : "+f"((d)[0]), "+f"((d)[1]), "+f"((d)[2]), "+f"((d)[3]) \
        : "r"((a)[0]), "r"((a)[1]), "r"((a)[2]), "r"((a)[3]), \
          "r"((b)[0]), "r"((b)[1]))

// ================= tf32 mma.sync GEMM =================
// C[M,N] = scale*(A[M,K] @ B[N,K]^T) + bias;  A,B K-major with pitches ldA/ldB.
// BM=128, BN=128, BK=16. 128 threads = 4 warps (2x2), warp tile 64x64.
// Smem row stride 20 words -> conflict-free LDS.32 fragments. 4-stage, 2 CTAs/SM.
// Optional segmented C: if cSeg>0, output column-space is split into segments of
// cSeg columns; segment i starts at C + i*cSegStride (for per-batch-compact outputs).
#define STAGES 4
#define AW 2560                    // words per A stage (128*20)
#define STW 5120                   // words per stage (A+B)
#define GSMEM (STAGES * STW * 4)   // 81920 bytes

__global__ void __launch_bounds__(128, 2)
gemm_mma(const float* __restrict__ A, const float* __restrict__ B,
         const float* __restrict__ bias, float* __restrict__ C,
         int K, int ldA, int ldB, int ldC,
         float scale, int round_out, int bias_mode,
         long long sA, long long sB, long long sC,
         int cSeg, long long cSegStride) {
    extern __shared__ uint32_t sm[];
    const uint32_t sb = smem_u32(sm);
    const int tid = threadIdx.x;
    const int lane = tid & 31, warp = tid >> 5;
    const int g = lane >> 2, t = lane & 3;
    const int m0 = (warp >> 1) * 64;
    const int n0 = (warp & 1) * 64;

    A += (long long)blockIdx.z * sA + (size_t)blockIdx.y * 128 * ldA;
    B += (long long)blockIdx.z * sB + (size_t)blockIdx.x * 128 * ldB;
    C += (long long)blockIdx.z * sC;

    const int r_ld = tid >> 2;
    const int c_ld = (tid & 3) * 4;

    float acc[4][8][4];
    #pragma unroll
    for (int i = 0; i < 4; i++)
        #pragma unroll
        for (int j = 0; j < 8; j++)
            #pragma unroll
            for (int e = 0; e < 4; e++) acc[i][j][e] = 0.f;

    const int nch = K >> 4;

    #pragma unroll
    for (int s = 0; s < STAGES - 1; s++) {
        const int k0 = s * 16;
        #pragma unroll
        for (int f = 0; f < 4; f++) {
            int row = r_ld + f * 32;
            cp_async16(sb + (s * STW + row * 20 + c_ld) * 4,
                       A + (size_t)row * ldA + k0 + c_ld);
            cp_async16(sb + (s * STW + AW + row * 20 + c_ld) * 4,
                       B + (size_t)row * ldB + k0 + c_ld);
        }
        cp_commit();
    }

    for (int i = 0; i < nch; i++) {
        cp_wait<STAGES - 2>();
        __syncthreads();

        {
            const int ic = i + STAGES - 1;
            if (ic < nch) {
                const int st = ic % STAGES;
                const int k0 = ic * 16;
                #pragma unroll
                for (int f = 0; f < 4; f++) {
                    int row = r_ld + f * 32;
                    cp_async16(sb + (st * STW + row * 20 + c_ld) * 4,
                               A + (size_t)row * ldA + k0 + c_ld);
                    cp_async16(sb + (st * STW + AW + row * 20 + c_ld) * 4,
                               B + (size_t)row * ldB + k0 + c_ld);
                }
            }
            cp_commit();
        }

        const uint32_t* __restrict__ smA = sm + (i % STAGES) * STW;
        const uint32_t* __restrict__ smB = smA + AW;
        #pragma unroll
        for (int ks = 0; ks < 2; ks++) {
            const int kk = ks * 8;
            uint32_t af[4][4], bf[8][2];
            #pragma unroll
            for (int ii = 0; ii < 4; ii++) {
                const int mr = m0 + ii * 16 + g;
                af[ii][0] = smA[mr * 20 + kk + t];
                af[ii][1] = smA[(mr + 8) * 20 + kk + t];
                af[ii][2] = smA[mr * 20 + kk + t + 4];
                af[ii][3] = smA[(mr + 8) * 20 + kk + t + 4];
            }
            #pragma unroll
            for (int jj = 0; jj < 8; jj++) {
                const int nr = n0 + jj * 8 + g;
                bf[jj][0] = smB[nr * 20 + kk + t];
                bf[jj][1] = smB[nr * 20 + kk + t + 4];
            }
            #pragma unroll
            for (int ii = 0; ii < 4; ii++)
                #pragma unroll
                for (int jj = 0; jj < 8; jj++)
                    MMA_TF32(acc[ii][jj], af[ii], bf[jj]);
        }
        __syncthreads();
    }

    // epilogue (with optional segmented C column space)
    int colblk = blockIdx.x * 128;
    if (cSeg > 0) {
        const int seg = colblk / cSeg;
        C += (long long)seg * cSegStride;
        colblk -= seg * cSeg;
    }
    const int row_base = blockIdx.y * 128 + m0 + g;
    const int col_base = colblk + n0 + t * 2;
    const int bcol_base = blockIdx.x * 128 + n0 + t * 2;   // bias indexed by global col
    #pragma unroll
    for (int ii = 0; ii < 4; ii++) {
        const int r0 = row_base + ii * 16;
        float rb0 = 0.f, rb1 = 0.f;
        if (bias_mode == 2) { rb0 = __ldg(bias + r0); rb1 = __ldg(bias + r0 + 8); }
        #pragma unroll
        for (int jj = 0; jj < 8; jj++) {
            const int col = col_base + jj * 8;
            float bx0, by0, bx1, by1;
            if (bias_mode == 1) {
                const int bc = bcol_base + jj * 8;
                float cb0 = __ldg(bias + bc), cb1 = __ldg(bias + bc + 1);
                bx0 = cb0; by0 = cb1; bx1 = cb0; by1 = cb1;
            } else {
                bx0 = rb0; by0 = rb0; bx1 = rb1; by1 = rb1;
            }
            float2 v0, v1;
            v0.x = acc[ii][jj][0] * scale + bx0;
            v0.y = acc[ii][jj][1] * scale + by0;
            v1.x = acc[ii][jj][2] * scale + bx1;
            v1.y = acc[ii][jj][3] * scale + by1;
            if (round_out) {
                v0.x = f2tf32f(v0.x); v0.y = f2tf32f(v0.y);
                v1.x = f2tf32f(v1.x); v1.y = f2tf32f(v1.y);
            }
            *(float2*)(C + (size_t)r0 * ldC + col) = v0;
            *(float2*)(C + (size_t)(r0 + 8) * ldC + col) = v1;
        }
    }
}

// ================= layernorm / softmax / transpose =================
static __device__ __forceinline__ float blockReduceSum256(float v) {
    __shared__ float sh[8];
    int lane = threadIdx.x & 31, w = threadIdx.x >> 5;
    #pragma unroll
    for (int o = 16; o > 0; o >>= 1) v += __shfl_xor_sync(0xffffffffu, v, o);
    __syncthreads();
    if (lane == 0) sh[w] = v;
    __syncthreads();
    if (w == 0) {
        v = (lane < 8) ? sh[lane] : 0.f;
        #pragma unroll
        for (int o = 4; o > 0; o >>= 1) v += __shfl_xor_sync(0xffffffffu, v, o);
        if (lane == 0) sh[0] = v;
    }
    __syncthreads();
    return sh[0];
}
static __device__ __forceinline__ float blockReduceMax256(float v) {
    __shared__ float sh[8];
    int lane = threadIdx.x & 31, w = threadIdx.x >> 5;
    #pragma unroll
    for (int o = 16; o > 0; o >>= 1) v = fmaxf(v, __shfl_xor_sync(0xffffffffu, v, o));
    __syncthreads();
    if (lane == 0) sh[w] = v;
    __syncthreads();
    if (w == 0) {
        v = (lane < 8) ? sh[lane] : -INFINITY;
        #pragma unroll
        for (int o = 4; o > 0; o >>= 1) v = fmaxf(v, __shfl_xor_sync(0xffffffffu, v, o));
        if (lane == 0) sh[0] = v;
    }
    __syncthreads();
    return sh[0];
}

template<int NV>
__global__ __launch_bounds__(256)
void layernorm_kernel(const float* __restrict__ x, const float* __restrict__ g,
                      const float* __restrict__ b, float* __restrict__ y, int D) {
    const size_t row = blockIdx.x;
    const float* xr = x + row * (size_t)D;
    float*       yr = y + row * (size_t)D;
    float v[NV];
    float s = 0.f;
    #pragma unroll
    for (int j = 0; j < NV; j++) { v[j] = xr[threadIdx.x + j * 256]; s += v[j]; }
    const float mu = blockReduceSum256(s) * (1.f / (float)D);
    float sq = 0.f;
    #pragma unroll
    for (int j = 0; j < NV; j++) { float d = v[j] - mu; sq += d * d; }
    const float rstd = rsqrtf(blockReduceSum256(sq) * (1.f / (float)D) + 1e-5f);
    #pragma unroll
    for (int j = 0; j < NV; j++) {
        int idx = threadIdx.x + j * 256;
        yr[idx] = f2tf32f((v[j] - mu) * rstd * g[idx] + b[idx]);
    }
}

__global__ __launch_bounds__(256)
void softmax_kernel(float* __restrict__ s) {
    const size_t row = blockIdx.x;
    float4* p = (float4*)(s + row * (size_t)L2);
    float4 a = p[threadIdx.x];
    float4 b = p[threadIdx.x + 256];
    float m = fmaxf(fmaxf(fmaxf(a.x, a.y), fmaxf(a.z, a.w)),
                    fmaxf(fmaxf(b.x, b.y), fmaxf(b.z, b.w)));
    m = blockReduceMax256(m);
    a.x = __expf(a.x - m); a.y = __expf(a.y - m);
    a.z = __expf(a.z - m); a.w = __expf(a.w - m);
    b.x = __expf(b.x - m); b.y = __expf(b.y - m);
    b.z = __expf(b.z - m); b.w = __expf(b.w - m);
    float sum = (a.x + a.y + a.z + a.w) + (b.x + b.y + b.z + b.w);
    const float inv = 1.f / blockReduceSum256(sum);
    a.x = f2tf32f(a.x * inv); a.y = f2tf32f(a.y * inv);
    a.z = f2tf32f(a.z * inv); a.w = f2tf32f(a.w * inv);
    b.x = f2tf32f(b.x * inv); b.y = f2tf32f(b.y * inv);
    b.z = f2tf32f(b.z * inv); b.w = f2tf32f(b.w * inv);
    p[threadIdx.x] = a;
    p[threadIdx.x + 256] = b;
}

// out[C,R] = in[R,C]^T (tf32-rounded) — weights only (small)
__global__ __launch_bounds__(256)
void transpose_kernel(const float* __restrict__ in, float* __restrict__ out,
                      int R, int C) {
    __shared__ float tb[32][33];
    const int r0 = blockIdx.y * 32, c0 = blockIdx.x * 32;
    const int tx = threadIdx.x & 31, ty = threadIdx.x >> 5;
    #pragma unroll
    for (int k = 0; k < 32; k += 8)
        tb[ty + k][tx] = in[(size_t)(r0 + ty + k) * C + c0 + tx];
    __syncthreads();
    #pragma unroll
    for (int k = 0; k < 32; k += 8)
        out[(size_t)(c0 + ty + k) * R + r0 + tx] = f2tf32f(tb[tx][ty + k]);
}

// ================= launch =================
extern "C" void kernel_launch(void* const* d_in, const int* in_sizes, int n_in,
                              void* d_out, int out_size) {
    const float* modality1 = (const float*)d_in[0];
    const float* modality2 = (const float*)d_in[1];
    const float* ln1_g = (const float*)d_in[2];
    const float* ln1_b = (const float*)d_in[3];
    const float* ln2_g = (const float*)d_in[4];
    const float* ln2_b = (const float*)d_in[5];
    const float* Wq = (const float*)d_in[6];
    const float* bq = (const float*)d_in[7];
    const float* Wk = (const float*)d_in[8];
    const float* bk = (const float*)d_in[9];
    const float* Wv = (const float*)d_in[10];
    const float* bv = (const float*)d_in[11];
    const float* Wo = (const float*)d_in[12];
    const float* bo = (const float*)d_in[13];
    float* out = (float*)d_out;

    float *x1, *x2, *q, *k, *vT, *s, *ctx, *wqT, *wkT, *wvT, *woT;
    cudaGetSymbolAddress((void**)&x1, g_x1);
    cudaGetSymbolAddress((void**)&x2, g_x2);
    cudaGetSymbolAddress((void**)&q, g_q);
    cudaGetSymbolAddress((void**)&k, g_k);
    cudaGetSymbolAddress((void**)&vT, g_vT);
    cudaGetSymbolAddress((void**)&s, g_s);
    cudaGetSymbolAddress((void**)&ctx, g_ctx);
    cudaGetSymbolAddress((void**)&wqT, g_wqT);
    cudaGetSymbolAddress((void**)&wkT, g_wkT);
    cudaGetSymbolAddress((void**)&wvT, g_wvT);
    cudaGetSymbolAddress((void**)&woT, g_woT);

    cudaFuncSetAttribute(gemm_mma, cudaFuncAttributeMaxDynamicSharedMemorySize, GSMEM);

    const float scaling = 1.0f / 32.0f;   // E^-0.5

    // 1) layernorms (tf32-rounded outputs)
    layernorm_kernel<4><<<ROWS1, 256>>>(modality1, ln1_g, ln1_b, x1, D1);
    layernorm_kernel<3><<<ROWS2, 256>>>(modality2, ln2_g, ln2_b, x2, D2);

    // 2) weight transposes -> K-major [N,K], tf32-rounded
    transpose_kernel<<<dim3(EDIM / 32, D1 / 32), 256>>>(Wq, wqT, D1, EDIM);
    transpose_kernel<<<dim3(EDIM / 32, D2 / 32), 256>>>(Wk, wkT, D2, EDIM);
    transpose_kernel<<<dim3(EDIM / 32, D2 / 32), 256>>>(Wv, wvT, D2, EDIM);
    transpose_kernel<<<dim3(D1 / 32, EDIM / 32), 256>>>(Wo, woT, EDIM, D1);

    // 3) Q/K projections
    gemm_mma<<<dim3(EDIM / 128, ROWS1 / 128), 128, GSMEM>>>(
        x1, wqT, bq, q, D1, D1, D1, EDIM, 1.f, 1, 1, 0, 0, 0, 0, 0);
    gemm_mma<<<dim3(EDIM / 128, ROWS2 / 128), 128, GSMEM>>>(
        x2, wkT, bk, k, D2, D2, D2, EDIM, 1.f, 1, 1, 0, 0, 0, 0, 0);

    // 3b) vT[b][e][c] = (Wv^T @ x2^T)[e, b*2048+c] + bv[e]  (segmented C, pitch 2048)
    gemm_mma<<<dim3(ROWS2 / 128, EDIM / 128), 128, GSMEM>>>(
        wvT, x2, bv, vT, D2, D2, D2, L2, 1.f, 1, 2, 0, 0, 0,
        L2, (long long)EDIM * L2);

    // 4) scores = scaling * Q @ K^T (batched)
    gemm_mma<<<dim3(L2 / 128, L1 / 128, BATCH), 128, GSMEM>>>(
        q, k, nullptr, s, EDIM, EDIM, EDIM, L2, scaling, 0, 0,
        (long long)L1 * EDIM, (long long)L2 * EDIM, (long long)L1 * L2, 0, 0);

    // 5) softmax rows (tf32-rounded output)
    softmax_kernel<<<BATCH * L1, 256>>>(s);

    // 6) ctx = attn @ V  (B = per-batch vT slice [E, L2], pitch 2048)
    gemm_mma<<<dim3(EDIM / 128, L1 / 128, BATCH), 128, GSMEM>>>(
        s, vT, nullptr, ctx, L2, L2, L2, EDIM, 1.f, 1, 0,
        (long long)L1 * L2, (long long)EDIM * L2, (long long)L1 * EDIM, 0, 0);

    // 7) out = ctx @ Wo + bo (fp32 output)
    gemm_mma<<<dim3(D1 / 128, ROWS1 / 128), 128, GSMEM>>>(
        ctx, woT, bo, out, EDIM, EDIM, EDIM, D1, 1.f, 0, 1, 0, 0, 0, 0, 0);
}

// round 7
// speedup vs baseline: 1.1756x; 1.0498x over previous
#include <cuda_runtime.h>
#include <math.h>
#include <stdint.h>

// ---------------- problem constants ----------------
#define BATCH 8
#define L1 2048
#define L2 2048
#define D1 1024
#define D2 768
#define EDIM 1024
#define ROWS1 (BATCH * L1)          // 16384
#define ROWS2 (BATCH * L2)          // 16384

// ---------------- scratch (device globals; no allocation) ----------------
__device__ float g_x1[ROWS1 * D1];
__device__ float g_x2[ROWS2 * D2];
__device__ float g_q[ROWS1 * EDIM];
__device__ float g_k[ROWS2 * EDIM];
__device__ float g_vT[(size_t)BATCH * EDIM * L2];  // [B][E][L2] pitch 2048
__device__ float g_s[(size_t)BATCH * L1 * L2];     // scores / attn
__device__ float g_ctx[ROWS1 * EDIM];
__device__ float g_wqT[EDIM * D1];
__device__ float g_wkT[EDIM * D2];
__device__ float g_wvT[EDIM * D2];
__device__ float g_woT[D1 * EDIM];

// ---------------- helpers ----------------
static __device__ __forceinline__ uint32_t smem_u32(const void* p) {
    uint32_t a;
    asm("{ .reg .u64 t; cvta.to.shared.u64 t, %1; cvt.u32.u64 %0, t; }" : "=r"(a) : "l"(p));
    return a;
}
static __device__ __forceinline__ float f2tf32f(float x) {
    uint32_t y; asm("cvt.rna.tf32.f32 %0, %1;" : "=r"(y) : "f"(x));
    return __uint_as_float(y);
}
static __device__ __forceinline__ void cp_async16(uint32_t saddr, const void* gptr) {
    asm volatile("cp.async.cg.shared.global [%0], [%1], 16;" :: "r"(saddr), "l"(gptr));
}
static __device__ __forceinline__ void cp_commit() {
    asm volatile("cp.async.commit_group;" ::: "memory");
}
template<int N>
static __device__ __forceinline__ void cp_wait() {
    asm volatile("cp.async.wait_group %0;" :: "n"(N) : "memory");
}

#define MMA_TF32(d, a, b) \
    asm volatile("mma.sync.aligned.m16n8k8.row.col.f32.tf32.tf32.f32 " \
        "{%0,%1,%2,%3}, {%4,%5,%6,%7}, {%8,%9}, {%0,%1,%2,%3};" \
        : "+f"((d)[0]), "+f"((d)[1]), "+f"((d)[2]), "+f"((d)[3]) \
        : "r"((a)[0]), "r"((a)[1]), "r"((a)[2]), "r"((a)[3]), \
          "r"((b)[0]), "r"((b)[1]))

// ================= tf32 mma.sync GEMM =================
// C[M,N] = scale*(A[M,K] @ B[N,K]^T) + bias;  A,B K-major with pitches ldA/ldB.
// BM=128, BN=128, BK=16. 128 threads = 4 warps (2x2), warp tile 64x64.
// Smem row stride 20 words -> conflict-free LDS.32 fragments.
// 3-stage cp.async, 3 CTAs/SM, ONE barrier per K-chunk.
#define STAGES 3
#define AW 2560                    // words per A stage (128*20)
#define STW 5120                   // words per stage (A+B)
#define GSMEM (STAGES * STW * 4)   // 61440 bytes

__global__ void __launch_bounds__(128, 3)
gemm_mma(const float* __restrict__ A, const float* __restrict__ B,
         const float* __restrict__ bias, float* __restrict__ C,
         int K, int ldA, int ldB, int ldC,
         float scale, int round_out, int bias_mode,
         long long sA, long long sB, long long sC,
         int cSeg, long long cSegStride) {
    extern __shared__ uint32_t sm[];
    const uint32_t sb = smem_u32(sm);
    const int tid = threadIdx.x;
    const int lane = tid & 31, warp = tid >> 5;
    const int g = lane >> 2, t = lane & 3;
    const int m0 = (warp >> 1) * 64;
    const int n0 = (warp & 1) * 64;

    A += (long long)blockIdx.z * sA + (size_t)blockIdx.y * 128 * ldA;
    B += (long long)blockIdx.z * sB + (size_t)blockIdx.x * 128 * ldB;
    C += (long long)blockIdx.z * sC;

    const int r_ld = tid >> 2;
    const int c_ld = (tid & 3) * 4;

    float acc[4][8][4];
    #pragma unroll
    for (int i = 0; i < 4; i++)
        #pragma unroll
        for (int j = 0; j < 8; j++)
            #pragma unroll
            for (int e = 0; e < 4; e++) acc[i][j][e] = 0.f;

    const int nch = K >> 4;

    #pragma unroll
    for (int s = 0; s < STAGES - 1; s++) {
        const int k0 = s * 16;
        #pragma unroll
        for (int f = 0; f < 4; f++) {
            int row = r_ld + f * 32;
            cp_async16(sb + (s * STW + row * 20 + c_ld) * 4,
                       A + (size_t)row * ldA + k0 + c_ld);
            cp_async16(sb + (s * STW + AW + row * 20 + c_ld) * 4,
                       B + (size_t)row * ldB + k0 + c_ld);
        }
        cp_commit();
    }

    for (int i = 0; i < nch; i++) {
        cp_wait<STAGES - 2>();
        __syncthreads();          // single barrier per chunk: all warps have
                                  // finished reading stage (i-1)%3 before the
                                  // loads below overwrite it.
        {
            const int ic = i + STAGES - 1;
            if (ic < nch) {
                const int st = ic % STAGES;
                const int k0 = ic * 16;
                #pragma unroll
                for (int f = 0; f < 4; f++) {
                    int row = r_ld + f * 32;
                    cp_async16(sb + (st * STW + row * 20 + c_ld) * 4,
                               A + (size_t)row * ldA + k0 + c_ld);
                    cp_async16(sb + (st * STW + AW + row * 20 + c_ld) * 4,
                               B + (size_t)row * ldB + k0 + c_ld);
                }
            }
            cp_commit();
        }

        const uint32_t* __restrict__ smA = sm + (i % STAGES) * STW;
        const uint32_t* __restrict__ smB = smA + AW;
        #pragma unroll
        for (int ks = 0; ks < 2; ks++) {
            const int kk = ks * 8;
            uint32_t af[4][4], bf[8][2];
            #pragma unroll
            for (int ii = 0; ii < 4; ii++) {
                const int mr = m0 + ii * 16 + g;
                af[ii][0] = smA[mr * 20 + kk + t];
                af[ii][1] = smA[(mr + 8) * 20 + kk + t];
                af[ii][2] = smA[mr * 20 + kk + t + 4];
                af[ii][3] = smA[(mr + 8) * 20 + kk + t + 4];
            }
            #pragma unroll
            for (int jj = 0; jj < 8; jj++) {
                const int nr = n0 + jj * 8 + g;
                bf[jj][0] = smB[nr * 20 + kk + t];
                bf[jj][1] = smB[nr * 20 + kk + t + 4];
            }
            #pragma unroll
            for (int ii = 0; ii < 4; ii++)
                #pragma unroll
                for (int jj = 0; jj < 8; jj++)
                    MMA_TF32(acc[ii][jj], af[ii], bf[jj]);
        }
    }

    // epilogue (with optional segmented C column space)
    int colblk = blockIdx.x * 128;
    if (cSeg > 0) {
        const int seg = colblk / cSeg;
        C += (long long)seg * cSegStride;
        colblk -= seg * cSeg;
    }
    const int row_base = blockIdx.y * 128 + m0 + g;
    const int col_base = colblk + n0 + t * 2;
    const int bcol_base = blockIdx.x * 128 + n0 + t * 2;
    #pragma unroll
    for (int ii = 0; ii < 4; ii++) {
        const int r0 = row_base + ii * 16;
        float rb0 = 0.f, rb1 = 0.f;
        if (bias_mode == 2) { rb0 = __ldg(bias + r0); rb1 = __ldg(bias + r0 + 8); }
        #pragma unroll
        for (int jj = 0; jj < 8; jj++) {
            const int col = col_base + jj * 8;
            float bx0, by0, bx1, by1;
            if (bias_mode == 1) {
                const int bc = bcol_base + jj * 8;
                float cb0 = __ldg(bias + bc), cb1 = __ldg(bias + bc + 1);
                bx0 = cb0; by0 = cb1; bx1 = cb0; by1 = cb1;
            } else {
                bx0 = rb0; by0 = rb0; bx1 = rb1; by1 = rb1;
            }
            float2 v0, v1;
            v0.x = acc[ii][jj][0] * scale + bx0;
            v0.y = acc[ii][jj][1] * scale + by0;
            v1.x = acc[ii][jj][2] * scale + bx1;
            v1.y = acc[ii][jj][3] * scale + by1;
            if (round_out) {
                v0.x = f2tf32f(v0.x); v0.y = f2tf32f(v0.y);
                v1.x = f2tf32f(v1.x); v1.y = f2tf32f(v1.y);
            }
            *(float2*)(C + (size_t)r0 * ldC + col) = v0;
            *(float2*)(C + (size_t)(r0 + 8) * ldC + col) = v1;
        }
    }
}

// ================= layernorm / softmax / transpose =================
static __device__ __forceinline__ float blockReduceSum256(float v) {
    __shared__ float sh[8];
    int lane = threadIdx.x & 31, w = threadIdx.x >> 5;
    #pragma unroll
    for (int o = 16; o > 0; o >>= 1) v += __shfl_xor_sync(0xffffffffu, v, o);
    __syncthreads();
    if (lane == 0) sh[w] = v;
    __syncthreads();
    if (w == 0) {
        v = (lane < 8) ? sh[lane] : 0.f;
        #pragma unroll
        for (int o = 4; o > 0; o >>= 1) v += __shfl_xor_sync(0xffffffffu, v, o);
        if (lane == 0) sh[0] = v;
    }
    __syncthreads();
    return sh[0];
}
static __device__ __forceinline__ float blockReduceMax256(float v) {
    __shared__ float sh[8];
    int lane = threadIdx.x & 31, w = threadIdx.x >> 5;
    #pragma unroll
    for (int o = 16; o > 0; o >>= 1) v = fmaxf(v, __shfl_xor_sync(0xffffffffu, v, o));
    __syncthreads();
    if (lane == 0) sh[w] = v;
    __syncthreads();
    if (w == 0) {
        v = (lane < 8) ? sh[lane] : -INFINITY;
        #pragma unroll
        for (int o = 4; o > 0; o >>= 1) v = fmaxf(v, __shfl_xor_sync(0xffffffffu, v, o));
        if (lane == 0) sh[0] = v;
    }
    __syncthreads();
    return sh[0];
}

template<int NV>
__global__ __launch_bounds__(256)
void layernorm_kernel(const float* __restrict__ x, const float* __restrict__ g,
                      const float* __restrict__ b, float* __restrict__ y, int D) {
    const size_t row = blockIdx.x;
    const float* xr = x + row * (size_t)D;
    float*       yr = y + row * (size_t)D;
    float v[NV];
    float s = 0.f;
    #pragma unroll
    for (int j = 0; j < NV; j++) { v[j] = xr[threadIdx.x + j * 256]; s += v[j]; }
    const float mu = blockReduceSum256(s) * (1.f / (float)D);
    float sq = 0.f;
    #pragma unroll
    for (int j = 0; j < NV; j++) { float d = v[j] - mu; sq += d * d; }
    const float rstd = rsqrtf(blockReduceSum256(sq) * (1.f / (float)D) + 1e-5f);
    #pragma unroll
    for (int j = 0; j < NV; j++) {
        int idx = threadIdx.x + j * 256;
        yr[idx] = f2tf32f((v[j] - mu) * rstd * g[idx] + b[idx]);
    }
}

__global__ __launch_bounds__(256)
void softmax_kernel(float* __restrict__ s) {
    const size_t row = blockIdx.x;
    float4* p = (float4*)(s + row * (size_t)L2);
    float4 a = p[threadIdx.x];
    float4 b = p[threadIdx.x + 256];
    float m = fmaxf(fmaxf(fmaxf(a.x, a.y), fmaxf(a.z, a.w)),
                    fmaxf(fmaxf(b.x, b.y), fmaxf(b.z, b.w)));
    m = blockReduceMax256(m);
    a.x = __expf(a.x - m); a.y = __expf(a.y - m);
    a.z = __expf(a.z - m); a.w = __expf(a.w - m);
    b.x = __expf(b.x - m); b.y = __expf(b.y - m);
    b.z = __expf(b.z - m); b.w = __expf(b.w - m);
    float sum = (a.x + a.y + a.z + a.w) + (b.x + b.y + b.z + b.w);
    const float inv = 1.f / blockReduceSum256(sum);
    a.x = f2tf32f(a.x * inv); a.y = f2tf32f(a.y * inv);
    a.z = f2tf32f(a.z * inv); a.w = f2tf32f(a.w * inv);
    b.x = f2tf32f(b.x * inv); b.y = f2tf32f(b.y * inv);
    b.z = f2tf32f(b.z * inv); b.w = f2tf32f(b.w * inv);
    p[threadIdx.x] = a;
    p[threadIdx.x + 256] = b;
}

// out[C,R] = in[R,C]^T (tf32-rounded) — weights only (small)
__global__ __launch_bounds__(256)
void transpose_kernel(const float* __restrict__ in, float* __restrict__ out,
                      int R, int C) {
    __shared__ float tb[32][33];
    const int r0 = blockIdx.y * 32, c0 = blockIdx.x * 32;
    const int tx = threadIdx.x & 31, ty = threadIdx.x >> 5;
    #pragma unroll
    for (int k = 0; k < 32; k += 8)
        tb[ty + k][tx] = in[(size_t)(r0 + ty + k) * C + c0 + tx];
    __syncthreads();
    #pragma unroll
    for (int k = 0; k < 32; k += 8)
        out[(size_t)(c0 + ty + k) * R + r0 + tx] = f2tf32f(tb[tx][ty + k]);
}

// ================= launch =================
extern "C" void kernel_launch(void* const* d_in, const int* in_sizes, int n_in,
                              void* d_out, int out_size) {
    const float* modality1 = (const float*)d_in[0];
    const float* modality2 = (const float*)d_in[1];
    const float* ln1_g = (const float*)d_in[2];
    const float* ln1_b = (const float*)d_in[3];
    const float* ln2_g = (const float*)d_in[4];
    const float* ln2_b = (const float*)d_in[5];
    const float* Wq = (const float*)d_in[6];
    const float* bq = (const float*)d_in[7];
    const float* Wk = (const float*)d_in[8];
    const float* bk = (const float*)d_in[9];
    const float* Wv = (const float*)d_in[10];
    const float* bv = (const float*)d_in[11];
    const float* Wo = (const float*)d_in[12];
    const float* bo = (const float*)d_in[13];
    float* out = (float*)d_out;

    float *x1, *x2, *q, *k, *vT, *s, *ctx, *wqT, *wkT, *wvT, *woT;
    cudaGetSymbolAddress((void**)&x1, g_x1);
    cudaGetSymbolAddress((void**)&x2, g_x2);
    cudaGetSymbolAddress((void**)&q, g_q);
    cudaGetSymbolAddress((void**)&k, g_k);
    cudaGetSymbolAddress((void**)&vT, g_vT);
    cudaGetSymbolAddress((void**)&s, g_s);
    cudaGetSymbolAddress((void**)&ctx, g_ctx);
    cudaGetSymbolAddress((void**)&wqT, g_wqT);
    cudaGetSymbolAddress((void**)&wkT, g_wkT);
    cudaGetSymbolAddress((void**)&wvT, g_wvT);
    cudaGetSymbolAddress((void**)&woT, g_woT);

    cudaFuncSetAttribute(gemm_mma, cudaFuncAttributeMaxDynamicSharedMemorySize, GSMEM);

    const float scaling = 1.0f / 32.0f;   // E^-0.5

    // 1) layernorms (tf32-rounded outputs)
    layernorm_kernel<4><<<ROWS1, 256>>>(modality1, ln1_g, ln1_b, x1, D1);
    layernorm_kernel<3><<<ROWS2, 256>>>(modality2, ln2_g, ln2_b, x2, D2);

    // 2) weight transposes -> K-major [N,K], tf32-rounded
    transpose_kernel<<<dim3(EDIM / 32, D1 / 32), 256>>>(Wq, wqT, D1, EDIM);
    transpose_kernel<<<dim3(EDIM / 32, D2 / 32), 256>>>(Wk, wkT, D2, EDIM);
    transpose_kernel<<<dim3(EDIM / 32, D2 / 32), 256>>>(Wv, wvT, D2, EDIM);
    transpose_kernel<<<dim3(D1 / 32, EDIM / 32), 256>>>(Wo, woT, EDIM, D1);

    // 3) Q/K projections
    gemm_mma<<<dim3(EDIM / 128, ROWS1 / 128), 128, GSMEM>>>(
        x1, wqT, bq, q, D1, D1, D1, EDIM, 1.f, 1, 1, 0, 0, 0, 0, 0);
    gemm_mma<<<dim3(EDIM / 128, ROWS2 / 128), 128, GSMEM>>>(
        x2, wkT, bk, k, D2, D2, D2, EDIM, 1.f, 1, 1, 0, 0, 0, 0, 0);

    // 3b) vT[b][e][c] = (Wv^T @ x2^T)[e, b*2048+c] + bv[e]  (segmented C, pitch 2048)
    gemm_mma<<<dim3(ROWS2 / 128, EDIM / 128), 128, GSMEM>>>(
        wvT, x2, bv, vT, D2, D2, D2, L2, 1.f, 1, 2, 0, 0, 0,
        L2, (long long)EDIM * L2);

    // 4) scores = scaling * Q @ K^T (batched)
    gemm_mma<<<dim3(L2 / 128, L1 / 128, BATCH), 128, GSMEM>>>(
        q, k, nullptr, s, EDIM, EDIM, EDIM, L2, scaling, 0, 0,
        (long long)L1 * EDIM, (long long)L2 * EDIM, (long long)L1 * L2, 0, 0);

    // 5) softmax rows (tf32-rounded output)
    softmax_kernel<<<BATCH * L1, 256>>>(s);

    // 6) ctx = attn @ V  (B = per-batch vT slice [E, L2], pitch 2048)
    gemm_mma<<<dim3(EDIM / 128, L1 / 128, BATCH), 128, GSMEM>>>(
        s, vT, nullptr, ctx, L2, L2, L2, EDIM, 1.f, 1, 0,
        (long long)L1 * L2, (long long)EDIM * L2, (long long)L1 * EDIM, 0, 0);

    // 7) out = ctx @ Wo + bo (fp32 output)
    gemm_mma<<<dim3(D1 / 128, ROWS1 / 128), 128, GSMEM>>>(
        ctx, woT, bo, out, EDIM, EDIM, EDIM, D1, 1.f, 0, 1, 0, 0, 0, 0, 0);
}

// round 8
// speedup vs baseline: 1.2387x; 1.0536x over previous
#include <cuda_runtime.h>
#include <math.h>
#include <stdint.h>

// ---------------- problem constants ----------------
#define BATCH 8
#define L1 2048
#define L2 2048
#define D1 1024
#define D2 768
#define EDIM 1024
#define ROWS1 (BATCH * L1)          // 16384
#define ROWS2 (BATCH * L2)          // 16384

// ---------------- scratch (device globals; no allocation) ----------------
__device__ float g_x1[ROWS1 * D1];
__device__ float g_x2[ROWS2 * D2];
__device__ float g_q[ROWS1 * EDIM];
__device__ float g_k[ROWS2 * EDIM];
__device__ float g_vT[(size_t)BATCH * EDIM * L2];  // [B][E][L2] pitch 2048
__device__ float g_s[(size_t)BATCH * L1 * L2];     // scores / attn
__device__ float g_ctx[ROWS1 * EDIM];
__device__ float g_wqT[EDIM * D1];
__device__ float g_wkT[EDIM * D2];
__device__ float g_wvT[EDIM * D2];
__device__ float g_woT[D1 * EDIM];

// ---------------- helpers ----------------
static __device__ __forceinline__ uint32_t smem_u32(const void* p) {
    uint32_t a;
    asm("{ .reg .u64 t; cvta.to.shared.u64 t, %1; cvt.u32.u64 %0, t; }" : "=r"(a) : "l"(p));
    return a;
}
static __device__ __forceinline__ float f2tf32f(float x) {
    uint32_t y; asm("cvt.rna.tf32.f32 %0, %1;" : "=r"(y) : "f"(x));
    return __uint_as_float(y);
}
static __device__ __forceinline__ void cp_async16(uint32_t saddr, const void* gptr) {
    asm volatile("cp.async.cg.shared.global [%0], [%1], 16;" :: "r"(saddr), "l"(gptr));
}
static __device__ __forceinline__ void cp_commit() {
    asm volatile("cp.async.commit_group;" ::: "memory");
}
template<int N>
static __device__ __forceinline__ void cp_wait() {
    asm volatile("cp.async.wait_group %0;" :: "n"(N) : "memory");
}
static __device__ __forceinline__ void ldsm_x4(uint32_t* r, uint32_t a) {
    asm volatile("ldmatrix.sync.aligned.m8n8.x4.shared.b16 {%0,%1,%2,%3}, [%4];"
                 : "=r"(r[0]), "=r"(r[1]), "=r"(r[2]), "=r"(r[3]) : "r"(a));
}
static __device__ __forceinline__ void ldsm_x2(uint32_t* r, uint32_t a) {
    asm volatile("ldmatrix.sync.aligned.m8n8.x2.shared.b16 {%0,%1}, [%2];"
                 : "=r"(r[0]), "=r"(r[1]) : "r"(a));
}

#define MMA_TF32(d, a, b) \
    asm volatile("mma.sync.aligned.m16n8k8.row.col.f32.tf32.tf32.f32 " \
        "{%0,%1,%2,%3}, {%4,%5,%6,%7}, {%8,%9}, {%0,%1,%2,%3};" \
        : "+f"((d)[0]), "+f"((d)[1]), "+f"((d)[2]), "+f"((d)[3]) \
        : "r"((a)[0]), "r"((a)[1]), "r"((a)[2]), "r"((a)[3]), \
          "r"((b)[0]), "r"((b)[1]))

// ================= tf32 mma.sync GEMM =================
// C[M,N] = scale*(A[M,K] @ B[N,K]^T) + bias;  A,B K-major with pitches ldA/ldB.
// BM=128, BN=128, BK=16. 128 threads = 4 warps (2x2), warp tile 64x64.
// Smem row stride 20 words -> conflict-free ldmatrix (20r mod 32 covers all quads).
// 3-stage cp.async, 3 CTAs/SM, one barrier per K-chunk, ldmatrix fragments.
#define STAGES 3
#define AW 2560                    // words per A stage (128*20)
#define STW 5120                   // words per stage (A+B)
#define GSMEM (STAGES * STW * 4)   // 61440 bytes

__global__ void __launch_bounds__(128, 3)
gemm_mma(const float* __restrict__ A, const float* __restrict__ B,
         const float* __restrict__ bias, float* __restrict__ C,
         int K, int ldA, int ldB, int ldC,
         float scale, int round_out, int bias_mode,
         long long sA, long long sB, long long sC,
         int cSeg, long long cSegStride) {
    extern __shared__ uint32_t sm[];
    const uint32_t sb = smem_u32(sm);
    const int tid = threadIdx.x;
    const int lane = tid & 31, warp = tid >> 5;
    const int g = lane >> 2, t = lane & 3;
    const int m0 = (warp >> 1) * 64;
    const int n0 = (warp & 1) * 64;

    A += (long long)blockIdx.z * sA + (size_t)blockIdx.y * 128 * ldA;
    B += (long long)blockIdx.z * sB + (size_t)blockIdx.x * 128 * ldB;
    C += (long long)blockIdx.z * sC;

    const int r_ld = tid >> 2;
    const int c_ld = (tid & 3) * 4;

    // ldmatrix per-thread source offsets (bytes, within a stage)
    const int lsub = lane >> 3, lr = lane & 7;
    const uint32_t aoff = (uint32_t)(((m0 + ((lsub & 1) << 3) + lr) * 20 +
                                      ((lsub >> 1) << 2)) * 4);
    const uint32_t boff = (uint32_t)(AW * 4 + ((n0 + lr) * 20 +
                                      (((lane >> 3) & 1) << 2)) * 4);

    float acc[4][8][4];
    #pragma unroll
    for (int i = 0; i < 4; i++)
        #pragma unroll
        for (int j = 0; j < 8; j++)
            #pragma unroll
            for (int e = 0; e < 4; e++) acc[i][j][e] = 0.f;

    const int nch = K >> 4;

    #pragma unroll
    for (int s = 0; s < STAGES - 1; s++) {
        const int k0 = s * 16;
        #pragma unroll
        for (int f = 0; f < 4; f++) {
            int row = r_ld + f * 32;
            cp_async16(sb + (s * STW + row * 20 + c_ld) * 4,
                       A + (size_t)row * ldA + k0 + c_ld);
            cp_async16(sb + (s * STW + AW + row * 20 + c_ld) * 4,
                       B + (size_t)row * ldB + k0 + c_ld);
        }
        cp_commit();
    }

    for (int i = 0; i < nch; i++) {
        cp_wait<STAGES - 2>();
        __syncthreads();          // all warps done reading stage (i-1)%3
        {
            const int ic = i + STAGES - 1;
            if (ic < nch) {
                const int st = ic % STAGES;
                const int k0 = ic * 16;
                #pragma unroll
                for (int f = 0; f < 4; f++) {
                    int row = r_ld + f * 32;
                    cp_async16(sb + (st * STW + row * 20 + c_ld) * 4,
                               A + (size_t)row * ldA + k0 + c_ld);
                    cp_async16(sb + (st * STW + AW + row * 20 + c_ld) * 4,
                               B + (size_t)row * ldB + k0 + c_ld);
                }
            }
            cp_commit();
        }

        const uint32_t stBase = sb + (uint32_t)((i % STAGES) * (STW * 4));
        #pragma unroll
        for (int ks = 0; ks < 2; ks++) {
            uint32_t af[4][4], bf[8][2];
            #pragma unroll
            for (int ii = 0; ii < 4; ii++)
                ldsm_x4(af[ii], stBase + aoff + ii * 1280 + ks * 32);
            #pragma unroll
            for (int jj = 0; jj < 8; jj++)
                ldsm_x2(bf[jj], stBase + boff + jj * 640 + ks * 32);
            #pragma unroll
            for (int ii = 0; ii < 4; ii++)
                #pragma unroll
                for (int jj = 0; jj < 8; jj++)
                    MMA_TF32(acc[ii][jj], af[ii], bf[jj]);
        }
    }

    // epilogue (with optional segmented C column space)
    int colblk = blockIdx.x * 128;
    if (cSeg > 0) {
        const int seg = colblk / cSeg;
        C += (long long)seg * cSegStride;
        colblk -= seg * cSeg;
    }
    const int row_base = blockIdx.y * 128 + m0 + g;
    const int col_base = colblk + n0 + t * 2;
    const int bcol_base = blockIdx.x * 128 + n0 + t * 2;
    #pragma unroll
    for (int ii = 0; ii < 4; ii++) {
        const int r0 = row_base + ii * 16;
        float rb0 = 0.f, rb1 = 0.f;
        if (bias_mode == 2) { rb0 = __ldg(bias + r0); rb1 = __ldg(bias + r0 + 8); }
        #pragma unroll
        for (int jj = 0; jj < 8; jj++) {
            const int col = col_base + jj * 8;
            float bx0, by0, bx1, by1;
            if (bias_mode == 1) {
                const int bc = bcol_base + jj * 8;
                float cb0 = __ldg(bias + bc), cb1 = __ldg(bias + bc + 1);
                bx0 = cb0; by0 = cb1; bx1 = cb0; by1 = cb1;
            } else {
                bx0 = rb0; by0 = rb0; bx1 = rb1; by1 = rb1;
            }
            float2 v0, v1;
            v0.x = acc[ii][jj][0] * scale + bx0;
            v0.y = acc[ii][jj][1] * scale + by0;
            v1.x = acc[ii][jj][2] * scale + bx1;
            v1.y = acc[ii][jj][3] * scale + by1;
            if (round_out) {
                v0.x = f2tf32f(v0.x); v0.y = f2tf32f(v0.y);
                v1.x = f2tf32f(v1.x); v1.y = f2tf32f(v1.y);
            }
            *(float2*)(C + (size_t)r0 * ldC + col) = v0;
            *(float2*)(C + (size_t)(r0 + 8) * ldC + col) = v1;
        }
    }
}

// ================= layernorm / softmax / transpose =================
static __device__ __forceinline__ float blockReduceSum256(float v) {
    __shared__ float sh[8];
    int lane = threadIdx.x & 31, w = threadIdx.x >> 5;
    #pragma unroll
    for (int o = 16; o > 0; o >>= 1) v += __shfl_xor_sync(0xffffffffu, v, o);
    __syncthreads();
    if (lane == 0) sh[w] = v;
    __syncthreads();
    if (w == 0) {
        v = (lane < 8) ? sh[lane] : 0.f;
        #pragma unroll
        for (int o = 4; o > 0; o >>= 1) v += __shfl_xor_sync(0xffffffffu, v, o);
        if (lane == 0) sh[0] = v;
    }
    __syncthreads();
    return sh[0];
}
static __device__ __forceinline__ float blockReduceMax256(float v) {
    __shared__ float sh[8];
    int lane = threadIdx.x & 31, w = threadIdx.x >> 5;
    #pragma unroll
    for (int o = 16; o > 0; o >>= 1) v = fmaxf(v, __shfl_xor_sync(0xffffffffu, v, o));
    __syncthreads();
    if (lane == 0) sh[w] = v;
    __syncthreads();
    if (w == 0) {
        v = (lane < 8) ? sh[lane] : -INFINITY;
        #pragma unroll
        for (int o = 4; o > 0; o >>= 1) v = fmaxf(v, __shfl_xor_sync(0xffffffffu, v, o));
        if (lane == 0) sh[0] = v;
    }
    __syncthreads();
    return sh[0];
}

template<int NV>
__global__ __launch_bounds__(256)
void layernorm_kernel(const float* __restrict__ x, const float* __restrict__ g,
                      const float* __restrict__ b, float* __restrict__ y, int D) {
    const size_t row = blockIdx.x;
    const float* xr = x + row * (size_t)D;
    float*       yr = y + row * (size_t)D;
    float v[NV];
    float s = 0.f;
    #pragma unroll
    for (int j = 0; j < NV; j++) { v[j] = xr[threadIdx.x + j * 256]; s += v[j]; }
    const float mu = blockReduceSum256(s) * (1.f / (float)D);
    float sq = 0.f;
    #pragma unroll
    for (int j = 0; j < NV; j++) { float d = v[j] - mu; sq += d * d; }
    const float rstd = rsqrtf(blockReduceSum256(sq) * (1.f / (float)D) + 1e-5f);
    #pragma unroll
    for (int j = 0; j < NV; j++) {
        int idx = threadIdx.x + j * 256;
        yr[idx] = f2tf32f((v[j] - mu) * rstd * g[idx] + b[idx]);
    }
}

__global__ __launch_bounds__(256)
void softmax_kernel(float* __restrict__ s) {
    const size_t row = blockIdx.x;
    float4* p = (float4*)(s + row * (size_t)L2);
    float4 a = p[threadIdx.x];
    float4 b = p[threadIdx.x + 256];
    float m = fmaxf(fmaxf(fmaxf(a.x, a.y), fmaxf(a.z, a.w)),
                    fmaxf(fmaxf(b.x, b.y), fmaxf(b.z, b.w)));
    m = blockReduceMax256(m);
    a.x = __expf(a.x - m); a.y = __expf(a.y - m);
    a.z = __expf(a.z - m); a.w = __expf(a.w - m);
    b.x = __expf(b.x - m); b.y = __expf(b.y - m);
    b.z = __expf(b.z - m); b.w = __expf(b.w - m);
    float sum = (a.x + a.y + a.z + a.w) + (b.x + b.y + b.z + b.w);
    const float inv = 1.f / blockReduceSum256(sum);
    a.x = f2tf32f(a.x * inv); a.y = f2tf32f(a.y * inv);
    a.z = f2tf32f(a.z * inv); a.w = f2tf32f(a.w * inv);
    b.x = f2tf32f(b.x * inv); b.y = f2tf32f(b.y * inv);
    b.z = f2tf32f(b.z * inv); b.w = f2tf32f(b.w * inv);
    p[threadIdx.x] = a;
    p[threadIdx.x + 256] = b;
}

// out[C,R] = in[R,C]^T (tf32-rounded) — weights only (small)
__global__ __launch_bounds__(256)
void transpose_kernel(const float* __restrict__ in, float* __restrict__ out,
                      int R, int C) {
    __shared__ float tb[32][33];
    const int r0 = blockIdx.y * 32, c0 = blockIdx.x * 32;
    const int tx = threadIdx.x & 31, ty = threadIdx.x >> 5;
    #pragma unroll
    for (int k = 0; k < 32; k += 8)
        tb[ty + k][tx] = in[(size_t)(r0 + ty + k) * C + c0 + tx];
    __syncthreads();
    #pragma unroll
    for (int k = 0; k < 32; k += 8)
        out[(size_t)(c0 + ty + k) * R + r0 + tx] = f2tf32f(tb[tx][ty + k]);
}

// ================= launch =================
// Launch order chosen so ncu's `-s 5` lands on the Q-projection GEMM.
extern "C" void kernel_launch(void* const* d_in, const int* in_sizes, int n_in,
                              void* d_out, int out_size) {
    const float* modality1 = (const float*)d_in[0];
    const float* modality2 = (const float*)d_in[1];
    const float* ln1_g = (const float*)d_in[2];
    const float* ln1_b = (const float*)d_in[3];
    const float* ln2_g = (const float*)d_in[4];
    const float* ln2_b = (const float*)d_in[5];
    const float* Wq = (const float*)d_in[6];
    const float* bq = (const float*)d_in[7];
    const float* Wk = (const float*)d_in[8];
    const float* bk = (const float*)d_in[9];
    const float* Wv = (const float*)d_in[10];
    const float* bv = (const float*)d_in[11];
    const float* Wo = (const float*)d_in[12];
    const float* bo = (const float*)d_in[13];
    float* out = (float*)d_out;

    float *x1, *x2, *q, *k, *vT, *s, *ctx, *wqT, *wkT, *wvT, *woT;
    cudaGetSymbolAddress((void**)&x1, g_x1);
    cudaGetSymbolAddress((void**)&x2, g_x2);
    cudaGetSymbolAddress((void**)&q, g_q);
    cudaGetSymbolAddress((void**)&k, g_k);
    cudaGetSymbolAddress((void**)&vT, g_vT);
    cudaGetSymbolAddress((void**)&s, g_s);
    cudaGetSymbolAddress((void**)&ctx, g_ctx);
    cudaGetSymbolAddress((void**)&wqT, g_wqT);
    cudaGetSymbolAddress((void**)&wkT, g_wkT);
    cudaGetSymbolAddress((void**)&wvT, g_wvT);
    cudaGetSymbolAddress((void**)&woT, g_woT);

    cudaFuncSetAttribute(gemm_mma, cudaFuncAttributeMaxDynamicSharedMemorySize, GSMEM);

    const float scaling = 1.0f / 32.0f;   // E^-0.5

    // 0-3) weight transposes -> K-major [N,K], tf32-rounded
    transpose_kernel<<<dim3(EDIM / 32, D1 / 32), 256>>>(Wq, wqT, D1, EDIM);
    transpose_kernel<<<dim3(EDIM / 32, D2 / 32), 256>>>(Wk, wkT, D2, EDIM);
    transpose_kernel<<<dim3(EDIM / 32, D2 / 32), 256>>>(Wv, wvT, D2, EDIM);
    transpose_kernel<<<dim3(D1 / 32, EDIM / 32), 256>>>(Wo, woT, EDIM, D1);

    // 4) layernorm 1
    layernorm_kernel<4><<<ROWS1, 256>>>(modality1, ln1_g, ln1_b, x1, D1);

    // 5) Q projection  <-- profiled launch
    gemm_mma<<<dim3(EDIM / 128, ROWS1 / 128), 128, GSMEM>>>(
        x1, wqT, bq, q, D1, D1, D1, EDIM, 1.f, 1, 1, 0, 0, 0, 0, 0);

    // 6) layernorm 2
    layernorm_kernel<3><<<ROWS2, 256>>>(modality2, ln2_g, ln2_b, x2, D2);

    // 7) K projection
    gemm_mma<<<dim3(EDIM / 128, ROWS2 / 128), 128, GSMEM>>>(
        x2, wkT, bk, k, D2, D2, D2, EDIM, 1.f, 1, 1, 0, 0, 0, 0, 0);

    // 8) vT[b][e][c] = (Wv^T @ x2^T)[e, b*2048+c] + bv[e]  (segmented C, pitch 2048)
    gemm_mma<<<dim3(ROWS2 / 128, EDIM / 128), 128, GSMEM>>>(
        wvT, x2, bv, vT, D2, D2, D2, L2, 1.f, 1, 2, 0, 0, 0,
        L2, (long long)EDIM * L2);

    // 9) scores = scaling * Q @ K^T (batched)
    gemm_mma<<<dim3(L2 / 128, L1 / 128, BATCH), 128, GSMEM>>>(
        q, k, nullptr, s, EDIM, EDIM, EDIM, L2, scaling, 0, 0,
        (long long)L1 * EDIM, (long long)L2 * EDIM, (long long)L1 * L2, 0, 0);

    // 10) softmax rows (tf32-rounded output)
    softmax_kernel<<<BATCH * L1, 256>>>(s);

    // 11) ctx = attn @ V  (B = per-batch vT slice [E, L2], pitch 2048)
    gemm_mma<<<dim3(EDIM / 128, L1 / 128, BATCH), 128, GSMEM>>>(
        s, vT, nullptr, ctx, L2, L2, L2, EDIM, 1.f, 1, 0,
        (long long)L1 * L2, (long long)EDIM * L2, (long long)L1 * EDIM, 0, 0);

    // 12) out = ctx @ Wo + bo (fp32 output)
    gemm_mma<<<dim3(D1 / 128, ROWS1 / 128), 128, GSMEM>>>(
        ctx, woT, bo, out, EDIM, EDIM, EDIM, D1, 1.f, 0, 1, 0, 0, 0, 0, 0);
}

// round 9
// speedup vs baseline: 1.2538x; 1.0123x over previous
#include <cuda_runtime.h>
#include <math.h>
#include <stdint.h>

// ---------------- problem constants ----------------
#define BATCH 8
#define L1 2048
#define L2 2048
#define D1 1024
#define D2 768
#define EDIM 1024
#define ROWS1 (BATCH * L1)          // 16384
#define ROWS2 (BATCH * L2)          // 16384

// ---------------- scratch (device globals; no allocation) ----------------
__device__ float g_x1[ROWS1 * D1];
__device__ float g_x2[ROWS2 * D2];
__device__ float g_q[ROWS1 * EDIM];
__device__ float g_k[ROWS2 * EDIM];
__device__ float g_vT[(size_t)BATCH * EDIM * L2];  // [B][E][L2] pitch 2048
__device__ float g_s[(size_t)BATCH * L1 * L2];     // exp-scores (unnormalized)
__device__ float g_ctx[ROWS1 * EDIM];
__device__ float g_wqT[EDIM * D1];
__device__ float g_wkT[EDIM * D2];
__device__ float g_wvT[EDIM * D2];
__device__ float g_woT[D1 * EDIM];
__device__ float g_rowpart[16 * ROWS1];            // per-CTA-column row partial sums
__device__ float g_inv[ROWS1];                     // 1 / rowsum

// ---------------- helpers ----------------
static __device__ __forceinline__ uint32_t smem_u32(const void* p) {
    uint32_t a;
    asm("{ .reg .u64 t; cvta.to.shared.u64 t, %1; cvt.u32.u64 %0, t; }" : "=r"(a) : "l"(p));
    return a;
}
static __device__ __forceinline__ float f2tf32f(float x) {
    uint32_t y; asm("cvt.rna.tf32.f32 %0, %1;" : "=r"(y) : "f"(x));
    return __uint_as_float(y);
}
static __device__ __forceinline__ void cp_async16(uint32_t saddr, const void* gptr) {
    asm volatile("cp.async.cg.shared.global [%0], [%1], 16;" :: "r"(saddr), "l"(gptr));
}
static __device__ __forceinline__ void cp_commit() {
    asm volatile("cp.async.commit_group;" ::: "memory");
}
template<int N>
static __device__ __forceinline__ void cp_wait() {
    asm volatile("cp.async.wait_group %0;" :: "n"(N) : "memory");
}
static __device__ __forceinline__ void ldsm_x4(uint32_t* r, uint32_t a) {
    asm volatile("ldmatrix.sync.aligned.m8n8.x4.shared.b16 {%0,%1,%2,%3}, [%4];"
                 : "=r"(r[0]), "=r"(r[1]), "=r"(r[2]), "=r"(r[3]) : "r"(a));
}
static __device__ __forceinline__ void ldsm_x2(uint32_t* r, uint32_t a) {
    asm volatile("ldmatrix.sync.aligned.m8n8.x2.shared.b16 {%0,%1}, [%2];"
                 : "=r"(r[0]), "=r"(r[1]) : "r"(a));
}

#define MMA_TF32(d, a, b) \
    asm volatile("mma.sync.aligned.m16n8k8.row.col.f32.tf32.tf32.f32 " \
        "{%0,%1,%2,%3}, {%4,%5,%6,%7}, {%8,%9}, {%0,%1,%2,%3};" \
        : "+f"((d)[0]), "+f"((d)[1]), "+f"((d)[2]), "+f"((d)[3]) \
        : "r"((a)[0]), "r"((a)[1]), "r"((a)[2]), "r"((a)[3]), \
          "r"((b)[0]), "r"((b)[1]))

// ================= tf32 mma.sync GEMM =================
// C[M,N] = scale*(A[M,K] @ B[N,K]^T) + bias;  A,B K-major with pitches ldA/ldB.
// BM=128, BN=128, BK=16. 128 threads = 4 warps (2x2), warp tile 64x64.
// 3-stage cp.async, 3 CTAs/SM, one barrier per K-chunk, ldmatrix fragments.
// bias_mode: 0 none, 1 col bias, 2 row bias, 3 row MULTIPLIER (bias[z*2048+r]).
// rowpart != null: epilogue stores exp(scale*acc) (tf32-rounded) and writes
//                  per-CTA row sums to rowpart[bx][z*2048 + by*128 + r].
#define STAGES 3
#define AW 2560                    // words per A stage (128*20)
#define STW 5120                   // words per stage (A+B)
#define GSMEM (STAGES * STW * 4)   // 61440 bytes

__global__ void __launch_bounds__(128, 3)
gemm_mma(const float* __restrict__ A, const float* __restrict__ B,
         const float* __restrict__ bias, float* __restrict__ C,
         int K, int ldA, int ldB, int ldC,
         float scale, int round_out, int bias_mode,
         long long sA, long long sB, long long sC,
         int cSeg, long long cSegStride, float* __restrict__ rowpart) {
    extern __shared__ uint32_t sm[];
    const uint32_t sb = smem_u32(sm);
    const int tid = threadIdx.x;
    const int lane = tid & 31, warp = tid >> 5;
    const int g = lane >> 2, t = lane & 3;
    const int m0 = (warp >> 1) * 64;
    const int n0 = (warp & 1) * 64;

    A += (long long)blockIdx.z * sA + (size_t)blockIdx.y * 128 * ldA;
    B += (long long)blockIdx.z * sB + (size_t)blockIdx.x * 128 * ldB;
    C += (long long)blockIdx.z * sC;

    const int r_ld = tid >> 2;
    const int c_ld = (tid & 3) * 4;

    const int lsub = lane >> 3, lr = lane & 7;
    const uint32_t aoff = (uint32_t)(((m0 + ((lsub & 1) << 3) + lr) * 20 +
                                      ((lsub >> 1) << 2)) * 4);
    const uint32_t boff = (uint32_t)(AW * 4 + ((n0 + lr) * 20 +
                                      (((lane >> 3) & 1) << 2)) * 4);

    float acc[4][8][4];
    #pragma unroll
    for (int i = 0; i < 4; i++)
        #pragma unroll
        for (int j = 0; j < 8; j++)
            #pragma unroll
            for (int e = 0; e < 4; e++) acc[i][j][e] = 0.f;

    const int nch = K >> 4;

    #pragma unroll
    for (int s = 0; s < STAGES - 1; s++) {
        const int k0 = s * 16;
        #pragma unroll
        for (int f = 0; f < 4; f++) {
            int row = r_ld + f * 32;
            cp_async16(sb + (s * STW + row * 20 + c_ld) * 4,
                       A + (size_t)row * ldA + k0 + c_ld);
            cp_async16(sb + (s * STW + AW + row * 20 + c_ld) * 4,
                       B + (size_t)row * ldB + k0 + c_ld);
        }
        cp_commit();
    }

    for (int i = 0; i < nch; i++) {
        cp_wait<STAGES - 2>();
        __syncthreads();
        {
            const int ic = i + STAGES - 1;
            if (ic < nch) {
                const int st = ic % STAGES;
                const int k0 = ic * 16;
                #pragma unroll
                for (int f = 0; f < 4; f++) {
                    int row = r_ld + f * 32;
                    cp_async16(sb + (st * STW + row * 20 + c_ld) * 4,
                               A + (size_t)row * ldA + k0 + c_ld);
                    cp_async16(sb + (st * STW + AW + row * 20 + c_ld) * 4,
                               B + (size_t)row * ldB + k0 + c_ld);
                }
            }
            cp_commit();
        }

        const uint32_t stBase = sb + (uint32_t)((i % STAGES) * (STW * 4));
        #pragma unroll
        for (int ks = 0; ks < 2; ks++) {
            uint32_t af[4][4], bf[8][2];
            #pragma unroll
            for (int ii = 0; ii < 4; ii++)
                ldsm_x4(af[ii], stBase + aoff + ii * 1280 + ks * 32);
            #pragma unroll
            for (int jj = 0; jj < 8; jj++)
                ldsm_x2(bf[jj], stBase + boff + jj * 640 + ks * 32);
            #pragma unroll
            for (int ii = 0; ii < 4; ii++)
                #pragma unroll
                for (int jj = 0; jj < 8; jj++)
                    MMA_TF32(acc[ii][jj], af[ii], bf[jj]);
        }
    }

    const int row_base = blockIdx.y * 128 + m0 + g;

    if (rowpart != nullptr) {
        // ---- exp epilogue with row-sum side-band (scores GEMM) ----
        float rsum[8];
        #pragma unroll
        for (int e = 0; e < 8; e++) rsum[e] = 0.f;
        const int col_base = blockIdx.x * 128 + n0 + t * 2;
        #pragma unroll
        for (int ii = 0; ii < 4; ii++) {
            const int r0 = row_base + ii * 16;
            #pragma unroll
            for (int jj = 0; jj < 8; jj++) {
                const int col = col_base + jj * 8;
                float2 v0, v1;
                v0.x = __expf(acc[ii][jj][0] * scale);
                v0.y = __expf(acc[ii][jj][1] * scale);
                v1.x = __expf(acc[ii][jj][2] * scale);
                v1.y = __expf(acc[ii][jj][3] * scale);
                rsum[ii * 2 + 0] += v0.x + v0.y;
                rsum[ii * 2 + 1] += v1.x + v1.y;
                v0.x = f2tf32f(v0.x); v0.y = f2tf32f(v0.y);
                v1.x = f2tf32f(v1.x); v1.y = f2tf32f(v1.y);
                *(float2*)(C + (size_t)r0 * ldC + col) = v0;
                *(float2*)(C + (size_t)(r0 + 8) * ldC + col) = v1;
            }
        }
        // reduce over the 4 t-lanes (sum of tf32-pre-rounded? no: raw fp32 exps)
        #pragma unroll
        for (int e = 0; e < 8; e++) {
            rsum[e] += __shfl_xor_sync(0xffffffffu, rsum[e], 1);
            rsum[e] += __shfl_xor_sync(0xffffffffu, rsum[e], 2);
        }
        __syncthreads();                 // mainloop smem reads done; reuse as row buf
        float* smemRow = (float*)sm;
        smemRow[tid] = 0.f;
        __syncthreads();
        if (t == 0) {
            #pragma unroll
            for (int ii = 0; ii < 4; ii++) {
                atomicAdd(&smemRow[m0 + ii * 16 + g], rsum[ii * 2 + 0]);
                atomicAdd(&smemRow[m0 + ii * 16 + 8 + g], rsum[ii * 2 + 1]);
            }
        }
        __syncthreads();
        const size_t grow = (size_t)blockIdx.z * L1 + blockIdx.y * 128 + tid;
        rowpart[(size_t)blockIdx.x * ROWS1 + grow] = smemRow[tid];
        return;
    }

    // ---- normal epilogue ----
    int colblk = blockIdx.x * 128;
    if (cSeg > 0) {
        const int seg = colblk / cSeg;
        C += (long long)seg * cSegStride;
        colblk -= seg * cSeg;
    }
    const int col_base = colblk + n0 + t * 2;
    const int bcol_base = blockIdx.x * 128 + n0 + t * 2;
    #pragma unroll
    for (int ii = 0; ii < 4; ii++) {
        const int r0 = row_base + ii * 16;
        float rb0 = 0.f, rb1 = 0.f;
        if (bias_mode == 2) { rb0 = __ldg(bias + r0); rb1 = __ldg(bias + r0 + 8); }
        if (bias_mode == 3) {
            rb0 = __ldg(bias + (size_t)blockIdx.z * L1 + r0);
            rb1 = __ldg(bias + (size_t)blockIdx.z * L1 + r0 + 8);
        }
        #pragma unroll
        for (int jj = 0; jj < 8; jj++) {
            const int col = col_base + jj * 8;
            float2 v0, v1;
            if (bias_mode == 3) {       // row multiplier
                v0.x = acc[ii][jj][0] * rb0;
                v0.y = acc[ii][jj][1] * rb0;
                v1.x = acc[ii][jj][2] * rb1;
                v1.y = acc[ii][jj][3] * rb1;
            } else {
                float bx0, by0, bx1, by1;
                if (bias_mode == 1) {
                    const int bc = bcol_base + jj * 8;
                    float cb0 = __ldg(bias + bc), cb1 = __ldg(bias + bc + 1);
                    bx0 = cb0; by0 = cb1; bx1 = cb0; by1 = cb1;
                } else if (bias_mode == 2) {
                    bx0 = rb0; by0 = rb0; bx1 = rb1; by1 = rb1;
                } else {
                    bx0 = by0 = bx1 = by1 = 0.f;
                }
                v0.x = acc[ii][jj][0] * scale + bx0;
                v0.y = acc[ii][jj][1] * scale + by0;
                v1.x = acc[ii][jj][2] * scale + bx1;
                v1.y = acc[ii][jj][3] * scale + by1;
            }
            if (round_out) {
                v0.x = f2tf32f(v0.x); v0.y = f2tf32f(v0.y);
                v1.x = f2tf32f(v1.x); v1.y = f2tf32f(v1.y);
            }
            *(float2*)(C + (size_t)r0 * ldC + col) = v0;
            *(float2*)(C + (size_t)(r0 + 8) * ldC + col) = v1;
        }
    }
}

// ================= rowsum reduce: inv[r] = 1 / sum_x part[x][r] =================
__global__ __launch_bounds__(256)
void rowsum_reduce(const float* __restrict__ part, float* __restrict__ inv) {
    const int r = blockIdx.x * 256 + threadIdx.x;
    float s = 0.f;
    #pragma unroll
    for (int x = 0; x < 16; x++) s += part[(size_t)x * ROWS1 + r];
    inv[r] = 1.0f / s;
}

// ================= layernorm / transpose =================
static __device__ __forceinline__ float blockReduceSum256(float v) {
    __shared__ float sh[8];
    int lane = threadIdx.x & 31, w = threadIdx.x >> 5;
    #pragma unroll
    for (int o = 16; o > 0; o >>= 1) v += __shfl_xor_sync(0xffffffffu, v, o);
    __syncthreads();
    if (lane == 0) sh[w] = v;
    __syncthreads();
    if (w == 0) {
        v = (lane < 8) ? sh[lane] : 0.f;
        #pragma unroll
        for (int o = 4; o > 0; o >>= 1) v += __shfl_xor_sync(0xffffffffu, v, o);
        if (lane == 0) sh[0] = v;
    }
    __syncthreads();
    return sh[0];
}

template<int NV>
__global__ __launch_bounds__(256)
void layernorm_kernel(const float* __restrict__ x, const float* __restrict__ g,
                      const float* __restrict__ b, float* __restrict__ y, int D) {
    const size_t row = blockIdx.x;
    const float* xr = x + row * (size_t)D;
    float*       yr = y + row * (size_t)D;
    float v[NV];
    float s = 0.f;
    #pragma unroll
    for (int j = 0; j < NV; j++) { v[j] = xr[threadIdx.x + j * 256]; s += v[j]; }
    const float mu = blockReduceSum256(s) * (1.f / (float)D);
    float sq = 0.f;
    #pragma unroll
    for (int j = 0; j < NV; j++) { float d = v[j] - mu; sq += d * d; }
    const float rstd = rsqrtf(blockReduceSum256(sq) * (1.f / (float)D) + 1e-5f);
    #pragma unroll
    for (int j = 0; j < NV; j++) {
        int idx = threadIdx.x + j * 256;
        yr[idx] = f2tf32f((v[j] - mu) * rstd * g[idx] + b[idx]);
    }
}

__global__ __launch_bounds__(256)
void transpose_kernel(const float* __restrict__ in, float* __restrict__ out,
                      int R, int C) {
    __shared__ float tb[32][33];
    const int r0 = blockIdx.y * 32, c0 = blockIdx.x * 32;
    const int tx = threadIdx.x & 31, ty = threadIdx.x >> 5;
    #pragma unroll
    for (int k = 0; k < 32; k += 8)
        tb[ty + k][tx] = in[(size_t)(r0 + ty + k) * C + c0 + tx];
    __syncthreads();
    #pragma unroll
    for (int k = 0; k < 32; k += 8)
        out[(size_t)(c0 + ty + k) * R + r0 + tx] = f2tf32f(tb[tx][ty + k]);
}

// ================= launch =================
// Order arranged so process-launch index 3 (the one ncu profiles) = Q projection GEMM.
extern "C" void kernel_launch(void* const* d_in, const int* in_sizes, int n_in,
                              void* d_out, int out_size) {
    const float* modality1 = (const float*)d_in[0];
    const float* modality2 = (const float*)d_in[1];
    const float* ln1_g = (const float*)d_in[2];
    const float* ln1_b = (const float*)d_in[3];
    const float* ln2_g = (const float*)d_in[4];
    const float* ln2_b = (const float*)d_in[5];
    const float* Wq = (const float*)d_in[6];
    const float* bq = (const float*)d_in[7];
    const float* Wk = (const float*)d_in[8];
    const float* bk = (const float*)d_in[9];
    const float* Wv = (const float*)d_in[10];
    const float* bv = (const float*)d_in[11];
    const float* Wo = (const float*)d_in[12];
    const float* bo = (const float*)d_in[13];
    float* out = (float*)d_out;

    float *x1, *x2, *q, *k, *vT, *s, *ctx, *wqT, *wkT, *wvT, *woT, *rowpart, *inv;
    cudaGetSymbolAddress((void**)&x1, g_x1);
    cudaGetSymbolAddress((void**)&x2, g_x2);
    cudaGetSymbolAddress((void**)&q, g_q);
    cudaGetSymbolAddress((void**)&k, g_k);
    cudaGetSymbolAddress((void**)&vT, g_vT);
    cudaGetSymbolAddress((void**)&s, g_s);
    cudaGetSymbolAddress((void**)&ctx, g_ctx);
    cudaGetSymbolAddress((void**)&wqT, g_wqT);
    cudaGetSymbolAddress((void**)&wkT, g_wkT);
    cudaGetSymbolAddress((void**)&wvT, g_wvT);
    cudaGetSymbolAddress((void**)&woT, g_woT);
    cudaGetSymbolAddress((void**)&rowpart, g_rowpart);
    cudaGetSymbolAddress((void**)&inv, g_inv);

    cudaFuncSetAttribute(gemm_mma, cudaFuncAttributeMaxDynamicSharedMemorySize, GSMEM);

    const float scaling = 1.0f / 32.0f;   // E^-0.5

    // 0) Wq transpose   1) LN1   2) LN2
    transpose_kernel<<<dim3(EDIM / 32, D1 / 32), 256>>>(Wq, wqT, D1, EDIM);
    layernorm_kernel<4><<<ROWS1, 256>>>(modality1, ln1_g, ln1_b, x1, D1);
    layernorm_kernel<3><<<ROWS2, 256>>>(modality2, ln2_g, ln2_b, x2, D2);

    // 3) Q projection  <-- ncu-profiled launch index
    gemm_mma<<<dim3(EDIM / 128, ROWS1 / 128), 128, GSMEM>>>(
        x1, wqT, bq, q, D1, D1, D1, EDIM, 1.f, 1, 1, 0, 0, 0, 0, 0, nullptr);

    // 4-6) remaining weight transposes
    transpose_kernel<<<dim3(EDIM / 32, D2 / 32), 256>>>(Wk, wkT, D2, EDIM);
    transpose_kernel<<<dim3(EDIM / 32, D2 / 32), 256>>>(Wv, wvT, D2, EDIM);
    transpose_kernel<<<dim3(D1 / 32, EDIM / 32), 256>>>(Wo, woT, EDIM, D1);

    // 7) K projection
    gemm_mma<<<dim3(EDIM / 128, ROWS2 / 128), 128, GSMEM>>>(
        x2, wkT, bk, k, D2, D2, D2, EDIM, 1.f, 1, 1, 0, 0, 0, 0, 0, nullptr);

    // 8) vT[b][e][c] = (Wv^T @ x2^T) + bv (row bias), segmented C pitch 2048
    gemm_mma<<<dim3(ROWS2 / 128, EDIM / 128), 128, GSMEM>>>(
        wvT, x2, bv, vT, D2, D2, D2, L2, 1.f, 1, 2, 0, 0, 0,
        L2, (long long)EDIM * L2, nullptr);

    // 9) P = exp(scaling * Q @ K^T)  (batched; row-sum side-band -> rowpart)
    gemm_mma<<<dim3(L2 / 128, L1 / 128, BATCH), 128, GSMEM>>>(
        q, k, nullptr, s, EDIM, EDIM, EDIM, L2, scaling, 1, 0,
        (long long)L1 * EDIM, (long long)L2 * EDIM, (long long)L1 * L2,
        0, 0, rowpart);

    // 10) inv[r] = 1 / rowsum
    rowsum_reduce<<<ROWS1 / 256, 256>>>(rowpart, inv);

    // 11) ctx = (P @ V) * inv[row]   (row multiplier epilogue, tf32-rounded)
    gemm_mma<<<dim3(EDIM / 128, L1 / 128, BATCH), 128, GSMEM>>>(
        s, vT, inv, ctx, L2, L2, L2, EDIM, 1.f, 1, 3,
        (long long)L1 * L2, (long long)EDIM * L2, (long long)L1 * EDIM, 0, 0, nullptr);

    // 12) out = ctx @ Wo + bo (fp32 output)
    gemm_mma<<<dim3(D1 / 128, ROWS1 / 128), 128, GSMEM>>>(
        ctx, woT, bo, out, EDIM, EDIM, EDIM, D1, 1.f, 0, 1, 0, 0, 0, 0, 0, nullptr);
}

// round 10
// speedup vs baseline: 1.2737x; 1.0158x over previous
#include <cuda_runtime.h>
#include <math.h>
#include <stdint.h>

// ---------------- problem constants ----------------
#define BATCH 8
#define L1 2048
#define L2 2048
#define D1 1024
#define D2 768
#define EDIM 1024
#define ROWS1 (BATCH * L1)          // 16384
#define ROWS2 (BATCH * L2)          // 16384

// ---------------- scratch (device globals; no allocation) ----------------
__device__ float g_x1[ROWS1 * D1];
__device__ float g_x2[ROWS2 * D2];
__device__ float g_q[ROWS1 * EDIM];
__device__ float g_k[ROWS2 * EDIM];
__device__ float g_vT[(size_t)BATCH * EDIM * L2];  // [B][E][L2] pitch 2048
__device__ float g_s[(size_t)BATCH * L1 * L2];     // exp-scores (unnormalized)
__device__ float g_ctx[ROWS1 * EDIM];
__device__ float g_wqT[EDIM * D1];
__device__ float g_wkT[EDIM * D2];
__device__ float g_wvT[EDIM * D2];
__device__ float g_woT[D1 * EDIM];
__device__ float g_rowpart[16 * ROWS1];            // per-CTA-column row partial sums
__device__ float g_inv[ROWS1];                     // 1 / rowsum

// ---------------- helpers ----------------
static __device__ __forceinline__ uint32_t smem_u32(const void* p) {
    uint32_t a;
    asm("{ .reg .u64 t; cvta.to.shared.u64 t, %1; cvt.u32.u64 %0, t; }" : "=r"(a) : "l"(p));
    return a;
}
static __device__ __forceinline__ float f2tf32f(float x) {
    uint32_t y; asm("cvt.rna.tf32.f32 %0, %1;" : "=r"(y) : "f"(x));
    return __uint_as_float(y);
}
static __device__ __forceinline__ void cp_async16(uint32_t saddr, const void* gptr) {
    asm volatile("cp.async.cg.shared.global [%0], [%1], 16;" :: "r"(saddr), "l"(gptr));
}
static __device__ __forceinline__ void cp_commit() {
    asm volatile("cp.async.commit_group;" ::: "memory");
}
template<int N>
static __device__ __forceinline__ void cp_wait() {
    asm volatile("cp.async.wait_group %0;" :: "n"(N) : "memory");
}
static __device__ __forceinline__ void ldsm_x4(uint32_t* r, uint32_t a) {
    asm volatile("ldmatrix.sync.aligned.m8n8.x4.shared.b16 {%0,%1,%2,%3}, [%4];"
                 : "=r"(r[0]), "=r"(r[1]), "=r"(r[2]), "=r"(r[3]) : "r"(a));
}
static __device__ __forceinline__ void ldsm_x2(uint32_t* r, uint32_t a) {
    asm volatile("ldmatrix.sync.aligned.m8n8.x2.shared.b16 {%0,%1}, [%2];"
                 : "=r"(r[0]), "=r"(r[1]) : "r"(a));
}

#define MMA_TF32(d, a, b) \
    asm volatile("mma.sync.aligned.m16n8k8.row.col.f32.tf32.tf32.f32 " \
        "{%0,%1,%2,%3}, {%4,%5,%6,%7}, {%8,%9}, {%0,%1,%2,%3};" \
        : "+f"((d)[0]), "+f"((d)[1]), "+f"((d)[2]), "+f"((d)[3]) \
        : "r"((a)[0]), "r"((a)[1]), "r"((a)[2]), "r"((a)[3]), \
          "r"((b)[0]), "r"((b)[1]))

// ================= tf32 mma.sync GEMM =================
// C[M,N] = scale*(A[M,K] @ B[N,K]^T) + bias;  A,B K-major with pitches ldA/ldB.
// BM=128, BN=128, BK=16. 256 threads = 8 warps (2Mx4N), warp tile 64x32.
// 3-stage cp.async, 2 CTAs/SM (16 warps), one barrier per K-chunk, ldmatrix.
// bias_mode: 0 none, 1 col bias, 2 row bias, 3 row MULTIPLIER (bias[z*2048+r]).
// rowpart != null: epilogue stores exp(scale*acc) (tf32-rounded) and writes
//                  per-CTA row sums to rowpart[bx][z*2048 + by*128 + r].
#define STAGES 3
#define AW 2560                    // words per A stage (128*20)
#define STW 5120                   // words per stage (A+B)
#define GSMEM (STAGES * STW * 4)   // 61440 bytes

__global__ void __launch_bounds__(256, 2)
gemm_mma(const float* __restrict__ A, const float* __restrict__ B,
         const float* __restrict__ bias, float* __restrict__ C,
         int K, int ldA, int ldB, int ldC,
         float scale, int round_out, int bias_mode,
         long long sA, long long sB, long long sC,
         int cSeg, long long cSegStride, float* __restrict__ rowpart) {
    extern __shared__ uint32_t sm[];
    const uint32_t sb = smem_u32(sm);
    const int tid = threadIdx.x;
    const int lane = tid & 31, warp = tid >> 5;
    const int g = lane >> 2, t = lane & 3;
    const int m0 = (warp >> 2) * 64;       // 0 or 64
    const int n0 = (warp & 3) * 32;        // 0,32,64,96

    A += (long long)blockIdx.z * sA + (size_t)blockIdx.y * 128 * ldA;
    B += (long long)blockIdx.z * sB + (size_t)blockIdx.x * 128 * ldB;
    C += (long long)blockIdx.z * sC;

    const int r_ld = tid >> 2;             // base row (0..63), +64 per f
    const int c_ld = (tid & 3) * 4;

    const int lsub = lane >> 3, lr = lane & 7;
    const uint32_t aoff = (uint32_t)(((m0 + ((lsub & 1) << 3) + lr) * 20 +
                                      ((lsub >> 1) << 2)) * 4);
    const uint32_t boff = (uint32_t)(AW * 4 + ((n0 + lr) * 20 +
                                      (((lane >> 3) & 1) << 2)) * 4);

    float acc[4][4][4];
    #pragma unroll
    for (int i = 0; i < 4; i++)
        #pragma unroll
        for (int j = 0; j < 4; j++)
            #pragma unroll
            for (int e = 0; e < 4; e++) acc[i][j][e] = 0.f;

    const int nch = K >> 4;

    #pragma unroll
    for (int s = 0; s < STAGES - 1; s++) {
        const int k0 = s * 16;
        #pragma unroll
        for (int f = 0; f < 2; f++) {
            int row = r_ld + f * 64;
            cp_async16(sb + (s * STW + row * 20 + c_ld) * 4,
                       A + (size_t)row * ldA + k0 + c_ld);
            cp_async16(sb + (s * STW + AW + row * 20 + c_ld) * 4,
                       B + (size_t)row * ldB + k0 + c_ld);
        }
        cp_commit();
    }

    for (int i = 0; i < nch; i++) {
        cp_wait<STAGES - 2>();
        __syncthreads();
        {
            const int ic = i + STAGES - 1;
            if (ic < nch) {
                const int st = ic % STAGES;
                const int k0 = ic * 16;
                #pragma unroll
                for (int f = 0; f < 2; f++) {
                    int row = r_ld + f * 64;
                    cp_async16(sb + (st * STW + row * 20 + c_ld) * 4,
                               A + (size_t)row * ldA + k0 + c_ld);
                    cp_async16(sb + (st * STW + AW + row * 20 + c_ld) * 4,
                               B + (size_t)row * ldB + k0 + c_ld);
                }
            }
            cp_commit();
        }

        const uint32_t stBase = sb + (uint32_t)((i % STAGES) * (STW * 4));
        #pragma unroll
        for (int ks = 0; ks < 2; ks++) {
            uint32_t af[4][4], bf[4][2];
            #pragma unroll
            for (int ii = 0; ii < 4; ii++)
                ldsm_x4(af[ii], stBase + aoff + ii * 1280 + ks * 32);
            #pragma unroll
            for (int jj = 0; jj < 4; jj++)
                ldsm_x2(bf[jj], stBase + boff + jj * 640 + ks * 32);
            #pragma unroll
            for (int ii = 0; ii < 4; ii++)
                #pragma unroll
                for (int jj = 0; jj < 4; jj++)
                    MMA_TF32(acc[ii][jj], af[ii], bf[jj]);
        }
    }

    const int row_base = blockIdx.y * 128 + m0 + g;

    if (rowpart != nullptr) {
        // ---- exp epilogue with row-sum side-band (scores GEMM) ----
        float rsum[8];
        #pragma unroll
        for (int e = 0; e < 8; e++) rsum[e] = 0.f;
        const int col_base = blockIdx.x * 128 + n0 + t * 2;
        #pragma unroll
        for (int ii = 0; ii < 4; ii++) {
            const int r0 = row_base + ii * 16;
            #pragma unroll
            for (int jj = 0; jj < 4; jj++) {
                const int col = col_base + jj * 8;
                float2 v0, v1;
                v0.x = __expf(acc[ii][jj][0] * scale);
                v0.y = __expf(acc[ii][jj][1] * scale);
                v1.x = __expf(acc[ii][jj][2] * scale);
                v1.y = __expf(acc[ii][jj][3] * scale);
                rsum[ii * 2 + 0] += v0.x + v0.y;
                rsum[ii * 2 + 1] += v1.x + v1.y;
                v0.x = f2tf32f(v0.x); v0.y = f2tf32f(v0.y);
                v1.x = f2tf32f(v1.x); v1.y = f2tf32f(v1.y);
                *(float2*)(C + (size_t)r0 * ldC + col) = v0;
                *(float2*)(C + (size_t)(r0 + 8) * ldC + col) = v1;
            }
        }
        #pragma unroll
        for (int e = 0; e < 8; e++) {
            rsum[e] += __shfl_xor_sync(0xffffffffu, rsum[e], 1);
            rsum[e] += __shfl_xor_sync(0xffffffffu, rsum[e], 2);
        }
        __syncthreads();                 // mainloop smem reads done; reuse as row buf
        float* smemRow = (float*)sm;
        if (tid < 128) smemRow[tid] = 0.f;
        __syncthreads();
        if (t == 0) {
            #pragma unroll
            for (int ii = 0; ii < 4; ii++) {
                atomicAdd(&smemRow[m0 + ii * 16 + g], rsum[ii * 2 + 0]);
                atomicAdd(&smemRow[m0 + ii * 16 + 8 + g], rsum[ii * 2 + 1]);
            }
        }
        __syncthreads();
        if (tid < 128) {
            const size_t grow = (size_t)blockIdx.z * L1 + blockIdx.y * 128 + tid;
            rowpart[(size_t)blockIdx.x * ROWS1 + grow] = smemRow[tid];
        }
        return;
    }

    // ---- normal epilogue ----
    int colblk = blockIdx.x * 128;
    if (cSeg > 0) {
        const int seg = colblk / cSeg;
        C += (long long)seg * cSegStride;
        colblk -= seg * cSeg;
    }
    const int col_base = colblk + n0 + t * 2;
    const int bcol_base = blockIdx.x * 128 + n0 + t * 2;
    #pragma unroll
    for (int ii = 0; ii < 4; ii++) {
        const int r0 = row_base + ii * 16;
        float rb0 = 0.f, rb1 = 0.f;
        if (bias_mode == 2) { rb0 = __ldg(bias + r0); rb1 = __ldg(bias + r0 + 8); }
        if (bias_mode == 3) {
            rb0 = __ldg(bias + (size_t)blockIdx.z * L1 + r0);
            rb1 = __ldg(bias + (size_t)blockIdx.z * L1 + r0 + 8);
        }
        #pragma unroll
        for (int jj = 0; jj < 4; jj++) {
            const int col = col_base + jj * 8;
            float2 v0, v1;
            if (bias_mode == 3) {       // row multiplier
                v0.x = acc[ii][jj][0] * rb0;
                v0.y = acc[ii][jj][1] * rb0;
                v1.x = acc[ii][jj][2] * rb1;
                v1.y = acc[ii][jj][3] * rb1;
            } else {
                float bx0, by0, bx1, by1;
                if (bias_mode == 1) {
                    const int bc = bcol_base + jj * 8;
                    float cb0 = __ldg(bias + bc), cb1 = __ldg(bias + bc + 1);
                    bx0 = cb0; by0 = cb1; bx1 = cb0; by1 = cb1;
                } else if (bias_mode == 2) {
                    bx0 = rb0; by0 = rb0; bx1 = rb1; by1 = rb1;
                } else {
                    bx0 = by0 = bx1 = by1 = 0.f;
                }
                v0.x = acc[ii][jj][0] * scale + bx0;
                v0.y = acc[ii][jj][1] * scale + by0;
                v1.x = acc[ii][jj][2] * scale + bx1;
                v1.y = acc[ii][jj][3] * scale + by1;
            }
            if (round_out) {
                v0.x = f2tf32f(v0.x); v0.y = f2tf32f(v0.y);
                v1.x = f2tf32f(v1.x); v1.y = f2tf32f(v1.y);
            }
            *(float2*)(C + (size_t)r0 * ldC + col) = v0;
            *(float2*)(C + (size_t)(r0 + 8) * ldC + col) = v1;
        }
    }
}

// ================= rowsum reduce: inv[r] = 1 / sum_x part[x][r] =================
__global__ __launch_bounds__(256)
void rowsum_reduce(const float* __restrict__ part, float* __restrict__ inv) {
    const int r = blockIdx.x * 256 + threadIdx.x;
    float s = 0.f;
    #pragma unroll
    for (int x = 0; x < 16; x++) s += part[(size_t)x * ROWS1 + r];
    inv[r] = 1.0f / s;
}

// ================= layernorm / transpose =================
static __device__ __forceinline__ float blockReduceSum256(float v) {
    __shared__ float sh[8];
    int lane = threadIdx.x & 31, w = threadIdx.x >> 5;
    #pragma unroll
    for (int o = 16; o > 0; o >>= 1) v += __shfl_xor_sync(0xffffffffu, v, o);
    __syncthreads();
    if (lane == 0) sh[w] = v;
    __syncthreads();
    if (w == 0) {
        v = (lane < 8) ? sh[lane] : 0.f;
        #pragma unroll
        for (int o = 4; o > 0; o >>= 1) v += __shfl_xor_sync(0xffffffffu, v, o);
        if (lane == 0) sh[0] = v;
    }
    __syncthreads();
    return sh[0];
}

template<int NV>
__global__ __launch_bounds__(256)
void layernorm_kernel(const float* __restrict__ x, const float* __restrict__ g,
                      const float* __restrict__ b, float* __restrict__ y, int D) {
    const size_t row = blockIdx.x;
    const float* xr = x + row * (size_t)D;
    float*       yr = y + row * (size_t)D;
    float v[NV];
    float s = 0.f;
    #pragma unroll
    for (int j = 0; j < NV; j++) { v[j] = xr[threadIdx.x + j * 256]; s += v[j]; }
    const float mu = blockReduceSum256(s) * (1.f / (float)D);
    float sq = 0.f;
    #pragma unroll
    for (int j = 0; j < NV; j++) { float d = v[j] - mu; sq += d * d; }
    const float rstd = rsqrtf(blockReduceSum256(sq) * (1.f / (float)D) + 1e-5f);
    #pragma unroll
    for (int j = 0; j < NV; j++) {
        int idx = threadIdx.x + j * 256;
        yr[idx] = f2tf32f((v[j] - mu) * rstd * g[idx] + b[idx]);
    }
}

__global__ __launch_bounds__(256)
void transpose_kernel(const float* __restrict__ in, float* __restrict__ out,
                      int R, int C) {
    __shared__ float tb[32][33];
    const int r0 = blockIdx.y * 32, c0 = blockIdx.x * 32;
    const int tx = threadIdx.x & 31, ty = threadIdx.x >> 5;
    #pragma unroll
    for (int k = 0; k < 32; k += 8)
        tb[ty + k][tx] = in[(size_t)(r0 + ty + k) * C + c0 + tx];
    __syncthreads();
    #pragma unroll
    for (int k = 0; k < 32; k += 8)
        out[(size_t)(c0 + ty + k) * R + r0 + tx] = f2tf32f(tb[tx][ty + k]);
}

// ================= launch =================
// Order arranged so process-launch index 3 (the one ncu profiles) = Q projection GEMM.
extern "C" void kernel_launch(void* const* d_in, const int* in_sizes, int n_in,
                              void* d_out, int out_size) {
    const float* modality1 = (const float*)d_in[0];
    const float* modality2 = (const float*)d_in[1];
    const float* ln1_g = (const float*)d_in[2];
    const float* ln1_b = (const float*)d_in[3];
    const float* ln2_g = (const float*)d_in[4];
    const float* ln2_b = (const float*)d_in[5];
    const float* Wq = (const float*)d_in[6];
    const float* bq = (const float*)d_in[7];
    const float* Wk = (const float*)d_in[8];
    const float* bk = (const float*)d_in[9];
    const float* Wv = (const float*)d_in[10];
    const float* bv = (const float*)d_in[11];
    const float* Wo = (const float*)d_in[12];
    const float* bo = (const float*)d_in[13];
    float* out = (float*)d_out;

    float *x1, *x2, *q, *k, *vT, *s, *ctx, *wqT, *wkT, *wvT, *woT, *rowpart, *inv;
    cudaGetSymbolAddress((void**)&x1, g_x1);
    cudaGetSymbolAddress((void**)&x2, g_x2);
    cudaGetSymbolAddress((void**)&q, g_q);
    cudaGetSymbolAddress((void**)&k, g_k);
    cudaGetSymbolAddress((void**)&vT, g_vT);
    cudaGetSymbolAddress((void**)&s, g_s);
    cudaGetSymbolAddress((void**)&ctx, g_ctx);
    cudaGetSymbolAddress((void**)&wqT, g_wqT);
    cudaGetSymbolAddress((void**)&wkT, g_wkT);
    cudaGetSymbolAddress((void**)&wvT, g_wvT);
    cudaGetSymbolAddress((void**)&woT, g_woT);
    cudaGetSymbolAddress((void**)&rowpart, g_rowpart);
    cudaGetSymbolAddress((void**)&inv, g_inv);

    cudaFuncSetAttribute(gemm_mma, cudaFuncAttributeMaxDynamicSharedMemorySize, GSMEM);

    const float scaling = 1.0f / 32.0f;   // E^-0.5

    // 0) Wq transpose   1) LN1   2) LN2
    transpose_kernel<<<dim3(EDIM / 32, D1 / 32), 256>>>(Wq, wqT, D1, EDIM);
    layernorm_kernel<4><<<ROWS1, 256>>>(modality1, ln1_g, ln1_b, x1, D1);
    layernorm_kernel<3><<<ROWS2, 256>>>(modality2, ln2_g, ln2_b, x2, D2);

    // 3) Q projection  <-- ncu-profiled launch index
    gemm_mma<<<dim3(EDIM / 128, ROWS1 / 128), 256, GSMEM>>>(
        x1, wqT, bq, q, D1, D1, D1, EDIM, 1.f, 1, 1, 0, 0, 0, 0, 0, nullptr);

    // 4-6) remaining weight transposes
    transpose_kernel<<<dim3(EDIM / 32, D2 / 32), 256>>>(Wk, wkT, D2, EDIM);
    transpose_kernel<<<dim3(EDIM / 32, D2 / 32), 256>>>(Wv, wvT, D2, EDIM);
    transpose_kernel<<<dim3(D1 / 32, EDIM / 32), 256>>>(Wo, woT, EDIM, D1);

    // 7) K projection
    gemm_mma<<<dim3(EDIM / 128, ROWS2 / 128), 256, GSMEM>>>(
        x2, wkT, bk, k, D2, D2, D2, EDIM, 1.f, 1, 1, 0, 0, 0, 0, 0, nullptr);

    // 8) vT[b][e][c] = (Wv^T @ x2^T) + bv (row bias), segmented C pitch 2048
    gemm_mma<<<dim3(ROWS2 / 128, EDIM / 128), 256, GSMEM>>>(
        wvT, x2, bv, vT, D2, D2, D2, L2, 1.f, 1, 2, 0, 0, 0,
        L2, (long long)EDIM * L2, nullptr);

    // 9) P = exp(scaling * Q @ K^T)  (batched; row-sum side-band -> rowpart)
    gemm_mma<<<dim3(L2 / 128, L1 / 128, BATCH), 256, GSMEM>>>(
        q, k, nullptr, s, EDIM, EDIM, EDIM, L2, scaling, 1, 0,
        (long long)L1 * EDIM, (long long)L2 * EDIM, (long long)L1 * L2,
        0, 0, rowpart);

    // 10) inv[r] = 1 / rowsum
    rowsum_reduce<<<ROWS1 / 256, 256>>>(rowpart, inv);

    // 11) ctx = (P @ V) * inv[row]   (row multiplier epilogue, tf32-rounded)
    gemm_mma<<<dim3(EDIM / 128, L1 / 128, BATCH), 256, GSMEM>>>(
        s, vT, inv, ctx, L2, L2, L2, EDIM, 1.f, 1, 3,
        (long long)L1 * L2, (long long)EDIM * L2, (long long)L1 * EDIM, 0, 0, nullptr);

    // 12) out = ctx @ Wo + bo (fp32 output)
    gemm_mma<<<dim3(D1 / 128, ROWS1 / 128), 256, GSMEM>>>(
        ctx, woT, bo, out, EDIM, EDIM, EDIM, D1, 1.f, 0, 1, 0, 0, 0, 0, 0, nullptr);
}

// round 11
// speedup vs baseline: 1.4111x; 1.1079x over previous
#include <cuda_runtime.h>
#include <math.h>
#include <stdint.h>

// ---------------- problem constants ----------------
#define BATCH 8
#define L1 2048
#define L2 2048
#define D1 1024
#define D2 768
#define EDIM 1024
#define ROWS1 (BATCH * L1)          // 16384
#define ROWS2 (BATCH * L2)          // 16384

// ---------------- scratch (device globals; no allocation) ----------------
__device__ float g_x1[ROWS1 * D1];
__device__ float g_x2[ROWS2 * D2];
__device__ float g_q[ROWS1 * EDIM];
__device__ float g_k[ROWS2 * EDIM];
__device__ float g_vT[(size_t)BATCH * EDIM * L2];  // [B][E][L2] pitch 2048
__device__ float g_s[(size_t)BATCH * L1 * L2];     // exp-scores (unnormalized)
__device__ float g_ctx[ROWS1 * EDIM];
__device__ float g_wqT[EDIM * D1];
__device__ float g_wkT[EDIM * D2];
__device__ float g_wvT[EDIM * D2];
__device__ float g_woT[D1 * EDIM];
__device__ float g_rowpart[16 * ROWS1];            // per-CTA-column row partial sums
__device__ float g_inv[ROWS1];                     // 1 / rowsum

// ---------------- helpers ----------------
static __device__ __forceinline__ uint32_t smem_u32(const void* p) {
    uint32_t a;
    asm("{ .reg .u64 t; cvta.to.shared.u64 t, %1; cvt.u32.u64 %0, t; }" : "=r"(a) : "l"(p));
    return a;
}
static __device__ __forceinline__ float f2tf32f(float x) {
    uint32_t y; asm("cvt.rna.tf32.f32 %0, %1;" : "=r"(y) : "f"(x));
    return __uint_as_float(y);
}
static __device__ __forceinline__ void cp_async16(uint32_t saddr, const void* gptr) {
    asm volatile("cp.async.cg.shared.global [%0], [%1], 16;" :: "r"(saddr), "l"(gptr));
}
static __device__ __forceinline__ void cp_commit() {
    asm volatile("cp.async.commit_group;" ::: "memory");
}
template<int N>
static __device__ __forceinline__ void cp_wait() {
    asm volatile("cp.async.wait_group %0;" :: "n"(N) : "memory");
}
static __device__ __forceinline__ void ldsm_x4(uint32_t* r, uint32_t a) {
    asm volatile("ldmatrix.sync.aligned.m8n8.x4.shared.b16 {%0,%1,%2,%3}, [%4];"
                 : "=r"(r[0]), "=r"(r[1]), "=r"(r[2]), "=r"(r[3]) : "r"(a));
}

#define MMA_TF32(d, a, b) \
    asm volatile("mma.sync.aligned.m16n8k8.row.col.f32.tf32.tf32.f32 " \
        "{%0,%1,%2,%3}, {%4,%5,%6,%7}, {%8,%9}, {%0,%1,%2,%3};" \
        : "+f"((d)[0]), "+f"((d)[1]), "+f"((d)[2]), "+f"((d)[3]) \
        : "r"((a)[0]), "r"((a)[1]), "r"((a)[2]), "r"((a)[3]), \
          "r"((b)[0]), "r"((b)[1]))

// ================= tf32 mma.sync GEMM =================
// C[M,N] = scale*(A[M,K] @ B[N,K]^T) + bias;  A,B K-major with pitches ldA/ldB.
// BM=128, BN=128, BK=32. 256 threads = 8 warps (2Mx4N), warp tile 64x32.
// Smem row stride 36 words (mod 32 == 4) -> conflict-free cp.async + ldmatrix.
// 3-stage cp.async, 2 CTAs/SM, one barrier per K-chunk (4 ks-steps each).
// bias_mode: 0 none, 1 col bias, 2 row bias, 3 row MULTIPLIER (bias[z*2048+r]).
// rowpart != null: epilogue stores exp(scale*acc) (tf32-rounded) and writes
//                  per-CTA row sums to rowpart[bx][z*2048 + by*128 + r].
#define STAGES 3
#define SW 36                       // smem row stride (words)
#define AW (128 * SW)               // words per A stage (4608)
#define STW (2 * AW)                // words per stage (9216)
#define GSMEM (STAGES * STW * 4)    // 110592 bytes

__global__ void __launch_bounds__(256, 2)
gemm_mma(const float* __restrict__ A, const float* __restrict__ B,
         const float* __restrict__ bias, float* __restrict__ C,
         int K, int ldA, int ldB, int ldC,
         float scale, int round_out, int bias_mode,
         long long sA, long long sB, long long sC,
         int cSeg, long long cSegStride, float* __restrict__ rowpart) {
    extern __shared__ uint32_t sm[];
    const uint32_t sb = smem_u32(sm);
    const int tid = threadIdx.x;
    const int lane = tid & 31, warp = tid >> 5;
    const int g = lane >> 2, t = lane & 3;
    const int m0 = (warp >> 2) * 64;       // 0 or 64
    const int n0 = (warp & 3) * 32;        // 0,32,64,96

    A += (long long)blockIdx.z * sA + (size_t)blockIdx.y * 128 * ldA;
    B += (long long)blockIdx.z * sB + (size_t)blockIdx.x * 128 * ldB;
    C += (long long)blockIdx.z * sC;

    const int r_ld = tid >> 3;             // base row (0..31), +32 per f
    const int c_ld = (tid & 7) * 4;        // word offset in K (0..28)

    // ldmatrix per-thread source offsets (bytes, within a stage)
    const int lsub = lane >> 3, lr = lane & 7;
    const uint32_t aoff = (uint32_t)(((m0 + ((lsub & 1) << 3) + lr) * SW +
                                      ((lsub >> 1) << 2)) * 4);
    // B pair-x4: matrix index mi = lane>>3 -> {jj-pair row half, k half}
    const uint32_t boff = (uint32_t)(AW * 4 + ((n0 + ((lsub >> 1) << 3) + lr) * SW +
                                      ((lsub & 1) << 2)) * 4);

    float acc[4][4][4];
    #pragma unroll
    for (int i = 0; i < 4; i++)
        #pragma unroll
        for (int j = 0; j < 4; j++)
            #pragma unroll
            for (int e = 0; e < 4; e++) acc[i][j][e] = 0.f;

    const int nch = K >> 5;

    #pragma unroll
    for (int s = 0; s < STAGES - 1; s++) {
        const int k0 = s * 32;
        #pragma unroll
        for (int f = 0; f < 4; f++) {
            int row = r_ld + f * 32;
            cp_async16(sb + (s * STW + row * SW + c_ld) * 4,
                       A + (size_t)row * ldA + k0 + c_ld);
            cp_async16(sb + (s * STW + AW + row * SW + c_ld) * 4,
                       B + (size_t)row * ldB + k0 + c_ld);
        }
        cp_commit();
    }

    for (int i = 0; i < nch; i++) {
        cp_wait<STAGES - 2>();
        __syncthreads();
        {
            const int ic = i + STAGES - 1;
            if (ic < nch) {
                const int st = ic % STAGES;
                const int k0 = ic * 32;
                #pragma unroll
                for (int f = 0; f < 4; f++) {
                    int row = r_ld + f * 32;
                    cp_async16(sb + (st * STW + row * SW + c_ld) * 4,
                               A + (size_t)row * ldA + k0 + c_ld);
                    cp_async16(sb + (st * STW + AW + row * SW + c_ld) * 4,
                               B + (size_t)row * ldB + k0 + c_ld);
                }
            }
            cp_commit();
        }

        const uint32_t stBase = sb + (uint32_t)((i % STAGES) * (STW * 4));
        #pragma unroll
        for (int ks = 0; ks < 4; ks++) {
            uint32_t af[4][4], bf[2][4];
            #pragma unroll
            for (int ii = 0; ii < 4; ii++)
                ldsm_x4(af[ii], stBase + aoff + ii * (16 * SW * 4) + ks * 32);
            #pragma unroll
            for (int p = 0; p < 2; p++)
                ldsm_x4(bf[p], stBase + boff + p * (16 * SW * 4) + ks * 32);
            #pragma unroll
            for (int ii = 0; ii < 4; ii++)
                #pragma unroll
                for (int jj = 0; jj < 4; jj++)
                    MMA_TF32(acc[ii][jj], af[ii], &bf[jj >> 1][(jj & 1) * 2]);
        }
    }

    const int row_base = blockIdx.y * 128 + m0 + g;

    if (rowpart != nullptr) {
        // ---- exp epilogue with row-sum side-band (scores GEMM) ----
        float rsum[8];
        #pragma unroll
        for (int e = 0; e < 8; e++) rsum[e] = 0.f;
        const int col_base = blockIdx.x * 128 + n0 + t * 2;
        #pragma unroll
        for (int ii = 0; ii < 4; ii++) {
            const int r0 = row_base + ii * 16;
            #pragma unroll
            for (int jj = 0; jj < 4; jj++) {
                const int col = col_base + jj * 8;
                float2 v0, v1;
                v0.x = __expf(acc[ii][jj][0] * scale);
                v0.y = __expf(acc[ii][jj][1] * scale);
                v1.x = __expf(acc[ii][jj][2] * scale);
                v1.y = __expf(acc[ii][jj][3] * scale);
                rsum[ii * 2 + 0] += v0.x + v0.y;
                rsum[ii * 2 + 1] += v1.x + v1.y;
                v0.x = f2tf32f(v0.x); v0.y = f2tf32f(v0.y);
                v1.x = f2tf32f(v1.x); v1.y = f2tf32f(v1.y);
                *(float2*)(C + (size_t)r0 * ldC + col) = v0;
                *(float2*)(C + (size_t)(r0 + 8) * ldC + col) = v1;
            }
        }
        #pragma unroll
        for (int e = 0; e < 8; e++) {
            rsum[e] += __shfl_xor_sync(0xffffffffu, rsum[e], 1);
            rsum[e] += __shfl_xor_sync(0xffffffffu, rsum[e], 2);
        }
        __syncthreads();                 // mainloop smem reads done; reuse as row buf
        float* smemRow = (float*)sm;
        if (tid < 128) smemRow[tid] = 0.f;
        __syncthreads();
        if (t == 0) {
            #pragma unroll
            for (int ii = 0; ii < 4; ii++) {
                atomicAdd(&smemRow[m0 + ii * 16 + g], rsum[ii * 2 + 0]);
                atomicAdd(&smemRow[m0 + ii * 16 + 8 + g], rsum[ii * 2 + 1]);
            }
        }
        __syncthreads();
        if (tid < 128) {
            const size_t grow = (size_t)blockIdx.z * L1 + blockIdx.y * 128 + tid;
            rowpart[(size_t)blockIdx.x * ROWS1 + grow] = smemRow[tid];
        }
        return;
    }

    // ---- normal epilogue ----
    int colblk = blockIdx.x * 128;
    if (cSeg > 0) {
        const int seg = colblk / cSeg;
        C += (long long)seg * cSegStride;
        colblk -= seg * cSeg;
    }
    const int col_base = colblk + n0 + t * 2;
    const int bcol_base = blockIdx.x * 128 + n0 + t * 2;
    #pragma unroll
    for (int ii = 0; ii < 4; ii++) {
        const int r0 = row_base + ii * 16;
        float rb0 = 0.f, rb1 = 0.f;
        if (bias_mode == 2) { rb0 = __ldg(bias + r0); rb1 = __ldg(bias + r0 + 8); }
        if (bias_mode == 3) {
            rb0 = __ldg(bias + (size_t)blockIdx.z * L1 + r0);
            rb1 = __ldg(bias + (size_t)blockIdx.z * L1 + r0 + 8);
        }
        #pragma unroll
        for (int jj = 0; jj < 4; jj++) {
            const int col = col_base + jj * 8;
            float2 v0, v1;
            if (bias_mode == 3) {       // row multiplier
                v0.x = acc[ii][jj][0] * rb0;
                v0.y = acc[ii][jj][1] * rb0;
                v1.x = acc[ii][jj][2] * rb1;
                v1.y = acc[ii][jj][3] * rb1;
            } else {
                float bx0, by0, bx1, by1;
                if (bias_mode == 1) {
                    const int bc = bcol_base + jj * 8;
                    float cb0 = __ldg(bias + bc), cb1 = __ldg(bias + bc + 1);
                    bx0 = cb0; by0 = cb1; bx1 = cb0; by1 = cb1;
                } else if (bias_mode == 2) {
                    bx0 = rb0; by0 = rb0; bx1 = rb1; by1 = rb1;
                } else {
                    bx0 = by0 = bx1 = by1 = 0.f;
                }
                v0.x = acc[ii][jj][0] * scale + bx0;
                v0.y = acc[ii][jj][1] * scale + by0;
                v1.x = acc[ii][jj][2] * scale + bx1;
                v1.y = acc[ii][jj][3] * scale + by1;
            }
            if (round_out) {
                v0.x = f2tf32f(v0.x); v0.y = f2tf32f(v0.y);
                v1.x = f2tf32f(v1.x); v1.y = f2tf32f(v1.y);
            }
            *(float2*)(C + (size_t)r0 * ldC + col) = v0;
            *(float2*)(C + (size_t)(r0 + 8) * ldC + col) = v1;
        }
    }
}

// ================= rowsum reduce: inv[r] = 1 / sum_x part[x][r] =================
__global__ __launch_bounds__(256)
void rowsum_reduce(const float* __restrict__ part, float* __restrict__ inv) {
    const int r = blockIdx.x * 256 + threadIdx.x;
    float s = 0.f;
    #pragma unroll
    for (int x = 0; x < 16; x++) s += part[(size_t)x * ROWS1 + r];
    inv[r] = 1.0f / s;
}

// ================= layernorm / transpose =================
static __device__ __forceinline__ float blockReduceSum256(float v) {
    __shared__ float sh[8];
    int lane = threadIdx.x & 31, w = threadIdx.x >> 5;
    #pragma unroll
    for (int o = 16; o > 0; o >>= 1) v += __shfl_xor_sync(0xffffffffu, v, o);
    __syncthreads();
    if (lane == 0) sh[w] = v;
    __syncthreads();
    if (w == 0) {
        v = (lane < 8) ? sh[lane] : 0.f;
        #pragma unroll
        for (int o = 4; o > 0; o >>= 1) v += __shfl_xor_sync(0xffffffffu, v, o);
        if (lane == 0) sh[0] = v;
    }
    __syncthreads();
    return sh[0];
}

template<int NV>
__global__ __launch_bounds__(256)
void layernorm_kernel(const float* __restrict__ x, const float* __restrict__ g,
                      const float* __restrict__ b, float* __restrict__ y, int D) {
    const size_t row = blockIdx.x;
    const float* xr = x + row * (size_t)D;
    float*       yr = y + row * (size_t)D;
    float v[NV];
    float s = 0.f;
    #pragma unroll
    for (int j = 0; j < NV; j++) { v[j] = xr[threadIdx.x + j * 256]; s += v[j]; }
    const float mu = blockReduceSum256(s) * (1.f / (float)D);
    float sq = 0.f;
    #pragma unroll
    for (int j = 0; j < NV; j++) { float d = v[j] - mu; sq += d * d; }
    const float rstd = rsqrtf(blockReduceSum256(sq) * (1.f / (float)D) + 1e-5f);
    #pragma unroll
    for (int j = 0; j < NV; j++) {
        int idx = threadIdx.x + j * 256;
        yr[idx] = f2tf32f((v[j] - mu) * rstd * g[idx] + b[idx]);
    }
}

__global__ __launch_bounds__(256)
void transpose_kernel(const float* __restrict__ in, float* __restrict__ out,
                      int R, int C) {
    __shared__ float tb[32][33];
    const int r0 = blockIdx.y * 32, c0 = blockIdx.x * 32;
    const int tx = threadIdx.x & 31, ty = threadIdx.x >> 5;
    #pragma unroll
    for (int k = 0; k < 32; k += 8)
        tb[ty + k][tx] = in[(size_t)(r0 + ty + k) * C + c0 + tx];
    __syncthreads();
    #pragma unroll
    for (int k = 0; k < 32; k += 8)
        out[(size_t)(c0 + ty + k) * R + r0 + tx] = f2tf32f(tb[tx][ty + k]);
}

// ================= launch =================
// Order arranged so process-launch index 3 (the one ncu profiles) = Q projection GEMM.
extern "C" void kernel_launch(void* const* d_in, const int* in_sizes, int n_in,
                              void* d_out, int out_size) {
    const float* modality1 = (const float*)d_in[0];
    const float* modality2 = (const float*)d_in[1];
    const float* ln1_g = (const float*)d_in[2];
    const float* ln1_b = (const float*)d_in[3];
    const float* ln2_g = (const float*)d_in[4];
    const float* ln2_b = (const float*)d_in[5];
    const float* Wq = (const float*)d_in[6];
    const float* bq = (const float*)d_in[7];
    const float* Wk = (const float*)d_in[8];
    const float* bk = (const float*)d_in[9];
    const float* Wv = (const float*)d_in[10];
    const float* bv = (const float*)d_in[11];
    const float* Wo = (const float*)d_in[12];
    const float* bo = (const float*)d_in[13];
    float* out = (float*)d_out;

    float *x1, *x2, *q, *k, *vT, *s, *ctx, *wqT, *wkT, *wvT, *woT, *rowpart, *inv;
    cudaGetSymbolAddress((void**)&x1, g_x1);
    cudaGetSymbolAddress((void**)&x2, g_x2);
    cudaGetSymbolAddress((void**)&q, g_q);
    cudaGetSymbolAddress((void**)&k, g_k);
    cudaGetSymbolAddress((void**)&vT, g_vT);
    cudaGetSymbolAddress((void**)&s, g_s);
    cudaGetSymbolAddress((void**)&ctx, g_ctx);
    cudaGetSymbolAddress((void**)&wqT, g_wqT);
    cudaGetSymbolAddress((void**)&wkT, g_wkT);
    cudaGetSymbolAddress((void**)&wvT, g_wvT);
    cudaGetSymbolAddress((void**)&woT, g_woT);
    cudaGetSymbolAddress((void**)&rowpart, g_rowpart);
    cudaGetSymbolAddress((void**)&inv, g_inv);

    cudaFuncSetAttribute(gemm_mma, cudaFuncAttributeMaxDynamicSharedMemorySize, GSMEM);

    const float scaling = 1.0f / 32.0f;   // E^-0.5

    // 0) Wq transpose   1) LN1   2) LN2
    transpose_kernel<<<dim3(EDIM / 32, D1 / 32), 256>>>(Wq, wqT, D1, EDIM);
    layernorm_kernel<4><<<ROWS1, 256>>>(modality1, ln1_g, ln1_b, x1, D1);
    layernorm_kernel<3><<<ROWS2, 256>>>(modality2, ln2_g, ln2_b, x2, D2);

    // 3) Q projection  <-- ncu-profiled launch index
    gemm_mma<<<dim3(EDIM / 128, ROWS1 / 128), 256, GSMEM>>>(
        x1, wqT, bq, q, D1, D1, D1, EDIM, 1.f, 1, 1, 0, 0, 0, 0, 0, nullptr);

    // 4-6) remaining weight transposes
    transpose_kernel<<<dim3(EDIM / 32, D2 / 32), 256>>>(Wk, wkT, D2, EDIM);
    transpose_kernel<<<dim3(EDIM / 32, D2 / 32), 256>>>(Wv, wvT, D2, EDIM);
    transpose_kernel<<<dim3(D1 / 32, EDIM / 32), 256>>>(Wo, woT, EDIM, D1);

    // 7) K projection
    gemm_mma<<<dim3(EDIM / 128, ROWS2 / 128), 256, GSMEM>>>(
        x2, wkT, bk, k, D2, D2, D2, EDIM, 1.f, 1, 1, 0, 0, 0, 0, 0, nullptr);

    // 8) vT[b][e][c] = (Wv^T @ x2^T) + bv (row bias), segmented C pitch 2048
    gemm_mma<<<dim3(ROWS2 / 128, EDIM / 128), 256, GSMEM>>>(
        wvT, x2, bv, vT, D2, D2, D2, L2, 1.f, 1, 2, 0, 0, 0,
        L2, (long long)EDIM * L2, nullptr);

    // 9) P = exp(scaling * Q @ K^T)  (batched; row-sum side-band -> rowpart)
    gemm_mma<<<dim3(L2 / 128, L1 / 128, BATCH), 256, GSMEM>>>(
        q, k, nullptr, s, EDIM, EDIM, EDIM, L2, scaling, 1, 0,
        (long long)L1 * EDIM, (long long)L2 * EDIM, (long long)L1 * L2,
        0, 0, rowpart);

    // 10) inv[r] = 1 / rowsum
    rowsum_reduce<<<ROWS1 / 256, 256>>>(rowpart, inv);

    // 11) ctx = (P @ V) * inv[row]   (row multiplier epilogue, tf32-rounded)
    gemm_mma<<<dim3(EDIM / 128, L1 / 128, BATCH), 256, GSMEM>>>(
        s, vT, inv, ctx, L2, L2, L2, EDIM, 1.f, 1, 3,
        (long long)L1 * L2, (long long)EDIM * L2, (long long)L1 * EDIM, 0, 0, nullptr);

    // 12) out = ctx @ Wo + bo (fp32 output)
    gemm_mma<<<dim3(D1 / 128, ROWS1 / 128), 256, GSMEM>>>(
        ctx, woT, bo, out, EDIM, EDIM, EDIM, D1, 1.f, 0, 1, 0, 0, 0, 0, 0, nullptr);
}

// round 12
// speedup vs baseline: 1.4202x; 1.0065x over previous
#include <cuda_runtime.h>
#include <math.h>
#include <stdint.h>

// ---------------- problem constants ----------------
#define BATCH 8
#define L1 2048
#define L2 2048
#define D1 1024
#define D2 768
#define EDIM 1024
#define ROWS1 (BATCH * L1)          // 16384
#define ROWS2 (BATCH * L2)          // 16384

// ---------------- scratch (device globals; no allocation) ----------------
__device__ float g_x1[ROWS1 * D1];
__device__ float g_x2[ROWS2 * D2];
__device__ float g_q[ROWS1 * EDIM];
__device__ float g_k[ROWS2 * EDIM];
__device__ float g_vT[(size_t)BATCH * EDIM * L2];  // [B][E][L2] pitch 2048
__device__ float g_s[(size_t)BATCH * L1 * L2];     // exp-scores (unnormalized)
__device__ float g_ctx[ROWS1 * EDIM];
__device__ float g_wqT[EDIM * D1];
__device__ float g_wkT[EDIM * D2];
__device__ float g_wvT[EDIM * D2];
__device__ float g_woT[D1 * EDIM];
__device__ float g_rowpart[16 * ROWS1];            // per-CTA-column row partial sums
__device__ float g_inv[ROWS1];                     // 1 / rowsum

// ---------------- helpers ----------------
static __device__ __forceinline__ uint32_t smem_u32(const void* p) {
    uint32_t a;
    asm("{ .reg .u64 t; cvta.to.shared.u64 t, %1; cvt.u32.u64 %0, t; }" : "=r"(a) : "l"(p));
    return a;
}
static __device__ __forceinline__ float f2tf32f(float x) {
    uint32_t y; asm("cvt.rna.tf32.f32 %0, %1;" : "=r"(y) : "f"(x));
    return __uint_as_float(y);
}
static __device__ __forceinline__ void cp_async16(uint32_t saddr, const void* gptr) {
    asm volatile("cp.async.cg.shared.global [%0], [%1], 16;" :: "r"(saddr), "l"(gptr));
}
static __device__ __forceinline__ void cp_commit() {
    asm volatile("cp.async.commit_group;" ::: "memory");
}
template<int N>
static __device__ __forceinline__ void cp_wait() {
    asm volatile("cp.async.wait_group %0;" :: "n"(N) : "memory");
}
static __device__ __forceinline__ void ldsm_x4(uint32_t* r, uint32_t a) {
    asm volatile("ldmatrix.sync.aligned.m8n8.x4.shared.b16 {%0,%1,%2,%3}, [%4];"
                 : "=r"(r[0]), "=r"(r[1]), "=r"(r[2]), "=r"(r[3]) : "r"(a));
}

#define MMA_TF32(d, a, b) \
    asm volatile("mma.sync.aligned.m16n8k8.row.col.f32.tf32.tf32.f32 " \
        "{%0,%1,%2,%3}, {%4,%5,%6,%7}, {%8,%9}, {%0,%1,%2,%3};" \
        : "+f"((d)[0]), "+f"((d)[1]), "+f"((d)[2]), "+f"((d)[3]) \
        : "r"((a)[0]), "r"((a)[1]), "r"((a)[2]), "r"((a)[3]), \
          "r"((b)[0]), "r"((b)[1]))

// ================= tf32 mma.sync GEMM =================
// C[M,N] = scale*(A[M,K] @ B[N,K]^T) + bias;  A,B K-major with pitches ldA/ldB.
// BM=128, BN=128, BK=32. 128 threads = 4 warps (2x2), warp tile 64x64.
// Smem row stride 36 words (mod 32 == 4) -> conflict-free cp.async + ldmatrix.
// 2-stage double buffer, 3 CTAs/SM, one barrier per K-chunk (4 ks-steps each).
// bias_mode: 0 none, 1 col bias, 2 row bias, 3 row MULTIPLIER (bias[z*2048+r]).
// rowpart != null: epilogue stores exp(scale*acc) (tf32-rounded) and writes
//                  per-CTA row sums to rowpart[bx][z*2048 + by*128 + r].
#define STAGES 2
#define SW 36                       // smem row stride (words)
#define AW (128 * SW)               // words per A stage (4608)
#define STW (2 * AW)                // words per stage (9216)
#define GSMEM (STAGES * STW * 4)    // 73728 bytes

__global__ void __launch_bounds__(128, 3)
gemm_mma(const float* __restrict__ A, const float* __restrict__ B,
         const float* __restrict__ bias, float* __restrict__ C,
         int K, int ldA, int ldB, int ldC,
         float scale, int round_out, int bias_mode,
         long long sA, long long sB, long long sC,
         int cSeg, long long cSegStride, float* __restrict__ rowpart) {
    extern __shared__ uint32_t sm[];
    const uint32_t sb = smem_u32(sm);
    const int tid = threadIdx.x;
    const int lane = tid & 31, warp = tid >> 5;
    const int g = lane >> 2, t = lane & 3;
    const int m0 = (warp >> 1) * 64;       // 0 or 64
    const int n0 = (warp & 1) * 64;        // 0 or 64

    A += (long long)blockIdx.z * sA + (size_t)blockIdx.y * 128 * ldA;
    B += (long long)blockIdx.z * sB + (size_t)blockIdx.x * 128 * ldB;
    C += (long long)blockIdx.z * sC;

    const int r_ld = tid >> 3;             // base row (0..15), +16 per f
    const int c_ld = (tid & 7) * 4;        // word offset in K (0..28)

    // ldmatrix per-thread source offsets (bytes, within a stage)
    const int lsub = lane >> 3, lr = lane & 7;
    const uint32_t aoff = (uint32_t)(((m0 + ((lsub & 1) << 3) + lr) * SW +
                                      ((lsub >> 1) << 2)) * 4);
    // B pair-x4: {r0,r1} = fragment for rows n..n+7, {r2,r3} = rows n+8..n+15
    const uint32_t boff = (uint32_t)(AW * 4 + ((n0 + ((lsub >> 1) << 3) + lr) * SW +
                                      ((lsub & 1) << 2)) * 4);

    float acc[4][8][4];
    #pragma unroll
    for (int i = 0; i < 4; i++)
        #pragma unroll
        for (int j = 0; j < 8; j++)
            #pragma unroll
            for (int e = 0; e < 4; e++) acc[i][j][e] = 0.f;

    const int nch = K >> 5;

    // prologue: chunk 0 -> stage 0
    #pragma unroll
    for (int f = 0; f < 8; f++) {
        int row = r_ld + f * 16;
        cp_async16(sb + (row * SW + c_ld) * 4, A + (size_t)row * ldA + c_ld);
        cp_async16(sb + (AW + row * SW + c_ld) * 4, B + (size_t)row * ldB + c_ld);
    }
    cp_commit();

    for (int i = 0; i < nch; i++) {
        cp_wait<0>();
        __syncthreads();
        {
            const int ic = i + 1;
            if (ic < nch) {
                const int st = ic & 1;
                const int k0 = ic * 32;
                #pragma unroll
                for (int f = 0; f < 8; f++) {
                    int row = r_ld + f * 16;
                    cp_async16(sb + (st * STW + row * SW + c_ld) * 4,
                               A + (size_t)row * ldA + k0 + c_ld);
                    cp_async16(sb + (st * STW + AW + row * SW + c_ld) * 4,
                               B + (size_t)row * ldB + k0 + c_ld);
                }
            }
            cp_commit();
        }

        const uint32_t stBase = sb + (uint32_t)((i & 1) * (STW * 4));
        #pragma unroll
        for (int ks = 0; ks < 4; ks++) {
            uint32_t af[4][4], bf[4][4];
            #pragma unroll
            for (int ii = 0; ii < 4; ii++)
                ldsm_x4(af[ii], stBase + aoff + ii * (16 * SW * 4) + ks * 32);
            #pragma unroll
            for (int p = 0; p < 4; p++)
                ldsm_x4(bf[p], stBase + boff + p * (16 * SW * 4) + ks * 32);
            #pragma unroll
            for (int ii = 0; ii < 4; ii++)
                #pragma unroll
                for (int jj = 0; jj < 8; jj++)
                    MMA_TF32(acc[ii][jj], af[ii], &bf[jj >> 1][(jj & 1) * 2]);
        }
    }

    const int row_base = blockIdx.y * 128 + m0 + g;

    if (rowpart != nullptr) {
        // ---- exp epilogue with row-sum side-band (scores GEMM) ----
        float rsum[8];
        #pragma unroll
        for (int e = 0; e < 8; e++) rsum[e] = 0.f;
        const int col_base = blockIdx.x * 128 + n0 + t * 2;
        #pragma unroll
        for (int ii = 0; ii < 4; ii++) {
            const int r0 = row_base + ii * 16;
            #pragma unroll
            for (int jj = 0; jj < 8; jj++) {
                const int col = col_base + jj * 8;
                float2 v0, v1;
                v0.x = __expf(acc[ii][jj][0] * scale);
                v0.y = __expf(acc[ii][jj][1] * scale);
                v1.x = __expf(acc[ii][jj][2] * scale);
                v1.y = __expf(acc[ii][jj][3] * scale);
                rsum[ii * 2 + 0] += v0.x + v0.y;
                rsum[ii * 2 + 1] += v1.x + v1.y;
                v0.x = f2tf32f(v0.x); v0.y = f2tf32f(v0.y);
                v1.x = f2tf32f(v1.x); v1.y = f2tf32f(v1.y);
                *(float2*)(C + (size_t)r0 * ldC + col) = v0;
                *(float2*)(C + (size_t)(r0 + 8) * ldC + col) = v1;
            }
        }
        #pragma unroll
        for (int e = 0; e < 8; e++) {
            rsum[e] += __shfl_xor_sync(0xffffffffu, rsum[e], 1);
            rsum[e] += __shfl_xor_sync(0xffffffffu, rsum[e], 2);
        }
        __syncthreads();                 // mainloop smem reads done; reuse as row buf
        float* smemRow = (float*)sm;
        smemRow[tid] = 0.f;
        __syncthreads();
        if (t == 0) {
            #pragma unroll
            for (int ii = 0; ii < 4; ii++) {
                atomicAdd(&smemRow[m0 + ii * 16 + g], rsum[ii * 2 + 0]);
                atomicAdd(&smemRow[m0 + ii * 16 + 8 + g], rsum[ii * 2 + 1]);
            }
        }
        __syncthreads();
        const size_t grow = (size_t)blockIdx.z * L1 + blockIdx.y * 128 + tid;
        rowpart[(size_t)blockIdx.x * ROWS1 + grow] = smemRow[tid];
        return;
    }

    // ---- normal epilogue ----
    int colblk = blockIdx.x * 128;
    if (cSeg > 0) {
        const int seg = colblk / cSeg;
        C += (long long)seg * cSegStride;
        colblk -= seg * cSeg;
    }
    const int col_base = colblk + n0 + t * 2;
    const int bcol_base = blockIdx.x * 128 + n0 + t * 2;
    #pragma unroll
    for (int ii = 0; ii < 4; ii++) {
        const int r0 = row_base + ii * 16;
        float rb0 = 0.f, rb1 = 0.f;
        if (bias_mode == 2) { rb0 = __ldg(bias + r0); rb1 = __ldg(bias + r0 + 8); }
        if (bias_mode == 3) {
            rb0 = __ldg(bias + (size_t)blockIdx.z * L1 + r0);
            rb1 = __ldg(bias + (size_t)blockIdx.z * L1 + r0 + 8);
        }
        #pragma unroll
        for (int jj = 0; jj < 8; jj++) {
            const int col = col_base + jj * 8;
            float2 v0, v1;
            if (bias_mode == 3) {       // row multiplier
                v0.x = acc[ii][jj][0] * rb0;
                v0.y = acc[ii][jj][1] * rb0;
                v1.x = acc[ii][jj][2] * rb1;
                v1.y = acc[ii][jj][3] * rb1;
            } else {
                float bx0, by0, bx1, by1;
                if (bias_mode == 1) {
                    const int bc = bcol_base + jj * 8;
                    float cb0 = __ldg(bias + bc), cb1 = __ldg(bias + bc + 1);
                    bx0 = cb0; by0 = cb1; bx1 = cb0; by1 = cb1;
                } else if (bias_mode == 2) {
                    bx0 = rb0; by0 = rb0; bx1 = rb1; by1 = rb1;
                } else {
                    bx0 = by0 = bx1 = by1 = 0.f;
                }
                v0.x = acc[ii][jj][0] * scale + bx0;
                v0.y = acc[ii][jj][1] * scale + by0;
                v1.x = acc[ii][jj][2] * scale + bx1;
                v1.y = acc[ii][jj][3] * scale + by1;
            }
            if (round_out) {
                v0.x = f2tf32f(v0.x); v0.y = f2tf32f(v0.y);
                v1.x = f2tf32f(v1.x); v1.y = f2tf32f(v1.y);
            }
            *(float2*)(C + (size_t)r0 * ldC + col) = v0;
            *(float2*)(C + (size_t)(r0 + 8) * ldC + col) = v1;
        }
    }
}

// ================= rowsum reduce: inv[r] = 1 / sum_x part[x][r] =================
__global__ __launch_bounds__(256)
void rowsum_reduce(const float* __restrict__ part, float* __restrict__ inv) {
    const int r = blockIdx.x * 256 + threadIdx.x;
    float s = 0.f;
    #pragma unroll
    for (int x = 0; x < 16; x++) s += part[(size_t)x * ROWS1 + r];
    inv[r] = 1.0f / s;
}

// ================= layernorm / transpose =================
static __device__ __forceinline__ float blockReduceSum256(float v) {
    __shared__ float sh[8];
    int lane = threadIdx.x & 31, w = threadIdx.x >> 5;
    #pragma unroll
    for (int o = 16; o > 0; o >>= 1) v += __shfl_xor_sync(0xffffffffu, v, o);
    __syncthreads();
    if (lane == 0) sh[w] = v;
    __syncthreads();
    if (w == 0) {
        v = (lane < 8) ? sh[lane] : 0.f;
        #pragma unroll
        for (int o = 4; o > 0; o >>= 1) v += __shfl_xor_sync(0xffffffffu, v, o);
        if (lane == 0) sh[0] = v;
    }
    __syncthreads();
    return sh[0];
}

template<int NV>
__global__ __launch_bounds__(256)
void layernorm_kernel(const float* __restrict__ x, const float* __restrict__ g,
                      const float* __restrict__ b, float* __restrict__ y, int D) {
    const size_t row = blockIdx.x;
    const float* xr = x + row * (size_t)D;
    float*       yr = y + row * (size_t)D;
    float v[NV];
    float s = 0.f;
    #pragma unroll
    for (int j = 0; j < NV; j++) { v[j] = xr[threadIdx.x + j * 256]; s += v[j]; }
    const float mu = blockReduceSum256(s) * (1.f / (float)D);
    float sq = 0.f;
    #pragma unroll
    for (int j = 0; j < NV; j++) { float d = v[j] - mu; sq += d * d; }
    const float rstd = rsqrtf(blockReduceSum256(sq) * (1.f / (float)D) + 1e-5f);
    #pragma unroll
    for (int j = 0; j < NV; j++) {
        int idx = threadIdx.x + j * 256;
        yr[idx] = f2tf32f((v[j] - mu) * rstd * g[idx] + b[idx]);
    }
}

__global__ __launch_bounds__(256)
void transpose_kernel(const float* __restrict__ in, float* __restrict__ out,
                      int R, int C) {
    __shared__ float tb[32][33];
    const int r0 = blockIdx.y * 32, c0 = blockIdx.x * 32;
    const int tx = threadIdx.x & 31, ty = threadIdx.x >> 5;
    #pragma unroll
    for (int k = 0; k < 32; k += 8)
        tb[ty + k][tx] = in[(size_t)(r0 + ty + k) * C + c0 + tx];
    __syncthreads();
    #pragma unroll
    for (int k = 0; k < 32; k += 8)
        out[(size_t)(c0 + ty + k) * R + r0 + tx] = f2tf32f(tb[tx][ty + k]);
}

// ================= launch =================
// Order arranged so process-launch index 3 (the one ncu profiles) = Q projection GEMM.
extern "C" void kernel_launch(void* const* d_in, const int* in_sizes, int n_in,
                              void* d_out, int out_size) {
    const float* modality1 = (const float*)d_in[0];
    const float* modality2 = (const float*)d_in[1];
    const float* ln1_g = (const float*)d_in[2];
    const float* ln1_b = (const float*)d_in[3];
    const float* ln2_g = (const float*)d_in[4];
    const float* ln2_b = (const float*)d_in[5];
    const float* Wq = (const float*)d_in[6];
    const float* bq = (const float*)d_in[7];
    const float* Wk = (const float*)d_in[8];
    const float* bk = (const float*)d_in[9];
    const float* Wv = (const float*)d_in[10];
    const float* bv = (const float*)d_in[11];
    const float* Wo = (const float*)d_in[12];
    const float* bo = (const float*)d_in[13];
    float* out = (float*)d_out;

    float *x1, *x2, *q, *k, *vT, *s, *ctx, *wqT, *wkT, *wvT, *woT, *rowpart, *inv;
    cudaGetSymbolAddress((void**)&x1, g_x1);
    cudaGetSymbolAddress((void**)&x2, g_x2);
    cudaGetSymbolAddress((void**)&q, g_q);
    cudaGetSymbolAddress((void**)&k, g_k);
    cudaGetSymbolAddress((void**)&vT, g_vT);
    cudaGetSymbolAddress((void**)&s, g_s);
    cudaGetSymbolAddress((void**)&ctx, g_ctx);
    cudaGetSymbolAddress((void**)&wqT, g_wqT);
    cudaGetSymbolAddress((void**)&wkT, g_wkT);
    cudaGetSymbolAddress((void**)&wvT, g_wvT);
    cudaGetSymbolAddress((void**)&woT, g_woT);
    cudaGetSymbolAddress((void**)&rowpart, g_rowpart);
    cudaGetSymbolAddress((void**)&inv, g_inv);

    cudaFuncSetAttribute(gemm_mma, cudaFuncAttributeMaxDynamicSharedMemorySize, GSMEM);

    const float scaling = 1.0f / 32.0f;   // E^-0.5

    // 0) Wq transpose   1) LN1   2) LN2
    transpose_kernel<<<dim3(EDIM / 32, D1 / 32), 256>>>(Wq, wqT, D1, EDIM);
    layernorm_kernel<4><<<ROWS1, 256>>>(modality1, ln1_g, ln1_b, x1, D1);
    layernorm_kernel<3><<<ROWS2, 256>>>(modality2, ln2_g, ln2_b, x2, D2);

    // 3) Q projection  <-- ncu-profiled launch index
    gemm_mma<<<dim3(EDIM / 128, ROWS1 / 128), 128, GSMEM>>>(
        x1, wqT, bq, q, D1, D1, D1, EDIM, 1.f, 1, 1, 0, 0, 0, 0, 0, nullptr);

    // 4-6) remaining weight transposes
    transpose_kernel<<<dim3(EDIM / 32, D2 / 32), 256>>>(Wk, wkT, D2, EDIM);
    transpose_kernel<<<dim3(EDIM / 32, D2 / 32), 256>>>(Wv, wvT, D2, EDIM);
    transpose_kernel<<<dim3(D1 / 32, EDIM / 32), 256>>>(Wo, woT, EDIM, D1);

    // 7) K projection
    gemm_mma<<<dim3(EDIM / 128, ROWS2 / 128), 128, GSMEM>>>(
        x2, wkT, bk, k, D2, D2, D2, EDIM, 1.f, 1, 1, 0, 0, 0, 0, 0, nullptr);

    // 8) vT[b][e][c] = (Wv^T @ x2^T) + bv (row bias), segmented C pitch 2048
    gemm_mma<<<dim3(ROWS2 / 128, EDIM / 128), 128, GSMEM>>>(
        wvT, x2, bv, vT, D2, D2, D2, L2, 1.f, 1, 2, 0, 0, 0,
        L2, (long long)EDIM * L2, nullptr);

    // 9) P = exp(scaling * Q @ K^T)  (batched; row-sum side-band -> rowpart)
    gemm_mma<<<dim3(L2 / 128, L1 / 128, BATCH), 128, GSMEM>>>(
        q, k, nullptr, s, EDIM, EDIM, EDIM, L2, scaling, 1, 0,
        (long long)L1 * EDIM, (long long)L2 * EDIM, (long long)L1 * L2,
        0, 0, rowpart);

    // 10) inv[r] = 1 / rowsum
    rowsum_reduce<<<ROWS1 / 256, 256>>>(rowpart, inv);

    // 11) ctx = (P @ V) * inv[row]   (row multiplier epilogue, tf32-rounded)
    gemm_mma<<<dim3(EDIM / 128, L1 / 128, BATCH), 128, GSMEM>>>(
        s, vT, inv, ctx, L2, L2, L2, EDIM, 1.f, 1, 3,
        (long long)L1 * L2, (long long)EDIM * L2, (long long)L1 * EDIM, 0, 0, nullptr);

    // 12) out = ctx @ Wo + bo (fp32 output)
    gemm_mma<<<dim3(D1 / 128, ROWS1 / 128), 128, GSMEM>>>(
        ctx, woT, bo, out, EDIM, EDIM, EDIM, D1, 1.f, 0, 1, 0, 0, 0, 0, 0, nullptr);
}

// round 13
// speedup vs baseline: 1.4695x; 1.0347x over previous
#include <cuda_runtime.h>
#include <math.h>
#include <stdint.h>

// ---------------- problem constants ----------------
#define BATCH 8
#define L1 2048
#define L2 2048
#define D1 1024
#define D2 768
#define EDIM 1024
#define ROWS1 (BATCH * L1)          // 16384
#define ROWS2 (BATCH * L2)          // 16384

// ---------------- scratch (device globals; no allocation) ----------------
__device__ float g_x1[ROWS1 * D1];
__device__ float g_x2[ROWS2 * D2];
__device__ float g_q[ROWS1 * EDIM];
__device__ float g_k[ROWS2 * EDIM];
__device__ float g_vT[(size_t)BATCH * EDIM * L2];  // [B][E][L2] pitch 2048
__device__ float g_s[(size_t)BATCH * L1 * L2];     // exp-scores (unnormalized)
__device__ float g_ctx[ROWS1 * EDIM];
__device__ float g_wqT[EDIM * D1];
__device__ float g_wkT[EDIM * D2];
__device__ float g_wvT[EDIM * D2];
__device__ float g_woT[D1 * EDIM];
__device__ float g_rowpart[16 * ROWS1];            // per-CTA-column row partial sums
__device__ float g_inv[ROWS1];                     // 1 / rowsum

// ---------------- helpers ----------------
static __device__ __forceinline__ uint32_t smem_u32(const void* p) {
    uint32_t a;
    asm("{ .reg .u64 t; cvta.to.shared.u64 t, %1; cvt.u32.u64 %0, t; }" : "=r"(a) : "l"(p));
    return a;
}
static __device__ __forceinline__ float f2tf32f(float x) {
    uint32_t y; asm("cvt.rna.tf32.f32 %0, %1;" : "=r"(y) : "f"(x));
    return __uint_as_float(y);
}
static __device__ __forceinline__ void cp_async16(uint32_t saddr, const void* gptr) {
    asm volatile("cp.async.cg.shared.global [%0], [%1], 16;" :: "r"(saddr), "l"(gptr));
}
static __device__ __forceinline__ void cp_commit() {
    asm volatile("cp.async.commit_group;" ::: "memory");
}
template<int N>
static __device__ __forceinline__ void cp_wait() {
    asm volatile("cp.async.wait_group %0;" :: "n"(N) : "memory");
}
static __device__ __forceinline__ void ldsm_x4(uint32_t* r, uint32_t a) {
    asm volatile("ldmatrix.sync.aligned.m8n8.x4.shared.b16 {%0,%1,%2,%3}, [%4];"
                 : "=r"(r[0]), "=r"(r[1]), "=r"(r[2]), "=r"(r[3]) : "r"(a));
}

#define MMA_TF32(d, a, b) \
    asm volatile("mma.sync.aligned.m16n8k8.row.col.f32.tf32.tf32.f32 " \
        "{%0,%1,%2,%3}, {%4,%5,%6,%7}, {%8,%9}, {%0,%1,%2,%3};" \
        : "+f"((d)[0]), "+f"((d)[1]), "+f"((d)[2]), "+f"((d)[3]) \
        : "r"((a)[0]), "r"((a)[1]), "r"((a)[2]), "r"((a)[3]), \
          "r"((b)[0]), "r"((b)[1]))

// ================= tf32 mma.sync GEMM body =================
// C[M,N] = scale*(A[M,K] @ B[N,K]^T) + bias;  A,B K-major with pitches ldA/ldB.
// BM=128, BN=128, BK=32. 128 threads = 4 warps (2x2), warp tile 64x64.
// Smem row stride 36 words (mod 32 == 4) -> conflict-free cp.async + ldmatrix.
// 2-stage double buffer, 3 CTAs/SM, one barrier per K-chunk (4 ks-steps each).
// bias_mode: 0 none, 1 col bias, 2 row bias, 3 row MULTIPLIER (bias[bz*2048+r]).
// rowpart != null: epilogue stores exp(scale*acc) (tf32-rounded) and writes
//                  per-CTA row sums to rowpart[bx][bz*2048 + by*128 + r].
#define STAGES 2
#define SW 36                       // smem row stride (words)
#define AW (128 * SW)               // words per A stage (4608)
#define STW (2 * AW)                // words per stage (9216)
#define GSMEM (STAGES * STW * 4)    // 73728 bytes

static __device__ __forceinline__ void gemm_body(
    const float* __restrict__ A, const float* __restrict__ B,
    const float* __restrict__ bias, float* __restrict__ C,
    int K, int ldA, int ldB, int ldC,
    float scale, int round_out, int bias_mode,
    int bx, int by, int bz,
    int cSeg, long long cSegStride, float* __restrict__ rowpart,
    uint32_t* sm) {
    const uint32_t sb = smem_u32(sm);
    const int tid = threadIdx.x;
    const int lane = tid & 31, warp = tid >> 5;
    const int g = lane >> 2, t = lane & 3;
    const int m0 = (warp >> 1) * 64;       // 0 or 64
    const int n0 = (warp & 1) * 64;        // 0 or 64

    A += (size_t)by * 128 * ldA;
    B += (size_t)bx * 128 * ldB;

    const int r_ld = tid >> 3;             // base row (0..15), +16 per f
    const int c_ld = (tid & 7) * 4;        // word offset in K (0..28)

    const int lsub = lane >> 3, lr = lane & 7;
    const uint32_t aoff = (uint32_t)(((m0 + ((lsub & 1) << 3) + lr) * SW +
                                      ((lsub >> 1) << 2)) * 4);
    const uint32_t boff = (uint32_t)(AW * 4 + ((n0 + ((lsub >> 1) << 3) + lr) * SW +
                                      ((lsub & 1) << 2)) * 4);

    float acc[4][8][4];
    #pragma unroll
    for (int i = 0; i < 4; i++)
        #pragma unroll
        for (int j = 0; j < 8; j++)
            #pragma unroll
            for (int e = 0; e < 4; e++) acc[i][j][e] = 0.f;

    const int nch = K >> 5;

    // prologue: chunk 0 -> stage 0
    #pragma unroll
    for (int f = 0; f < 8; f++) {
        int row = r_ld + f * 16;
        cp_async16(sb + (row * SW + c_ld) * 4, A + (size_t)row * ldA + c_ld);
        cp_async16(sb + (AW + row * SW + c_ld) * 4, B + (size_t)row * ldB + c_ld);
    }
    cp_commit();

    for (int i = 0; i < nch; i++) {
        cp_wait<0>();
        __syncthreads();
        {
            const int ic = i + 1;
            if (ic < nch) {
                const int st = ic & 1;
                const int k0 = ic * 32;
                #pragma unroll
                for (int f = 0; f < 8; f++) {
                    int row = r_ld + f * 16;
                    cp_async16(sb + (st * STW + row * SW + c_ld) * 4,
                               A + (size_t)row * ldA + k0 + c_ld);
                    cp_async16(sb + (st * STW + AW + row * SW + c_ld) * 4,
                               B + (size_t)row * ldB + k0 + c_ld);
                }
            }
            cp_commit();
        }

        const uint32_t stBase = sb + (uint32_t)((i & 1) * (STW * 4));
        #pragma unroll
        for (int ks = 0; ks < 4; ks++) {
            uint32_t af[4][4], bf[4][4];
            #pragma unroll
            for (int ii = 0; ii < 4; ii++)
                ldsm_x4(af[ii], stBase + aoff + ii * (16 * SW * 4) + ks * 32);
            #pragma unroll
            for (int p = 0; p < 4; p++)
                ldsm_x4(bf[p], stBase + boff + p * (16 * SW * 4) + ks * 32);
            #pragma unroll
            for (int ii = 0; ii < 4; ii++)
                #pragma unroll
                for (int jj = 0; jj < 8; jj++)
                    MMA_TF32(acc[ii][jj], af[ii], &bf[jj >> 1][(jj & 1) * 2]);
        }
    }

    const int row_base = by * 128 + m0 + g;

    if (rowpart != nullptr) {
        // ---- exp epilogue with row-sum side-band (scores GEMM) ----
        float rsum[8];
        #pragma unroll
        for (int e = 0; e < 8; e++) rsum[e] = 0.f;
        const int col_base = bx * 128 + n0 + t * 2;
        #pragma unroll
        for (int ii = 0; ii < 4; ii++) {
            const int r0 = row_base + ii * 16;
            #pragma unroll
            for (int jj = 0; jj < 8; jj++) {
                const int col = col_base + jj * 8;
                float2 v0, v1;
                v0.x = __expf(acc[ii][jj][0] * scale);
                v0.y = __expf(acc[ii][jj][1] * scale);
                v1.x = __expf(acc[ii][jj][2] * scale);
                v1.y = __expf(acc[ii][jj][3] * scale);
                rsum[ii * 2 + 0] += v0.x + v0.y;
                rsum[ii * 2 + 1] += v1.x + v1.y;
                v0.x = f2tf32f(v0.x); v0.y = f2tf32f(v0.y);
                v1.x = f2tf32f(v1.x); v1.y = f2tf32f(v1.y);
                *(float2*)(C + (size_t)r0 * ldC + col) = v0;
                *(float2*)(C + (size_t)(r0 + 8) * ldC + col) = v1;
            }
        }
        #pragma unroll
        for (int e = 0; e < 8; e++) {
            rsum[e] += __shfl_xor_sync(0xffffffffu, rsum[e], 1);
            rsum[e] += __shfl_xor_sync(0xffffffffu, rsum[e], 2);
        }
        __syncthreads();
        float* smemRow = (float*)sm;
        smemRow[tid] = 0.f;
        __syncthreads();
        if (t == 0) {
            #pragma unroll
            for (int ii = 0; ii < 4; ii++) {
                atomicAdd(&smemRow[m0 + ii * 16 + g], rsum[ii * 2 + 0]);
                atomicAdd(&smemRow[m0 + ii * 16 + 8 + g], rsum[ii * 2 + 1]);
            }
        }
        __syncthreads();
        const size_t grow = (size_t)bz * L1 + by * 128 + tid;
        rowpart[(size_t)bx * ROWS1 + grow] = smemRow[tid];
        return;
    }

    // ---- normal epilogue ----
    int colblk = bx * 128;
    if (cSeg > 0) {
        const int seg = colblk / cSeg;
        C += (long long)seg * cSegStride;
        colblk -= seg * cSeg;
    }
    const int col_base = colblk + n0 + t * 2;
    const int bcol_base = bx * 128 + n0 + t * 2;
    #pragma unroll
    for (int ii = 0; ii < 4; ii++) {
        const int r0 = row_base + ii * 16;
        float rb0 = 0.f, rb1 = 0.f;
        if (bias_mode == 2) { rb0 = __ldg(bias + r0); rb1 = __ldg(bias + r0 + 8); }
        if (bias_mode == 3) {
            rb0 = __ldg(bias + (size_t)bz * L1 + r0);
            rb1 = __ldg(bias + (size_t)bz * L1 + r0 + 8);
        }
        #pragma unroll
        for (int jj = 0; jj < 8; jj++) {
            const int col = col_base + jj * 8;
            float2 v0, v1;
            if (bias_mode == 3) {       // row multiplier
                v0.x = acc[ii][jj][0] * rb0;
                v0.y = acc[ii][jj][1] * rb0;
                v1.x = acc[ii][jj][2] * rb1;
                v1.y = acc[ii][jj][3] * rb1;
            } else {
                float bx0, by0, bx1, by1;
                if (bias_mode == 1) {
                    const int bc = bcol_base + jj * 8;
                    float cb0 = __ldg(bias + bc), cb1 = __ldg(bias + bc + 1);
                    bx0 = cb0; by0 = cb1; bx1 = cb0; by1 = cb1;
                } else if (bias_mode == 2) {
                    bx0 = rb0; by0 = rb0; bx1 = rb1; by1 = rb1;
                } else {
                    bx0 = by0 = bx1 = by1 = 0.f;
                }
                v0.x = acc[ii][jj][0] * scale + bx0;
                v0.y = acc[ii][jj][1] * scale + by0;
                v1.x = acc[ii][jj][2] * scale + bx1;
                v1.y = acc[ii][jj][3] * scale + by1;
            }
            if (round_out) {
                v0.x = f2tf32f(v0.x); v0.y = f2tf32f(v0.y);
                v1.x = f2tf32f(v1.x); v1.y = f2tf32f(v1.y);
            }
            *(float2*)(C + (size_t)r0 * ldC + col) = v0;
            *(float2*)(C + (size_t)(r0 + 8) * ldC + col) = v1;
        }
    }
}

// ---- standalone GEMM (batched via blockIdx.z strides) ----
__global__ void __launch_bounds__(128, 3)
gemm_mma(const float* __restrict__ A, const float* __restrict__ B,
         const float* __restrict__ bias, float* __restrict__ C,
         int K, int ldA, int ldB, int ldC,
         float scale, int round_out, int bias_mode,
         long long sA, long long sB, long long sC,
         int cSeg, long long cSegStride, float* __restrict__ rowpart) {
    extern __shared__ uint32_t sm[];
    gemm_body(A + (long long)blockIdx.z * sA, B + (long long)blockIdx.z * sB,
              bias, C + (long long)blockIdx.z * sC,
              K, ldA, ldB, ldC, scale, round_out, bias_mode,
              blockIdx.x, blockIdx.y, blockIdx.z, cSeg, cSegStride, rowpart, sm);
}

// ---- fused {Q-proj, K-proj, vT} : 3072 CTAs, one tail wave ----
__global__ void __launch_bounds__(128, 3)
gemm_fused3(const float* __restrict__ x1, const float* __restrict__ wqT,
            const float* __restrict__ bq, float* __restrict__ q,
            const float* __restrict__ x2, const float* __restrict__ wkT,
            const float* __restrict__ bk, float* __restrict__ kk,
            const float* __restrict__ wvT, const float* __restrict__ bv,
            float* __restrict__ vT) {
    extern __shared__ uint32_t sm[];
    const int id = blockIdx.x >> 10;
    const int local = blockIdx.x & 1023;
    if (id == 0) {
        // q[16384,1024] = x1 @ wqT^T + bq ; grid 8 x 128
        gemm_body(x1, wqT, bq, q, D1, D1, D1, EDIM, 1.f, 1, 1,
                  local & 7, local >> 3, 0, 0, 0, nullptr, sm);
    } else if (id == 1) {
        // k[16384,1024] = x2 @ wkT^T + bk ; grid 8 x 128
        gemm_body(x2, wkT, bk, kk, D2, D2, D2, EDIM, 1.f, 1, 1,
                  local & 7, local >> 3, 0, 0, 0, nullptr, sm);
    } else {
        // vT[b][e][c] = (wvT @ x2^T) + bv (row bias); grid 128 x 8, segmented C
        gemm_body(wvT, x2, bv, vT, D2, D2, D2, L2, 1.f, 1, 2,
                  local & 127, local >> 7, 0, L2, (long long)EDIM * L2, nullptr, sm);
    }
}

// ================= rowsum reduce: inv[r] = 1 / sum_x part[x][r] =================
__global__ __launch_bounds__(256)
void rowsum_reduce(const float* __restrict__ part, float* __restrict__ inv) {
    const int r = blockIdx.x * 256 + threadIdx.x;
    float s = 0.f;
    #pragma unroll
    for (int x = 0; x < 16; x++) s += part[(size_t)x * ROWS1 + r];
    inv[r] = 1.0f / s;
}

// ================= layernorm / transpose =================
static __device__ __forceinline__ float blockReduceSum256(float v) {
    __shared__ float sh[8];
    int lane = threadIdx.x & 31, w = threadIdx.x >> 5;
    #pragma unroll
    for (int o = 16; o > 0; o >>= 1) v += __shfl_xor_sync(0xffffffffu, v, o);
    __syncthreads();
    if (lane == 0) sh[w] = v;
    __syncthreads();
    if (w == 0) {
        v = (lane < 8) ? sh[lane] : 0.f;
        #pragma unroll
        for (int o = 4; o > 0; o >>= 1) v += __shfl_xor_sync(0xffffffffu, v, o);
        if (lane == 0) sh[0] = v;
    }
    __syncthreads();
    return sh[0];
}

template<int NV>
__global__ __launch_bounds__(256)
void layernorm_kernel(const float* __restrict__ x, const float* __restrict__ g,
                      const float* __restrict__ b, float* __restrict__ y, int D) {
    const size_t row = blockIdx.x;
    const float* xr = x + row * (size_t)D;
    float*       yr = y + row * (size_t)D;
    float v[NV];
    float s = 0.f;
    #pragma unroll
    for (int j = 0; j < NV; j++) { v[j] = xr[threadIdx.x + j * 256]; s += v[j]; }
    const float mu = blockReduceSum256(s) * (1.f / (float)D);
    float sq = 0.f;
    #pragma unroll
    for (int j = 0; j < NV; j++) { float d = v[j] - mu; sq += d * d; }
    const float rstd = rsqrtf(blockReduceSum256(sq) * (1.f / (float)D) + 1e-5f);
    #pragma unroll
    for (int j = 0; j < NV; j++) {
        int idx = threadIdx.x + j * 256;
        yr[idx] = f2tf32f((v[j] - mu) * rstd * g[idx] + b[idx]);
    }
}

static __device__ __forceinline__ void transpose_body(
    const float* __restrict__ in, float* __restrict__ out,
    int R, int C, int bx, int by) {
    __shared__ float tb[32][33];
    const int r0 = by * 32, c0 = bx * 32;
    const int tx = threadIdx.x & 31, ty = threadIdx.x >> 5;
    #pragma unroll
    for (int k = 0; k < 32; k += 8)
        tb[ty + k][tx] = in[(size_t)(r0 + ty + k) * C + c0 + tx];
    __syncthreads();
    #pragma unroll
    for (int k = 0; k < 32; k += 8)
        out[(size_t)(c0 + ty + k) * R + r0 + tx] = f2tf32f(tb[tx][ty + k]);
}

// all 4 weight transposes in one launch (3584 blocks)
__global__ __launch_bounds__(256)
void transpose4(const float* __restrict__ Wq, float* __restrict__ wqT,
                const float* __restrict__ Wk, float* __restrict__ wkT,
                const float* __restrict__ Wv, float* __restrict__ wvT,
                const float* __restrict__ Wo, float* __restrict__ woT) {
    int b = blockIdx.x;
    if (b < 1024) {
        transpose_body(Wq, wqT, D1, EDIM, b & 31, b >> 5);          // 32 x 32
    } else if (b < 1792) {
        b -= 1024;
        transpose_body(Wk, wkT, D2, EDIM, b & 31, b >> 5);          // 32 x 24
    } else if (b < 2560) {
        b -= 1792;
        transpose_body(Wv, wvT, D2, EDIM, b & 31, b >> 5);          // 32 x 24
    } else {
        b -= 2560;
        transpose_body(Wo, woT, EDIM, D1, b & 31, b >> 5);          // 32 x 32
    }
}

// ================= launch =================
// Order: launch index 3 (ncu-profiled) = fused projection GEMM.
extern "C" void kernel_launch(void* const* d_in, const int* in_sizes, int n_in,
                              void* d_out, int out_size) {
    const float* modality1 = (const float*)d_in[0];
    const float* modality2 = (const float*)d_in[1];
    const float* ln1_g = (const float*)d_in[2];
    const float* ln1_b = (const float*)d_in[3];
    const float* ln2_g = (const float*)d_in[4];
    const float* ln2_b = (const float*)d_in[5];
    const float* Wq = (const float*)d_in[6];
    const float* bq = (const float*)d_in[7];
    const float* Wk = (const float*)d_in[8];
    const float* bk = (const float*)d_in[9];
    const float* Wv = (const float*)d_in[10];
    const float* bv = (const float*)d_in[11];
    const float* Wo = (const float*)d_in[12];
    const float* bo = (const float*)d_in[13];
    float* out = (float*)d_out;

    float *x1, *x2, *q, *k, *vT, *s, *ctx, *wqT, *wkT, *wvT, *woT, *rowpart, *inv;
    cudaGetSymbolAddress((void**)&x1, g_x1);
    cudaGetSymbolAddress((void**)&x2, g_x2);
    cudaGetSymbolAddress((void**)&q, g_q);
    cudaGetSymbolAddress((void**)&k, g_k);
    cudaGetSymbolAddress((void**)&vT, g_vT);
    cudaGetSymbolAddress((void**)&s, g_s);
    cudaGetSymbolAddress((void**)&ctx, g_ctx);
    cudaGetSymbolAddress((void**)&wqT, g_wqT);
    cudaGetSymbolAddress((void**)&wkT, g_wkT);
    cudaGetSymbolAddress((void**)&wvT, g_wvT);
    cudaGetSymbolAddress((void**)&woT, g_woT);
    cudaGetSymbolAddress((void**)&rowpart, g_rowpart);
    cudaGetSymbolAddress((void**)&inv, g_inv);

    cudaFuncSetAttribute(gemm_mma, cudaFuncAttributeMaxDynamicSharedMemorySize, GSMEM);
    cudaFuncSetAttribute(gemm_fused3, cudaFuncAttributeMaxDynamicSharedMemorySize, GSMEM);

    const float scaling = 1.0f / 32.0f;   // E^-0.5

    // 0) all weight transposes   1) LN1   2) LN2
    transpose4<<<3584, 256>>>(Wq, wqT, Wk, wkT, Wv, wvT, Wo, woT);
    layernorm_kernel<4><<<ROWS1, 256>>>(modality1, ln1_g, ln1_b, x1, D1);
    layernorm_kernel<3><<<ROWS2, 256>>>(modality2, ln2_g, ln2_b, x2, D2);

    // 3) fused {Q-proj, K-proj, vT}  <-- ncu-profiled launch index
    gemm_fused3<<<3072, 128, GSMEM>>>(x1, wqT, bq, q,
                                      x2, wkT, bk, k,
                                      wvT, bv, vT);

    // 4) P = exp(scaling * Q @ K^T)  (batched; row-sum side-band -> rowpart)
    gemm_mma<<<dim3(L2 / 128, L1 / 128, BATCH), 128, GSMEM>>>(
        q, k, nullptr, s, EDIM, EDIM, EDIM, L2, scaling, 1, 0,
        (long long)L1 * EDIM, (long long)L2 * EDIM, (long long)L1 * L2,
        0, 0, rowpart);

    // 5) inv[r] = 1 / rowsum
    rowsum_reduce<<<ROWS1 / 256, 256>>>(rowpart, inv);

    // 6) ctx = (P @ V) * inv[row]   (row multiplier epilogue, tf32-rounded)
    gemm_mma<<<dim3(EDIM / 128, L1 / 128, BATCH), 128, GSMEM>>>(
        s, vT, inv, ctx, L2, L2, L2, EDIM, 1.f, 1, 3,
        (long long)L1 * L2, (long long)EDIM * L2, (long long)L1 * EDIM, 0, 0, nullptr);

    // 7) out = ctx @ Wo + bo (fp32 output)
    gemm_mma<<<dim3(D1 / 128, ROWS1 / 128), 128, GSMEM>>>(
        ctx, woT, bo, out, EDIM, EDIM, EDIM, D1, 1.f, 0, 1, 0, 0, 0, 0, 0, nullptr);
}

// round 14
// speedup vs baseline: 2.6829x; 1.8258x over previous
#include <cuda_runtime.h>
#include <cuda_fp16.h>
#include <math.h>
#include <stdint.h>

// ---------------- problem constants ----------------
#define BATCH 8
#define L1 2048
#define L2 2048
#define D1 1024
#define D2 768
#define EDIM 1024
#define ROWS1 (BATCH * L1)          // 16384
#define ROWS2 (BATCH * L2)          // 16384

// ---------------- scratch (device globals; no allocation) ----------------
__device__ __half g_x1[ROWS1 * D1];
__device__ __half g_x2[ROWS2 * D2];
__device__ __half g_q[ROWS1 * EDIM];
__device__ __half g_k[ROWS2 * EDIM];
__device__ __half g_vT[(size_t)BATCH * EDIM * L2];  // [B][E][L2] pitch 2048
__device__ __half g_s[(size_t)BATCH * L1 * L2];     // exp-scores (unnormalized)
__device__ __half g_ctx[ROWS1 * EDIM];
__device__ __half g_wqT[EDIM * D1];
__device__ __half g_wkT[EDIM * D2];
__device__ __half g_wvT[EDIM * D2];
__device__ __half g_woT[D1 * EDIM];
__device__ float g_rowpart[16 * ROWS1];            // per-CTA-column row partial sums
__device__ float g_inv[ROWS1];                     // 1 / rowsum

// ---------------- helpers ----------------
static __device__ __forceinline__ uint32_t smem_u32(const void* p) {
    uint32_t a;
    asm("{ .reg .u64 t; cvta.to.shared.u64 t, %1; cvt.u32.u64 %0, t; }" : "=r"(a) : "l"(p));
    return a;
}
static __device__ __forceinline__ void cp_async16(uint32_t saddr, const void* gptr) {
    asm volatile("cp.async.cg.shared.global [%0], [%1], 16;" :: "r"(saddr), "l"(gptr));
}
static __device__ __forceinline__ void cp_commit() {
    asm volatile("cp.async.commit_group;" ::: "memory");
}
template<int N>
static __device__ __forceinline__ void cp_wait() {
    asm volatile("cp.async.wait_group %0;" :: "n"(N) : "memory");
}
static __device__ __forceinline__ void ldsm_x4(uint32_t* r, uint32_t a) {
    asm volatile("ldmatrix.sync.aligned.m8n8.x4.shared.b16 {%0,%1,%2,%3}, [%4];"
                 : "=r"(r[0]), "=r"(r[1]), "=r"(r[2]), "=r"(r[3]) : "r"(a));
}

#define MMA_F16(d, a, b) \
    asm volatile("mma.sync.aligned.m16n8k16.row.col.f32.f16.f16.f32 " \
        "{%0,%1,%2,%3}, {%4,%5,%6,%7}, {%8,%9}, {%0,%1,%2,%3};" \
        : "+f"((d)[0]), "+f"((d)[1]), "+f"((d)[2]), "+f"((d)[3]) \
        : "r"((a)[0]), "r"((a)[1]), "r"((a)[2]), "r"((a)[3]), \
          "r"((b)[0]), "r"((b)[1]))

// ================= fp16 mma.sync GEMM body =================
// C[M,N] = scale*(A[M,K] @ B[N,K]^T) + bias;  A,B fp16 K-major, pitches in halves.
// BM=128, BN=128, BK=64 halves. 128 threads = 4 warps (2x2), warp tile 64x64.
// Smem rows: 64 halves padded to 144 bytes -> conflict-free cp.async + ldmatrix.
// 2-stage double buffer, 3 CTAs/SM, one barrier per K-chunk (4 k16-steps each).
// bias_mode: 0 none, 1 col bias, 2 row bias, 3 row MULTIPLIER (bias[bz*2048+r]).
// round_out: 1 -> C is __half, 0 -> C is float.
// rowpart != null: epilogue stores exp(scale*acc) as fp16 and per-CTA row sums.
#define ROWB 144                      // bytes per smem row
#define ASTG (128 * ROWB)             // bytes per A stage (18432)
#define STGB (2 * ASTG)               // bytes per stage (36864)
#define GSMEM (2 * STGB)              // 73728 bytes

static __device__ __forceinline__ void gemm_body(
    const __half* __restrict__ A, const __half* __restrict__ B,
    const float* __restrict__ bias, void* __restrict__ Cv,
    int K, int ldA, int ldB, int ldC,
    float scale, int round_out, int bias_mode,
    int bx, int by, int bz,
    int cSeg, long long cSegStride, float* __restrict__ rowpart,
    uint32_t* sm) {
    const uint32_t sb = smem_u32(sm);
    const int tid = threadIdx.x;
    const int lane = tid & 31, warp = tid >> 5;
    const int g = lane >> 2, t = lane & 3;
    const int m0 = (warp >> 1) * 64;       // 0 or 64
    const int n0 = (warp & 1) * 64;        // 0 or 64

    A += (size_t)by * 128 * ldA;
    B += (size_t)bx * 128 * ldB;

    const int r_ld = tid >> 3;             // base row (0..15), +16 per f
    const int c16 = tid & 7;               // 16B chunk in K (0..7)

    const int lsub = lane >> 3, lr = lane & 7;
    const uint32_t aoff = (uint32_t)((m0 + ((lsub & 1) << 3) + lr) * ROWB +
                                     ((lsub >> 1) << 4));
    const uint32_t boff = (uint32_t)(ASTG + (n0 + ((lsub >> 1) << 3) + lr) * ROWB +
                                     ((lsub & 1) << 4));

    float acc[4][8][4];
    #pragma unroll
    for (int i = 0; i < 4; i++)
        #pragma unroll
        for (int j = 0; j < 8; j++)
            #pragma unroll
            for (int e = 0; e < 4; e++) acc[i][j][e] = 0.f;

    const int nch = K >> 6;

    // prologue: chunk 0 -> stage 0
    #pragma unroll
    for (int f = 0; f < 8; f++) {
        int row = r_ld + f * 16;
        cp_async16(sb + row * ROWB + c16 * 16, A + (size_t)row * ldA + c16 * 8);
        cp_async16(sb + ASTG + row * ROWB + c16 * 16, B + (size_t)row * ldB + c16 * 8);
    }
    cp_commit();

    for (int i = 0; i < nch; i++) {
        cp_wait<0>();
        __syncthreads();
        {
            const int ic = i + 1;
            if (ic < nch) {
                const uint32_t stb = sb + (uint32_t)((ic & 1) * STGB);
                const int k0 = ic * 64;
                #pragma unroll
                for (int f = 0; f < 8; f++) {
                    int row = r_ld + f * 16;
                    cp_async16(stb + row * ROWB + c16 * 16,
                               A + (size_t)row * ldA + k0 + c16 * 8);
                    cp_async16(stb + ASTG + row * ROWB + c16 * 16,
                               B + (size_t)row * ldB + k0 + c16 * 8);
                }
            }
            cp_commit();
        }

        const uint32_t stBase = sb + (uint32_t)((i & 1) * STGB);
        #pragma unroll
        for (int ks = 0; ks < 4; ks++) {
            uint32_t af[4][4], bf[4][4];
            #pragma unroll
            for (int ii = 0; ii < 4; ii++)
                ldsm_x4(af[ii], stBase + aoff + ii * (16 * ROWB) + ks * 32);
            #pragma unroll
            for (int p = 0; p < 4; p++)
                ldsm_x4(bf[p], stBase + boff + p * (16 * ROWB) + ks * 32);
            #pragma unroll
            for (int ii = 0; ii < 4; ii++)
                #pragma unroll
                for (int jj = 0; jj < 8; jj++)
                    MMA_F16(acc[ii][jj], af[ii], &bf[jj >> 1][(jj & 1) * 2]);
        }
    }

    const int row_base = by * 128 + m0 + g;

    if (rowpart != nullptr) {
        // ---- exp epilogue with row-sum side-band (scores GEMM), fp16 out ----
        __half* C = (__half*)Cv;
        float rsum[8];
        #pragma unroll
        for (int e = 0; e < 8; e++) rsum[e] = 0.f;
        const int col_base = bx * 128 + n0 + t * 2;
        #pragma unroll
        for (int ii = 0; ii < 4; ii++) {
            const int r0 = row_base + ii * 16;
            #pragma unroll
            for (int jj = 0; jj < 8; jj++) {
                const int col = col_base + jj * 8;
                float e0 = __expf(acc[ii][jj][0] * scale);
                float e1 = __expf(acc[ii][jj][1] * scale);
                float e2 = __expf(acc[ii][jj][2] * scale);
                float e3 = __expf(acc[ii][jj][3] * scale);
                rsum[ii * 2 + 0] += e0 + e1;
                rsum[ii * 2 + 1] += e2 + e3;
                *(__half2*)(C + (size_t)r0 * ldC + col) = __floats2half2_rn(e0, e1);
                *(__half2*)(C + (size_t)(r0 + 8) * ldC + col) = __floats2half2_rn(e2, e3);
            }
        }
        #pragma unroll
        for (int e = 0; e < 8; e++) {
            rsum[e] += __shfl_xor_sync(0xffffffffu, rsum[e], 1);
            rsum[e] += __shfl_xor_sync(0xffffffffu, rsum[e], 2);
        }
        __syncthreads();
        float* smemRow = (float*)sm;
        smemRow[tid] = 0.f;
        __syncthreads();
        if (t == 0) {
            #pragma unroll
            for (int ii = 0; ii < 4; ii++) {
                atomicAdd(&smemRow[m0 + ii * 16 + g], rsum[ii * 2 + 0]);
                atomicAdd(&smemRow[m0 + ii * 16 + 8 + g], rsum[ii * 2 + 1]);
            }
        }
        __syncthreads();
        const size_t grow = (size_t)bz * L1 + by * 128 + tid;
        rowpart[(size_t)bx * ROWS1 + grow] = smemRow[tid];
        return;
    }

    // ---- normal epilogue ----
    int colblk = bx * 128;
    __half* Ch = (__half*)Cv;
    float* Cf = (float*)Cv;
    if (cSeg > 0) {
        const int seg = colblk / cSeg;
        Ch += (long long)seg * cSegStride;
        colblk -= seg * cSeg;
    }
    const int col_base = colblk + n0 + t * 2;
    const int bcol_base = bx * 128 + n0 + t * 2;
    #pragma unroll
    for (int ii = 0; ii < 4; ii++) {
        const int r0 = row_base + ii * 16;
        float rb0 = 0.f, rb1 = 0.f;
        if (bias_mode == 2) { rb0 = __ldg(bias + r0); rb1 = __ldg(bias + r0 + 8); }
        if (bias_mode == 3) {
            rb0 = __ldg(bias + (size_t)bz * L1 + r0);
            rb1 = __ldg(bias + (size_t)bz * L1 + r0 + 8);
        }
        #pragma unroll
        for (int jj = 0; jj < 8; jj++) {
            const int col = col_base + jj * 8;
            float2 v0, v1;
            if (bias_mode == 3) {       // row multiplier
                v0.x = acc[ii][jj][0] * rb0;
                v0.y = acc[ii][jj][1] * rb0;
                v1.x = acc[ii][jj][2] * rb1;
                v1.y = acc[ii][jj][3] * rb1;
            } else {
                float bx0, by0, bx1, by1;
                if (bias_mode == 1) {
                    const int bc = bcol_base + jj * 8;
                    float cb0 = __ldg(bias + bc), cb1 = __ldg(bias + bc + 1);
                    bx0 = cb0; by0 = cb1; bx1 = cb0; by1 = cb1;
                } else if (bias_mode == 2) {
                    bx0 = rb0; by0 = rb0; bx1 = rb1; by1 = rb1;
                } else {
                    bx0 = by0 = bx1 = by1 = 0.f;
                }
                v0.x = acc[ii][jj][0] * scale + bx0;
                v0.y = acc[ii][jj][1] * scale + by0;
                v1.x = acc[ii][jj][2] * scale + bx1;
                v1.y = acc[ii][jj][3] * scale + by1;
            }
            if (round_out) {
                *(__half2*)(Ch + (size_t)r0 * ldC + col) = __floats2half2_rn(v0.x, v0.y);
                *(__half2*)(Ch + (size_t)(r0 + 8) * ldC + col) = __floats2half2_rn(v1.x, v1.y);
            } else {
                *(float2*)(Cf + (size_t)r0 * ldC + col) = v0;
                *(float2*)(Cf + (size_t)(r0 + 8) * ldC + col) = v1;
            }
        }
    }
}

// ---- standalone GEMM (batched via blockIdx.z strides, element strides) ----
__global__ void __launch_bounds__(128, 3)
gemm_mma(const __half* __restrict__ A, const __half* __restrict__ B,
         const float* __restrict__ bias, void* __restrict__ C,
         int K, int ldA, int ldB, int ldC,
         float scale, int round_out, int bias_mode,
         long long sA, long long sB, long long sC,
         int cSeg, long long cSegStride, float* __restrict__ rowpart) {
    extern __shared__ uint32_t sm[];
    void* Cz = round_out ? (void*)((__half*)C + (long long)blockIdx.z * sC)
                         : (void*)((float*)C + (long long)blockIdx.z * sC);
    gemm_body(A + (long long)blockIdx.z * sA, B + (long long)blockIdx.z * sB,
              bias, Cz, K, ldA, ldB, ldC, scale, round_out, bias_mode,
              blockIdx.x, blockIdx.y, blockIdx.z, cSeg, cSegStride, rowpart, sm);
}

// ---- fused {Q-proj, K-proj, vT} : 3072 CTAs, one tail wave ----
__global__ void __launch_bounds__(128, 3)
gemm_fused3(const __half* __restrict__ x1, const __half* __restrict__ wqT,
            const float* __restrict__ bq, __half* __restrict__ q,
            const __half* __restrict__ x2, const __half* __restrict__ wkT,
            const float* __restrict__ bk, __half* __restrict__ kk,
            const __half* __restrict__ wvT, const float* __restrict__ bv,
            __half* __restrict__ vT) {
    extern __shared__ uint32_t sm[];
    const int id = blockIdx.x >> 10;
    const int local = blockIdx.x & 1023;
    if (id == 0) {
        gemm_body(x1, wqT, bq, q, D1, D1, D1, EDIM, 1.f, 1, 1,
                  local & 7, local >> 3, 0, 0, 0, nullptr, sm);
    } else if (id == 1) {
        gemm_body(x2, wkT, bk, kk, D2, D2, D2, EDIM, 1.f, 1, 1,
                  local & 7, local >> 3, 0, 0, 0, nullptr, sm);
    } else {
        gemm_body(wvT, x2, bv, vT, D2, D2, D2, L2, 1.f, 1, 2,
                  local & 127, local >> 7, 0, L2, (long long)EDIM * L2, nullptr, sm);
    }
}

// ================= rowsum reduce: inv[r] = 1 / sum_x part[x][r] =================
__global__ __launch_bounds__(256)
void rowsum_reduce(const float* __restrict__ part, float* __restrict__ inv) {
    const int r = blockIdx.x * 256 + threadIdx.x;
    float s = 0.f;
    #pragma unroll
    for (int x = 0; x < 16; x++) s += part[(size_t)x * ROWS1 + r];
    inv[r] = 1.0f / s;
}

// ================= layernorm / transpose =================
static __device__ __forceinline__ float blockReduceSum256(float v) {
    __shared__ float sh[8];
    int lane = threadIdx.x & 31, w = threadIdx.x >> 5;
    #pragma unroll
    for (int o = 16; o > 0; o >>= 1) v += __shfl_xor_sync(0xffffffffu, v, o);
    __syncthreads();
    if (lane == 0) sh[w] = v;
    __syncthreads();
    if (w == 0) {
        v = (lane < 8) ? sh[lane] : 0.f;
        #pragma unroll
        for (int o = 4; o > 0; o >>= 1) v += __shfl_xor_sync(0xffffffffu, v, o);
        if (lane == 0) sh[0] = v;
    }
    __syncthreads();
    return sh[0];
}

template<int NV>
__global__ __launch_bounds__(256)
void layernorm_kernel(const float* __restrict__ x, const float* __restrict__ g,
                      const float* __restrict__ b, __half* __restrict__ y, int D) {
    const size_t row = blockIdx.x;
    const float* xr = x + row * (size_t)D;
    __half*      yr = y + row * (size_t)D;
    float v[NV];
    float s = 0.f;
    #pragma unroll
    for (int j = 0; j < NV; j++) { v[j] = xr[threadIdx.x + j * 256]; s += v[j]; }
    const float mu = blockReduceSum256(s) * (1.f / (float)D);
    float sq = 0.f;
    #pragma unroll
    for (int j = 0; j < NV; j++) { float d = v[j] - mu; sq += d * d; }
    const float rstd = rsqrtf(blockReduceSum256(sq) * (1.f / (float)D) + 1e-5f);
    #pragma unroll
    for (int j = 0; j < NV; j++) {
        int idx = threadIdx.x + j * 256;
        yr[idx] = __float2half_rn((v[j] - mu) * rstd * g[idx] + b[idx]);
    }
}

static __device__ __forceinline__ void transpose_body(
    const float* __restrict__ in, __half* __restrict__ out,
    int R, int C, int bx, int by) {
    __shared__ float tb[32][33];
    const int r0 = by * 32, c0 = bx * 32;
    const int tx = threadIdx.x & 31, ty = threadIdx.x >> 5;
    #pragma unroll
    for (int k = 0; k < 32; k += 8)
        tb[ty + k][tx] = in[(size_t)(r0 + ty + k) * C + c0 + tx];
    __syncthreads();
    #pragma unroll
    for (int k = 0; k < 32; k += 8)
        out[(size_t)(c0 + ty + k) * R + r0 + tx] = __float2half_rn(tb[tx][ty + k]);
}

// all 4 weight transposes in one launch (3584 blocks)
__global__ __launch_bounds__(256)
void transpose4(const float* __restrict__ Wq, __half* __restrict__ wqT,
                const float* __restrict__ Wk, __half* __restrict__ wkT,
                const float* __restrict__ Wv, __half* __restrict__ wvT,
                const float* __restrict__ Wo, __half* __restrict__ woT) {
    int b = blockIdx.x;
    if (b < 1024) {
        transpose_body(Wq, wqT, D1, EDIM, b & 31, b >> 5);
    } else if (b < 1792) {
        b -= 1024;
        transpose_body(Wk, wkT, D2, EDIM, b & 31, b >> 5);
    } else if (b < 2560) {
        b -= 1792;
        transpose_body(Wv, wvT, D2, EDIM, b & 31, b >> 5);
    } else {
        b -= 2560;
        transpose_body(Wo, woT, EDIM, D1, b & 31, b >> 5);
    }
}

// ================= launch =================
// Order: launch index 3 (ncu-profiled) = fused projection GEMM.
extern "C" void kernel_launch(void* const* d_in, const int* in_sizes, int n_in,
                              void* d_out, int out_size) {
    const float* modality1 = (const float*)d_in[0];
    const float* modality2 = (const float*)d_in[1];
    const float* ln1_g = (const float*)d_in[2];
    const float* ln1_b = (const float*)d_in[3];
    const float* ln2_g = (const float*)d_in[4];
    const float* ln2_b = (const float*)d_in[5];
    const float* Wq = (const float*)d_in[6];
    const float* bq = (const float*)d_in[7];
    const float* Wk = (const float*)d_in[8];
    const float* bk = (const float*)d_in[9];
    const float* Wv = (const float*)d_in[10];
    const float* bv = (const float*)d_in[11];
    const float* Wo = (const float*)d_in[12];
    const float* bo = (const float*)d_in[13];
    float* out = (float*)d_out;

    __half *x1, *x2, *q, *k, *vT, *s, *ctx, *wqT, *wkT, *wvT, *woT;
    float *rowpart, *inv;
    cudaGetSymbolAddress((void**)&x1, g_x1);
    cudaGetSymbolAddress((void**)&x2, g_x2);
    cudaGetSymbolAddress((void**)&q, g_q);
    cudaGetSymbolAddress((void**)&k, g_k);
    cudaGetSymbolAddress((void**)&vT, g_vT);
    cudaGetSymbolAddress((void**)&s, g_s);
    cudaGetSymbolAddress((void**)&ctx, g_ctx);
    cudaGetSymbolAddress((void**)&wqT, g_wqT);
    cudaGetSymbolAddress((void**)&wkT, g_wkT);
    cudaGetSymbolAddress((void**)&wvT, g_wvT);
    cudaGetSymbolAddress((void**)&woT, g_woT);
    cudaGetSymbolAddress((void**)&rowpart, g_rowpart);
    cudaGetSymbolAddress((void**)&inv, g_inv);

    cudaFuncSetAttribute(gemm_mma, cudaFuncAttributeMaxDynamicSharedMemorySize, GSMEM);
    cudaFuncSetAttribute(gemm_fused3, cudaFuncAttributeMaxDynamicSharedMemorySize, GSMEM);

    const float scaling = 1.0f / 32.0f;   // E^-0.5

    // 0) all weight transposes   1) LN1   2) LN2
    transpose4<<<3584, 256>>>(Wq, wqT, Wk, wkT, Wv, wvT, Wo, woT);
    layernorm_kernel<4><<<ROWS1, 256>>>(modality1, ln1_g, ln1_b, x1, D1);
    layernorm_kernel<3><<<ROWS2, 256>>>(modality2, ln2_g, ln2_b, x2, D2);

    // 3) fused {Q-proj, K-proj, vT}  <-- ncu-profiled launch index
    gemm_fused3<<<3072, 128, GSMEM>>>(x1, wqT, bq, q,
                                      x2, wkT, bk, k,
                                      wvT, bv, vT);

    // 4) P = exp(scaling * Q @ K^T)  (batched; row-sum side-band -> rowpart)
    gemm_mma<<<dim3(L2 / 128, L1 / 128, BATCH), 128, GSMEM>>>(
        q, k, nullptr, s, EDIM, EDIM, EDIM, L2, scaling, 1, 0,
        (long long)L1 * EDIM, (long long)L2 * EDIM, (long long)L1 * L2,
        0, 0, rowpart);

    // 5) inv[r] = 1 / rowsum
    rowsum_reduce<<<ROWS1 / 256, 256>>>(rowpart, inv);

    // 6) ctx = (P @ V) * inv[row]   (row multiplier epilogue, fp16 out)
    gemm_mma<<<dim3(EDIM / 128, L1 / 128, BATCH), 128, GSMEM>>>(
        s, vT, inv, ctx, L2, L2, L2, EDIM, 1.f, 1, 3,
        (long long)L1 * L2, (long long)EDIM * L2, (long long)L1 * EDIM, 0, 0, nullptr);

    // 7) out = ctx @ Wo + bo (fp32 output)
    gemm_mma<<<dim3(D1 / 128, ROWS1 / 128), 128, GSMEM>>>(
        ctx, woT, bo, out, EDIM, EDIM, EDIM, D1, 1.f, 0, 1, 0, 0, 0, 0, 0, nullptr);
}

// round 15
// speedup vs baseline: 2.6895x; 1.0024x over previous
#include <cuda_runtime.h>
#include <cuda_fp16.h>
#include <math.h>
#include <stdint.h>

// ---------------- problem constants ----------------
#define BATCH 8
#define L1 2048
#define L2 2048
#define D1 1024
#define D2 768
#define EDIM 1024
#define ROWS1 (BATCH * L1)          // 16384
#define ROWS2 (BATCH * L2)          // 16384

// ---------------- scratch (device globals; no allocation) ----------------
__device__ __half g_x1[ROWS1 * D1];
__device__ __half g_x2[ROWS2 * D2];
__device__ __half g_q[ROWS1 * EDIM];
__device__ __half g_k[ROWS2 * EDIM];
__device__ __half g_uT[(size_t)BATCH * D1 * L2];   // [B][D1][L2] pitch 2048
__device__ __half g_s[(size_t)BATCH * L1 * L2];    // exp-scores (unnormalized)
__device__ __half g_wqT[EDIM * D1];
__device__ __half g_wkT[EDIM * D2];
__device__ __half g_wvH[D2 * EDIM];                // fp16 copy of Wv
__device__ __half g_woT[D1 * EDIM];
__device__ __half g_w2T[D1 * D2];                  // (Wv@Wo)^T
__device__ float g_c2[D1];                         // bv@Wo + bo
__device__ float g_rowpart[16 * ROWS1];
__device__ float g_inv[ROWS1];

// ---------------- helpers ----------------
static __device__ __forceinline__ uint32_t smem_u32(const void* p) {
    uint32_t a;
    asm("{ .reg .u64 t; cvta.to.shared.u64 t, %1; cvt.u32.u64 %0, t; }" : "=r"(a) : "l"(p));
    return a;
}
static __device__ __forceinline__ void cp_async16(uint32_t saddr, const void* gptr) {
    asm volatile("cp.async.cg.shared.global [%0], [%1], 16;" :: "r"(saddr), "l"(gptr));
}
static __device__ __forceinline__ void cp_commit() {
    asm volatile("cp.async.commit_group;" ::: "memory");
}
template<int N>
static __device__ __forceinline__ void cp_wait() {
    asm volatile("cp.async.wait_group %0;" :: "n"(N) : "memory");
}
static __device__ __forceinline__ void ldsm_x4(uint32_t* r, uint32_t a) {
    asm volatile("ldmatrix.sync.aligned.m8n8.x4.shared.b16 {%0,%1,%2,%3}, [%4];"
                 : "=r"(r[0]), "=r"(r[1]), "=r"(r[2]), "=r"(r[3]) : "r"(a));
}

#define MMA_F16(d, a, b) \
    asm volatile("mma.sync.aligned.m16n8k16.row.col.f32.f16.f16.f32 " \
        "{%0,%1,%2,%3}, {%4,%5,%6,%7}, {%8,%9}, {%0,%1,%2,%3};" \
        : "+f"((d)[0]), "+f"((d)[1]), "+f"((d)[2]), "+f"((d)[3]) \
        : "r"((a)[0]), "r"((a)[1]), "r"((a)[2]), "r"((a)[3]), \
          "r"((b)[0]), "r"((b)[1]))

// ================= fp16 mma.sync GEMM body =================
// C[M,N] = scale*(A[M,K] @ B[N,K]^T) + bias;  A,B fp16 K-major, pitches in halves.
// BM=128, BN=128, BK=64 halves. 128 threads = 4 warps (2x2), warp tile 64x64.
// bias_mode: 0 none, 1 col bias, 2 row bias,
//            3 row MULTIPLIER bias[bz*2048+r],
//            4 row MULTIPLIER bias[bz*2048+r] + col bias bias2[col].
// round_out: 1 -> C is __half, 0 -> C is float.
// rowpart != null: epilogue stores exp(scale*acc) as fp16 and per-CTA row sums.
#define ROWB 144                      // bytes per smem row
#define ASTG (128 * ROWB)             // bytes per A stage (18432)
#define STGB (2 * ASTG)               // bytes per stage (36864)
#define GSMEM (2 * STGB)              // 73728 bytes

static __device__ __forceinline__ void gemm_body(
    const __half* __restrict__ A, const __half* __restrict__ B,
    const float* __restrict__ bias, const float* __restrict__ bias2,
    void* __restrict__ Cv,
    int K, int ldA, int ldB, int ldC,
    float scale, int round_out, int bias_mode,
    int bx, int by, int bz,
    int cSeg, long long cSegStride, float* __restrict__ rowpart,
    uint32_t* sm) {
    const uint32_t sb = smem_u32(sm);
    const int tid = threadIdx.x;
    const int lane = tid & 31, warp = tid >> 5;
    const int g = lane >> 2, t = lane & 3;
    const int m0 = (warp >> 1) * 64;
    const int n0 = (warp & 1) * 64;

    A += (size_t)by * 128 * ldA;
    B += (size_t)bx * 128 * ldB;

    const int r_ld = tid >> 3;
    const int c16 = tid & 7;

    const int lsub = lane >> 3, lr = lane & 7;
    const uint32_t aoff = (uint32_t)((m0 + ((lsub & 1) << 3) + lr) * ROWB +
                                     ((lsub >> 1) << 4));
    const uint32_t boff = (uint32_t)(ASTG + (n0 + ((lsub >> 1) << 3) + lr) * ROWB +
                                     ((lsub & 1) << 4));

    float acc[4][8][4];
    #pragma unroll
    for (int i = 0; i < 4; i++)
        #pragma unroll
        for (int j = 0; j < 8; j++)
            #pragma unroll
            for (int e = 0; e < 4; e++) acc[i][j][e] = 0.f;

    const int nch = K >> 6;

    #pragma unroll
    for (int f = 0; f < 8; f++) {
        int row = r_ld + f * 16;
        cp_async16(sb + row * ROWB + c16 * 16, A + (size_t)row * ldA + c16 * 8);
        cp_async16(sb + ASTG + row * ROWB + c16 * 16, B + (size_t)row * ldB + c16 * 8);
    }
    cp_commit();

    for (int i = 0; i < nch; i++) {
        cp_wait<0>();
        __syncthreads();
        {
            const int ic = i + 1;
            if (ic < nch) {
                const uint32_t stb = sb + (uint32_t)((ic & 1) * STGB);
                const int k0 = ic * 64;
                #pragma unroll
                for (int f = 0; f < 8; f++) {
                    int row = r_ld + f * 16;
                    cp_async16(stb + row * ROWB + c16 * 16,
                               A + (size_t)row * ldA + k0 + c16 * 8);
                    cp_async16(stb + ASTG + row * ROWB + c16 * 16,
                               B + (size_t)row * ldB + k0 + c16 * 8);
                }
            }
            cp_commit();
        }

        const uint32_t stBase = sb + (uint32_t)((i & 1) * STGB);
        #pragma unroll
        for (int ks = 0; ks < 4; ks++) {
            uint32_t af[4][4], bf[4][4];
            #pragma unroll
            for (int ii = 0; ii < 4; ii++)
                ldsm_x4(af[ii], stBase + aoff + ii * (16 * ROWB) + ks * 32);
            #pragma unroll
            for (int p = 0; p < 4; p++)
                ldsm_x4(bf[p], stBase + boff + p * (16 * ROWB) + ks * 32);
            #pragma unroll
            for (int ii = 0; ii < 4; ii++)
                #pragma unroll
                for (int jj = 0; jj < 8; jj++)
                    MMA_F16(acc[ii][jj], af[ii], &bf[jj >> 1][(jj & 1) * 2]);
        }
    }

    const int row_base = by * 128 + m0 + g;

    if (rowpart != nullptr) {
        // ---- exp epilogue with row-sum side-band (scores GEMM), fp16 out ----
        __half* C = (__half*)Cv;
        float rsum[8];
        #pragma unroll
        for (int e = 0; e < 8; e++) rsum[e] = 0.f;
        const int col_base = bx * 128 + n0 + t * 2;
        #pragma unroll
        for (int ii = 0; ii < 4; ii++) {
            const int r0 = row_base + ii * 16;
            #pragma unroll
            for (int jj = 0; jj < 8; jj++) {
                const int col = col_base + jj * 8;
                float e0 = __expf(acc[ii][jj][0] * scale);
                float e1 = __expf(acc[ii][jj][1] * scale);
                float e2 = __expf(acc[ii][jj][2] * scale);
                float e3 = __expf(acc[ii][jj][3] * scale);
                rsum[ii * 2 + 0] += e0 + e1;
                rsum[ii * 2 + 1] += e2 + e3;
                *(__half2*)(C + (size_t)r0 * ldC + col) = __floats2half2_rn(e0, e1);
                *(__half2*)(C + (size_t)(r0 + 8) * ldC + col) = __floats2half2_rn(e2, e3);
            }
        }
        #pragma unroll
        for (int e = 0; e < 8; e++) {
            rsum[e] += __shfl_xor_sync(0xffffffffu, rsum[e], 1);
            rsum[e] += __shfl_xor_sync(0xffffffffu, rsum[e], 2);
        }
        __syncthreads();
        float* smemRow = (float*)sm;
        smemRow[tid] = 0.f;
        __syncthreads();
        if (t == 0) {
            #pragma unroll
            for (int ii = 0; ii < 4; ii++) {
                atomicAdd(&smemRow[m0 + ii * 16 + g], rsum[ii * 2 + 0]);
                atomicAdd(&smemRow[m0 + ii * 16 + 8 + g], rsum[ii * 2 + 1]);
            }
        }
        __syncthreads();
        const size_t grow = (size_t)bz * L1 + by * 128 + tid;
        rowpart[(size_t)bx * ROWS1 + grow] = smemRow[tid];
        return;
    }

    // ---- normal epilogue ----
    int colblk = bx * 128;
    __half* Ch = (__half*)Cv;
    float* Cf = (float*)Cv;
    if (cSeg > 0) {
        const int seg = colblk / cSeg;
        Ch += (long long)seg * cSegStride;
        colblk -= seg * cSeg;
    }
    const int col_base = colblk + n0 + t * 2;
    const int bcol_base = bx * 128 + n0 + t * 2;
    #pragma unroll
    for (int ii = 0; ii < 4; ii++) {
        const int r0 = row_base + ii * 16;
        float rb0 = 0.f, rb1 = 0.f;
        if (bias_mode == 2) { rb0 = __ldg(bias + r0); rb1 = __ldg(bias + r0 + 8); }
        if (bias_mode >= 3) {
            rb0 = __ldg(bias + (size_t)bz * L1 + r0);
            rb1 = __ldg(bias + (size_t)bz * L1 + r0 + 8);
        }
        #pragma unroll
        for (int jj = 0; jj < 8; jj++) {
            const int col = col_base + jj * 8;
            float2 v0, v1;
            if (bias_mode >= 3) {       // row multiplier (+ optional col bias)
                float cb0 = 0.f, cb1 = 0.f;
                if (bias_mode == 4) {
                    const int bc = bcol_base + jj * 8;
                    cb0 = __ldg(bias2 + bc);
                    cb1 = __ldg(bias2 + bc + 1);
                }
                v0.x = acc[ii][jj][0] * rb0 + cb0;
                v0.y = acc[ii][jj][1] * rb0 + cb1;
                v1.x = acc[ii][jj][2] * rb1 + cb0;
                v1.y = acc[ii][jj][3] * rb1 + cb1;
            } else {
                float bx0, by0, bx1, by1;
                if (bias_mode == 1) {
                    const int bc = bcol_base + jj * 8;
                    float cb0 = __ldg(bias + bc), cb1 = __ldg(bias + bc + 1);
                    bx0 = cb0; by0 = cb1; bx1 = cb0; by1 = cb1;
                } else if (bias_mode == 2) {
                    bx0 = rb0; by0 = rb0; bx1 = rb1; by1 = rb1;
                } else {
                    bx0 = by0 = bx1 = by1 = 0.f;
                }
                v0.x = acc[ii][jj][0] * scale + bx0;
                v0.y = acc[ii][jj][1] * scale + by0;
                v1.x = acc[ii][jj][2] * scale + bx1;
                v1.y = acc[ii][jj][3] * scale + by1;
            }
            if (round_out) {
                *(__half2*)(Ch + (size_t)r0 * ldC + col) = __floats2half2_rn(v0.x, v0.y);
                *(__half2*)(Ch + (size_t)(r0 + 8) * ldC + col) = __floats2half2_rn(v1.x, v1.y);
            } else {
                *(float2*)(Cf + (size_t)r0 * ldC + col) = v0;
                *(float2*)(Cf + (size_t)(r0 + 8) * ldC + col) = v1;
            }
        }
    }
}

// ---- standalone GEMM (batched via blockIdx.z strides, element strides) ----
__global__ void __launch_bounds__(128, 3)
gemm_mma(const __half* __restrict__ A, const __half* __restrict__ B,
         const float* __restrict__ bias, const float* __restrict__ bias2,
         void* __restrict__ C,
         int K, int ldA, int ldB, int ldC,
         float scale, int round_out, int bias_mode,
         long long sA, long long sB, long long sC,
         int cSeg, long long cSegStride, float* __restrict__ rowpart) {
    extern __shared__ uint32_t sm[];
    void* Cz = round_out ? (void*)((__half*)C + (long long)blockIdx.z * sC)
                         : (void*)((float*)C + (long long)blockIdx.z * sC);
    gemm_body(A + (long long)blockIdx.z * sA, B + (long long)blockIdx.z * sB,
              bias, bias2, Cz, K, ldA, ldB, ldC, scale, round_out, bias_mode,
              blockIdx.x, blockIdx.y, blockIdx.z, cSeg, cSegStride, rowpart, sm);
}

// ---- fused {Q-proj, K-proj, uT} : 3072 CTAs, one tail wave ----
__global__ void __launch_bounds__(128, 3)
gemm_fused3(const __half* __restrict__ x1, const __half* __restrict__ wqT,
            const float* __restrict__ bq, __half* __restrict__ q,
            const __half* __restrict__ x2, const __half* __restrict__ wkT,
            const float* __restrict__ bk, __half* __restrict__ kk,
            const __half* __restrict__ w2T, __half* __restrict__ uT) {
    extern __shared__ uint32_t sm[];
    const int id = blockIdx.x >> 10;
    const int local = blockIdx.x & 1023;
    if (id == 0) {
        gemm_body(x1, wqT, bq, nullptr, q, D1, D1, D1, EDIM, 1.f, 1, 1,
                  local & 7, local >> 3, 0, 0, 0, nullptr, sm);
    } else if (id == 1) {
        gemm_body(x2, wkT, bk, nullptr, kk, D2, D2, D2, EDIM, 1.f, 1, 1,
                  local & 7, local >> 3, 0, 0, 0, nullptr, sm);
    } else {
        // uT[b][d1][c] = (w2T @ x2^T), segmented C pitch 2048, no bias
        gemm_body(w2T, x2, nullptr, nullptr, uT, D2, D2, D2, L2, 1.f, 1, 0,
                  local & 127, local >> 7, 0, L2, (long long)D1 * L2, nullptr, sm);
    }
}

// ================= rowsum reduce: inv[r] = 1 / sum_x part[x][r] =================
__global__ __launch_bounds__(256)
void rowsum_reduce(const float* __restrict__ part, float* __restrict__ inv) {
    const int r = blockIdx.x * 256 + threadIdx.x;
    float s = 0.f;
    #pragma unroll
    for (int x = 0; x < 16; x++) s += part[(size_t)x * ROWS1 + r];
    inv[r] = 1.0f / s;
}

// ================= c2[j] = bo[j] + sum_e bv[e]*Wo[e,j] =================
__global__ __launch_bounds__(256)
void c2_kernel(const float* __restrict__ Wo, const float* __restrict__ bv,
               const float* __restrict__ bo, float* __restrict__ c2) {
    const int j = blockIdx.x * 256 + threadIdx.x;
    float s = bo[j];
    #pragma unroll 8
    for (int e = 0; e < EDIM; e++) s += bv[e] * Wo[(size_t)e * D1 + j];
    c2[j] = s;
}

// ================= layernorm / transpose =================
static __device__ __forceinline__ float blockReduceSum256(float v) {
    __shared__ float sh[8];
    int lane = threadIdx.x & 31, w = threadIdx.x >> 5;
    #pragma unroll
    for (int o = 16; o > 0; o >>= 1) v += __shfl_xor_sync(0xffffffffu, v, o);
    __syncthreads();
    if (lane == 0) sh[w] = v;
    __syncthreads();
    if (w == 0) {
        v = (lane < 8) ? sh[lane] : 0.f;
        #pragma unroll
        for (int o = 4; o > 0; o >>= 1) v += __shfl_xor_sync(0xffffffffu, v, o);
        if (lane == 0) sh[0] = v;
    }
    __syncthreads();
    return sh[0];
}

template<int NV>
__global__ __launch_bounds__(256)
void layernorm_kernel(const float* __restrict__ x, const float* __restrict__ g,
                      const float* __restrict__ b, __half* __restrict__ y, int D) {
    const size_t row = blockIdx.x;
    const float* xr = x + row * (size_t)D;
    __half*      yr = y + row * (size_t)D;
    float v[NV];
    float s = 0.f;
    #pragma unroll
    for (int j = 0; j < NV; j++) { v[j] = xr[threadIdx.x + j * 256]; s += v[j]; }
    const float mu = blockReduceSum256(s) * (1.f / (float)D);
    float sq = 0.f;
    #pragma unroll
    for (int j = 0; j < NV; j++) { float d = v[j] - mu; sq += d * d; }
    const float rstd = rsqrtf(blockReduceSum256(sq) * (1.f / (float)D) + 1e-5f);
    #pragma unroll
    for (int j = 0; j < NV; j++) {
        int idx = threadIdx.x + j * 256;
        yr[idx] = __float2half_rn((v[j] - mu) * rstd * g[idx] + b[idx]);
    }
}

static __device__ __forceinline__ void transpose_body(
    const float* __restrict__ in, __half* __restrict__ out,
    int R, int C, int bx, int by) {
    __shared__ float tb[32][33];
    const int r0 = by * 32, c0 = bx * 32;
    const int tx = threadIdx.x & 31, ty = threadIdx.x >> 5;
    #pragma unroll
    for (int k = 0; k < 32; k += 8)
        tb[ty + k][tx] = in[(size_t)(r0 + ty + k) * C + c0 + tx];
    __syncthreads();
    #pragma unroll
    for (int k = 0; k < 32; k += 8)
        out[(size_t)(c0 + ty + k) * R + r0 + tx] = __float2half_rn(tb[tx][ty + k]);
}

// wqT, wkT, woT transposes + plain fp16 copy of Wv, one launch (3584 blocks)
__global__ __launch_bounds__(256)
void transpose4(const float* __restrict__ Wq, __half* __restrict__ wqT,
                const float* __restrict__ Wk, __half* __restrict__ wkT,
                const float* __restrict__ Wv, __half* __restrict__ wvH,
                const float* __restrict__ Wo, __half* __restrict__ woT) {
    int b = blockIdx.x;
    if (b < 1024) {
        transpose_body(Wq, wqT, D1, EDIM, b & 31, b >> 5);
    } else if (b < 1792) {
        b -= 1024;
        transpose_body(Wk, wkT, D2, EDIM, b & 31, b >> 5);
    } else if (b < 2560) {
        b -= 1792;                            // 768 blocks: copy Wv [768,1024]
        const int r0 = (b >> 5) * 32, c0 = (b & 31) * 32;
        const int tx = threadIdx.x & 31, ty = threadIdx.x >> 5;
        #pragma unroll
        for (int k = 0; k < 32; k += 8) {
            size_t idx = (size_t)(r0 + ty + k) * EDIM + c0 + tx;
            wvH[idx] = __float2half_rn(Wv[idx]);
        }
    } else {
        b -= 2560;
        transpose_body(Wo, woT, EDIM, D1, b & 31, b >> 5);
    }
}

// ================= launch =================
extern "C" void kernel_launch(void* const* d_in, const int* in_sizes, int n_in,
                              void* d_out, int out_size) {
    const float* modality1 = (const float*)d_in[0];
    const float* modality2 = (const float*)d_in[1];
    const float* ln1_g = (const float*)d_in[2];
    const float* ln1_b = (const float*)d_in[3];
    const float* ln2_g = (const float*)d_in[4];
    const float* ln2_b = (const float*)d_in[5];
    const float* Wq = (const float*)d_in[6];
    const float* bq = (const float*)d_in[7];
    const float* Wk = (const float*)d_in[8];
    const float* bk = (const float*)d_in[9];
    const float* Wv = (const float*)d_in[10];
    const float* bv = (const float*)d_in[11];
    const float* Wo = (const float*)d_in[12];
    const float* bo = (const float*)d_in[13];
    float* out = (float*)d_out;

    __half *x1, *x2, *q, *k, *uT, *s, *wqT, *wkT, *wvH, *woT, *w2T;
    float *rowpart, *inv, *c2;
    cudaGetSymbolAddress((void**)&x1, g_x1);
    cudaGetSymbolAddress((void**)&x2, g_x2);
    cudaGetSymbolAddress((void**)&q, g_q);
    cudaGetSymbolAddress((void**)&k, g_k);
    cudaGetSymbolAddress((void**)&uT, g_uT);
    cudaGetSymbolAddress((void**)&s, g_s);
    cudaGetSymbolAddress((void**)&wqT, g_wqT);
    cudaGetSymbolAddress((void**)&wkT, g_wkT);
    cudaGetSymbolAddress((void**)&wvH, g_wvH);
    cudaGetSymbolAddress((void**)&woT, g_woT);
    cudaGetSymbolAddress((void**)&w2T, g_w2T);
    cudaGetSymbolAddress((void**)&c2, g_c2);
    cudaGetSymbolAddress((void**)&rowpart, g_rowpart);
    cudaGetSymbolAddress((void**)&inv, g_inv);

    cudaFuncSetAttribute(gemm_mma, cudaFuncAttributeMaxDynamicSharedMemorySize, GSMEM);
    cudaFuncSetAttribute(gemm_fused3, cudaFuncAttributeMaxDynamicSharedMemorySize, GSMEM);

    const float scaling = 1.0f / 32.0f;   // E^-0.5

    // 0) weight transposes + Wv fp16 copy
    transpose4<<<3584, 256>>>(Wq, wqT, Wk, wkT, Wv, wvH, Wo, woT);
    // 1-2) layernorms
    layernorm_kernel<4><<<ROWS1, 256>>>(modality1, ln1_g, ln1_b, x1, D1);
    layernorm_kernel<3><<<ROWS2, 256>>>(modality2, ln2_g, ln2_b, x2, D2);

    // 3) w2T[d1,d2] = (Wv@Wo)^T = woT @ wvH^T   (48 CTAs)
    gemm_mma<<<dim3(D2 / 128, D1 / 128), 128, GSMEM>>>(
        woT, wvH, nullptr, nullptr, w2T, EDIM, EDIM, EDIM, D2,
        1.f, 1, 0, 0, 0, 0, 0, 0, nullptr);

    // 4) c2 = bv@Wo + bo
    c2_kernel<<<D1 / 256, 256>>>(Wo, bv, bo, c2);

    // 5) fused {Q-proj, K-proj, uT}
    gemm_fused3<<<3072, 128, GSMEM>>>(x1, wqT, bq, q,
                                      x2, wkT, bk, k,
                                      w2T, uT);

    // 6) P = exp(scaling * Q @ K^T)  (batched; row-sum side-band -> rowpart)
    gemm_mma<<<dim3(L2 / 128, L1 / 128, BATCH), 128, GSMEM>>>(
        q, k, nullptr, nullptr, s, EDIM, EDIM, EDIM, L2, scaling, 1, 0,
        (long long)L1 * EDIM, (long long)L2 * EDIM, (long long)L1 * L2,
        0, 0, rowpart);

    // 7) inv[r] = 1 / rowsum
    rowsum_reduce<<<ROWS1 / 256, 256>>>(rowpart, inv);

    // 8) out = (P @ u) * inv[row] + c2[col]   (fp32 output)
    gemm_mma<<<dim3(D1 / 128, L1 / 128, BATCH), 128, GSMEM>>>(
        s, uT, inv, c2, out, L2, L2, L2, D1, 1.f, 0, 4,
        (long long)L1 * L2, (long long)D1 * L2, (long long)L1 * D1,
        0, 0, nullptr);
}

// round 16
// speedup vs baseline: 2.6945x; 1.0019x over previous
#include <cuda_runtime.h>
#include <cuda_fp16.h>
#include <math.h>
#include <stdint.h>

// ---------------- problem constants ----------------
#define BATCH 8
#define L1 2048
#define L2 2048
#define D1 1024
#define D2 768
#define EDIM 1024
#define ROWS1 (BATCH * L1)          // 16384
#define ROWS2 (BATCH * L2)          // 16384

// ---------------- scratch (device globals; no allocation) ----------------
__device__ __half g_x1[ROWS1 * D1];
__device__ __half g_x2[ROWS2 * D2];
__device__ __half g_q[ROWS1 * EDIM];
__device__ __half g_k[ROWS2 * EDIM];
__device__ __half g_uT[(size_t)BATCH * D1 * L2];   // [B][D1][L2] pitch 2048
__device__ __half g_s[(size_t)BATCH * L1 * L2];    // exp-scores (unnormalized)
__device__ __half g_wqT[EDIM * D1];
__device__ __half g_wkT[EDIM * D2];
__device__ __half g_wvH[D2 * EDIM];                // fp16 copy of Wv
__device__ __half g_woT[D1 * EDIM];
__device__ __half g_w2T[D1 * D2];                  // (Wv@Wo)^T
__device__ float g_c2[D1];                         // bv@Wo + bo
__device__ float g_rowpart[16 * ROWS1];
__device__ float g_inv[ROWS1];

// ---------------- helpers ----------------
static __device__ __forceinline__ uint32_t smem_u32(const void* p) {
    uint32_t a;
    asm("{ .reg .u64 t; cvta.to.shared.u64 t, %1; cvt.u32.u64 %0, t; }" : "=r"(a) : "l"(p));
    return a;
}
static __device__ __forceinline__ void cp_async16(uint32_t saddr, const void* gptr) {
    asm volatile("cp.async.cg.shared.global [%0], [%1], 16;" :: "r"(saddr), "l"(gptr));
}
static __device__ __forceinline__ void cp_commit() {
    asm volatile("cp.async.commit_group;" ::: "memory");
}
template<int N>
static __device__ __forceinline__ void cp_wait() {
    asm volatile("cp.async.wait_group %0;" :: "n"(N) : "memory");
}
static __device__ __forceinline__ void ldsm_x4(uint32_t* r, uint32_t a) {
    asm volatile("ldmatrix.sync.aligned.m8n8.x4.shared.b16 {%0,%1,%2,%3}, [%4];"
                 : "=r"(r[0]), "=r"(r[1]), "=r"(r[2]), "=r"(r[3]) : "r"(a));
}

#define MMA_F16(d, a, b) \
    asm volatile("mma.sync.aligned.m16n8k16.row.col.f32.f16.f16.f32 " \
        "{%0,%1,%2,%3}, {%4,%5,%6,%7}, {%8,%9}, {%0,%1,%2,%3};" \
        : "+f"((d)[0]), "+f"((d)[1]), "+f"((d)[2]), "+f"((d)[3]) \
        : "r"((a)[0]), "r"((a)[1]), "r"((a)[2]), "r"((a)[3]), \
          "r"((b)[0]), "r"((b)[1]))

// ================= fp16 mma.sync GEMM body =================
// C[M,N] = scale*(A[M,K] @ B[N,K]^T) + bias;  A,B fp16 K-major, pitches in halves.
// BM=128, BN=128, BK=64 halves. 128 threads = 4 warps (2x2), warp tile 64x64.
// 3-stage cp.async, 2 CTAs/SM, fragment double-buffering (ldsm ks+1 under MMA ks).
// bias_mode: 0 none, 1 col bias, 2 row bias,
//            3 row MULT bias[bz*2048+r], 4 row MULT + col bias bias2[col].
#define ROWB 144                      // bytes per smem row
#define ASTG (128 * ROWB)             // bytes per A stage (18432)
#define STGB (2 * ASTG)               // bytes per stage (36864)
#define GSMEM (3 * STGB)              // 110592 bytes

#define LDSM_ALL(buf, base, ks) do { \
    _Pragma("unroll") \
    for (int _ii = 0; _ii < 4; _ii++) \
        ldsm_x4(af[buf][_ii], (base) + aoff + _ii * (16 * ROWB) + (ks) * 32); \
    _Pragma("unroll") \
    for (int _p = 0; _p < 4; _p++) \
        ldsm_x4(bf[buf][_p], (base) + boff + _p * (16 * ROWB) + (ks) * 32); \
} while (0)

static __device__ __forceinline__ void gemm_body(
    const __half* __restrict__ A, const __half* __restrict__ B,
    const float* __restrict__ bias, const float* __restrict__ bias2,
    void* __restrict__ Cv,
    int K, int ldA, int ldB, int ldC,
    float scale, int round_out, int bias_mode,
    int bx, int by, int bz,
    int cSeg, long long cSegStride, float* __restrict__ rowpart,
    uint32_t* sm) {
    const uint32_t sb = smem_u32(sm);
    const int tid = threadIdx.x;
    const int lane = tid & 31, warp = tid >> 5;
    const int g = lane >> 2, t = lane & 3;
    const int m0 = (warp >> 1) * 64;
    const int n0 = (warp & 1) * 64;

    A += (size_t)by * 128 * ldA;
    B += (size_t)bx * 128 * ldB;

    const int r_ld = tid >> 3;
    const int c16 = tid & 7;

    const int lsub = lane >> 3, lr = lane & 7;
    const uint32_t aoff = (uint32_t)((m0 + ((lsub & 1) << 3) + lr) * ROWB +
                                     ((lsub >> 1) << 4));
    const uint32_t boff = (uint32_t)(ASTG + (n0 + ((lsub >> 1) << 3) + lr) * ROWB +
                                     ((lsub & 1) << 4));

    float acc[4][8][4];
    #pragma unroll
    for (int i = 0; i < 4; i++)
        #pragma unroll
        for (int j = 0; j < 8; j++)
            #pragma unroll
            for (int e = 0; e < 4; e++) acc[i][j][e] = 0.f;

    const int nch = K >> 6;

    // prologue: chunks 0,1 -> stages 0,1
    #pragma unroll
    for (int s = 0; s < 2; s++) {
        const uint32_t stb = sb + (uint32_t)(s * STGB);
        const int k0 = s * 64;
        #pragma unroll
        for (int f = 0; f < 8; f++) {
            int row = r_ld + f * 16;
            cp_async16(stb + row * ROWB + c16 * 16, A + (size_t)row * ldA + k0 + c16 * 8);
            cp_async16(stb + ASTG + row * ROWB + c16 * 16, B + (size_t)row * ldB + k0 + c16 * 8);
        }
        cp_commit();
    }

    int cs = 0, ps = 2;                       // compute stage, prefetch stage
    for (int i = 0; i < nch; i++) {
        cp_wait<1>();
        __syncthreads();
        {
            const int ic = i + 2;
            if (ic < nch) {
                const uint32_t stb = sb + (uint32_t)(ps * STGB);
                const int k0 = ic * 64;
                #pragma unroll
                for (int f = 0; f < 8; f++) {
                    int row = r_ld + f * 16;
                    cp_async16(stb + row * ROWB + c16 * 16,
                               A + (size_t)row * ldA + k0 + c16 * 8);
                    cp_async16(stb + ASTG + row * ROWB + c16 * 16,
                               B + (size_t)row * ldB + k0 + c16 * 8);
                }
            }
            cp_commit();
        }

        const uint32_t stBase = sb + (uint32_t)(cs * STGB);
        uint32_t af[2][4][4], bf[2][4][4];
        LDSM_ALL(0, stBase, 0);
        #pragma unroll
        for (int ks = 0; ks < 4; ks++) {
            const int cur = ks & 1;
            if (ks < 3) LDSM_ALL(cur ^ 1, stBase, ks + 1);
            #pragma unroll
            for (int ii = 0; ii < 4; ii++)
                #pragma unroll
                for (int jj = 0; jj < 8; jj++)
                    MMA_F16(acc[ii][jj], af[cur][ii], &bf[cur][jj >> 1][(jj & 1) * 2]);
        }
        cs = (cs + 1) == 3 ? 0 : cs + 1;
        ps = (ps + 1) == 3 ? 0 : ps + 1;
    }

    const int row_base = by * 128 + m0 + g;

    if (rowpart != nullptr) {
        // ---- exp epilogue with row-sum side-band (scores GEMM), fp16 out ----
        __half* C = (__half*)Cv;
        float rsum[8];
        #pragma unroll
        for (int e = 0; e < 8; e++) rsum[e] = 0.f;
        const int col_base = bx * 128 + n0 + t * 2;
        #pragma unroll
        for (int ii = 0; ii < 4; ii++) {
            const int r0 = row_base + ii * 16;
            #pragma unroll
            for (int jj = 0; jj < 8; jj++) {
                const int col = col_base + jj * 8;
                float e0 = __expf(acc[ii][jj][0] * scale);
                float e1 = __expf(acc[ii][jj][1] * scale);
                float e2 = __expf(acc[ii][jj][2] * scale);
                float e3 = __expf(acc[ii][jj][3] * scale);
                rsum[ii * 2 + 0] += e0 + e1;
                rsum[ii * 2 + 1] += e2 + e3;
                *(__half2*)(C + (size_t)r0 * ldC + col) = __floats2half2_rn(e0, e1);
                *(__half2*)(C + (size_t)(r0 + 8) * ldC + col) = __floats2half2_rn(e2, e3);
            }
        }
        #pragma unroll
        for (int e = 0; e < 8; e++) {
            rsum[e] += __shfl_xor_sync(0xffffffffu, rsum[e], 1);
            rsum[e] += __shfl_xor_sync(0xffffffffu, rsum[e], 2);
        }
        __syncthreads();
        float* smemRow = (float*)sm;
        smemRow[tid] = 0.f;
        __syncthreads();
        if (t == 0) {
            #pragma unroll
            for (int ii = 0; ii < 4; ii++) {
                atomicAdd(&smemRow[m0 + ii * 16 + g], rsum[ii * 2 + 0]);
                atomicAdd(&smemRow[m0 + ii * 16 + 8 + g], rsum[ii * 2 + 1]);
            }
        }
        __syncthreads();
        const size_t grow = (size_t)bz * L1 + by * 128 + tid;
        rowpart[(size_t)bx * ROWS1 + grow] = smemRow[tid];
        return;
    }

    // ---- normal epilogue ----
    int colblk = bx * 128;
    __half* Ch = (__half*)Cv;
    float* Cf = (float*)Cv;
    if (cSeg > 0) {
        const int seg = colblk / cSeg;
        Ch += (long long)seg * cSegStride;
        colblk -= seg * cSeg;
    }
    const int col_base = colblk + n0 + t * 2;
    const int bcol_base = bx * 128 + n0 + t * 2;
    #pragma unroll
    for (int ii = 0; ii < 4; ii++) {
        const int r0 = row_base + ii * 16;
        float rb0 = 0.f, rb1 = 0.f;
        if (bias_mode == 2) { rb0 = __ldg(bias + r0); rb1 = __ldg(bias + r0 + 8); }
        if (bias_mode >= 3) {
            rb0 = __ldg(bias + (size_t)bz * L1 + r0);
            rb1 = __ldg(bias + (size_t)bz * L1 + r0 + 8);
        }
        #pragma unroll
        for (int jj = 0; jj < 8; jj++) {
            const int col = col_base + jj * 8;
            float2 v0, v1;
            if (bias_mode >= 3) {
                float cb0 = 0.f, cb1 = 0.f;
                if (bias_mode == 4) {
                    const int bc = bcol_base + jj * 8;
                    cb0 = __ldg(bias2 + bc);
                    cb1 = __ldg(bias2 + bc + 1);
                }
                v0.x = acc[ii][jj][0] * rb0 + cb0;
                v0.y = acc[ii][jj][1] * rb0 + cb1;
                v1.x = acc[ii][jj][2] * rb1 + cb0;
                v1.y = acc[ii][jj][3] * rb1 + cb1;
            } else {
                float bx0, by0, bx1, by1;
                if (bias_mode == 1) {
                    const int bc = bcol_base + jj * 8;
                    float cb0 = __ldg(bias + bc), cb1 = __ldg(bias + bc + 1);
                    bx0 = cb0; by0 = cb1; bx1 = cb0; by1 = cb1;
                } else if (bias_mode == 2) {
                    bx0 = rb0; by0 = rb0; bx1 = rb1; by1 = rb1;
                } else {
                    bx0 = by0 = bx1 = by1 = 0.f;
                }
                v0.x = acc[ii][jj][0] * scale + bx0;
                v0.y = acc[ii][jj][1] * scale + by0;
                v1.x = acc[ii][jj][2] * scale + bx1;
                v1.y = acc[ii][jj][3] * scale + by1;
            }
            if (round_out) {
                *(__half2*)(Ch + (size_t)r0 * ldC + col) = __floats2half2_rn(v0.x, v0.y);
                *(__half2*)(Ch + (size_t)(r0 + 8) * ldC + col) = __floats2half2_rn(v1.x, v1.y);
            } else {
                *(float2*)(Cf + (size_t)r0 * ldC + col) = v0;
                *(float2*)(Cf + (size_t)(r0 + 8) * ldC + col) = v1;
            }
        }
    }
}

// ---- standalone GEMM (batched via blockIdx.z strides, element strides) ----
__global__ void __launch_bounds__(128, 2)
gemm_mma(const __half* __restrict__ A, const __half* __restrict__ B,
         const float* __restrict__ bias, const float* __restrict__ bias2,
         void* __restrict__ C,
         int K, int ldA, int ldB, int ldC,
         float scale, int round_out, int bias_mode,
         long long sA, long long sB, long long sC,
         int cSeg, long long cSegStride, float* __restrict__ rowpart) {
    extern __shared__ uint32_t sm[];
    void* Cz = round_out ? (void*)((__half*)C + (long long)blockIdx.z * sC)
                         : (void*)((float*)C + (long long)blockIdx.z * sC);
    gemm_body(A + (long long)blockIdx.z * sA, B + (long long)blockIdx.z * sB,
              bias, bias2, Cz, K, ldA, ldB, ldC, scale, round_out, bias_mode,
              blockIdx.x, blockIdx.y, blockIdx.z, cSeg, cSegStride, rowpart, sm);
}

// ---- fused {Q-proj, K-proj, uT} : 3072 CTAs, one tail wave ----
__global__ void __launch_bounds__(128, 2)
gemm_fused3(const __half* __restrict__ x1, const __half* __restrict__ wqT,
            const float* __restrict__ bq, __half* __restrict__ q,
            const __half* __restrict__ x2, const __half* __restrict__ wkT,
            const float* __restrict__ bk, __half* __restrict__ kk,
            const __half* __restrict__ w2T, __half* __restrict__ uT) {
    extern __shared__ uint32_t sm[];
    const int id = blockIdx.x >> 10;
    const int local = blockIdx.x & 1023;
    if (id == 0) {
        gemm_body(x1, wqT, bq, nullptr, q, D1, D1, D1, EDIM, 1.f, 1, 1,
                  local & 7, local >> 3, 0, 0, 0, nullptr, sm);
    } else if (id == 1) {
        gemm_body(x2, wkT, bk, nullptr, kk, D2, D2, D2, EDIM, 1.f, 1, 1,
                  local & 7, local >> 3, 0, 0, 0, nullptr, sm);
    } else {
        gemm_body(w2T, x2, nullptr, nullptr, uT, D2, D2, D2, L2, 1.f, 1, 0,
                  local & 127, local >> 7, 0, L2, (long long)D1 * L2, nullptr, sm);
    }
}

// ================= rowsum reduce: inv[r] = 1 / sum_x part[x][r] =================
__global__ __launch_bounds__(256)
void rowsum_reduce(const float* __restrict__ part, float* __restrict__ inv) {
    const int r = blockIdx.x * 256 + threadIdx.x;
    float s = 0.f;
    #pragma unroll
    for (int x = 0; x < 16; x++) s += part[(size_t)x * ROWS1 + r];
    inv[r] = 1.0f / s;
}

// ================= layernorm (both modalities, one launch) =================
static __device__ __forceinline__ float blockReduceSum256(float v) {
    __shared__ float sh[8];
    int lane = threadIdx.x & 31, w = threadIdx.x >> 5;
    #pragma unroll
    for (int o = 16; o > 0; o >>= 1) v += __shfl_xor_sync(0xffffffffu, v, o);
    __syncthreads();
    if (lane == 0) sh[w] = v;
    __syncthreads();
    if (w == 0) {
        v = (lane < 8) ? sh[lane] : 0.f;
        #pragma unroll
        for (int o = 4; o > 0; o >>= 1) v += __shfl_xor_sync(0xffffffffu, v, o);
        if (lane == 0) sh[0] = v;
    }
    __syncthreads();
    return sh[0];
}

template<int NV>
static __device__ __forceinline__ void ln_body(
    const float* __restrict__ x, const float* __restrict__ g,
    const float* __restrict__ b, __half* __restrict__ y, int D, int row) {
    const float* xr = x + (size_t)row * D;
    __half*      yr = y + (size_t)row * D;
    float v[NV];
    float s = 0.f;
    #pragma unroll
    for (int j = 0; j < NV; j++) { v[j] = xr[threadIdx.x + j * 256]; s += v[j]; }
    const float mu = blockReduceSum256(s) * (1.f / (float)D);
    float sq = 0.f;
    #pragma unroll
    for (int j = 0; j < NV; j++) { float d = v[j] - mu; sq += d * d; }
    const float rstd = rsqrtf(blockReduceSum256(sq) * (1.f / (float)D) + 1e-5f);
    #pragma unroll
    for (int j = 0; j < NV; j++) {
        int idx = threadIdx.x + j * 256;
        yr[idx] = __float2half_rn((v[j] - mu) * rstd * g[idx] + b[idx]);
    }
}

__global__ __launch_bounds__(256)
void layernorm_fused(const float* __restrict__ m1, const float* __restrict__ g1,
                     const float* __restrict__ b1, __half* __restrict__ y1,
                     const float* __restrict__ m2, const float* __restrict__ g2,
                     const float* __restrict__ b2, __half* __restrict__ y2) {
    if (blockIdx.x < ROWS1) ln_body<4>(m1, g1, b1, y1, D1, blockIdx.x);
    else                    ln_body<3>(m2, g2, b2, y2, D2, blockIdx.x - ROWS1);
}

// ================= transposes + Wv copy + c2, one launch =================
static __device__ __forceinline__ void transpose_body(
    const float* __restrict__ in, __half* __restrict__ out,
    int R, int C, int bx, int by) {
    __shared__ float tb[32][33];
    const int r0 = by * 32, c0 = bx * 32;
    const int tx = threadIdx.x & 31, ty = threadIdx.x >> 5;
    #pragma unroll
    for (int k = 0; k < 32; k += 8)
        tb[ty + k][tx] = in[(size_t)(r0 + ty + k) * C + c0 + tx];
    __syncthreads();
    #pragma unroll
    for (int k = 0; k < 32; k += 8)
        out[(size_t)(c0 + ty + k) * R + r0 + tx] = __float2half_rn(tb[tx][ty + k]);
}

__global__ __launch_bounds__(256)
void prep_kernel(const float* __restrict__ Wq, __half* __restrict__ wqT,
                 const float* __restrict__ Wk, __half* __restrict__ wkT,
                 const float* __restrict__ Wv, __half* __restrict__ wvH,
                 const float* __restrict__ Wo, __half* __restrict__ woT,
                 const float* __restrict__ bv, const float* __restrict__ bo,
                 float* __restrict__ c2) {
    int b = blockIdx.x;
    if (b < 1024) {
        transpose_body(Wq, wqT, D1, EDIM, b & 31, b >> 5);
    } else if (b < 1792) {
        b -= 1024;
        transpose_body(Wk, wkT, D2, EDIM, b & 31, b >> 5);
    } else if (b < 2560) {
        b -= 1792;                            // copy Wv [768,1024] to fp16
        const int r0 = (b >> 5) * 32, c0 = (b & 31) * 32;
        const int tx = threadIdx.x & 31, ty = threadIdx.x >> 5;
        #pragma unroll
        for (int k = 0; k < 32; k += 8) {
            size_t idx = (size_t)(r0 + ty + k) * EDIM + c0 + tx;
            wvH[idx] = __float2half_rn(Wv[idx]);
        }
    } else if (b < 3584) {
        b -= 2560;
        transpose_body(Wo, woT, EDIM, D1, b & 31, b >> 5);
    } else {
        b -= 3584;                            // c2[j] = bo[j] + sum_e bv[e]*Wo[e,j]
        const int j = b * 256 + threadIdx.x;
        float s = bo[j];
        #pragma unroll 8
        for (int e = 0; e < EDIM; e++) s += bv[e] * Wo[(size_t)e * D1 + j];
        c2[j] = s;
    }
}

// ================= launch =================
// Order: launch index 3 (ncu-profiled) = fused projection GEMM.
extern "C" void kernel_launch(void* const* d_in, const int* in_sizes, int n_in,
                              void* d_out, int out_size) {
    const float* modality1 = (const float*)d_in[0];
    const float* modality2 = (const float*)d_in[1];
    const float* ln1_g = (const float*)d_in[2];
    const float* ln1_b = (const float*)d_in[3];
    const float* ln2_g = (const float*)d_in[4];
    const float* ln2_b = (const float*)d_in[5];
    const float* Wq = (const float*)d_in[6];
    const float* bq = (const float*)d_in[7];
    const float* Wk = (const float*)d_in[8];
    const float* bk = (const float*)d_in[9];
    const float* Wv = (const float*)d_in[10];
    const float* bv = (const float*)d_in[11];
    const float* Wo = (const float*)d_in[12];
    const float* bo = (const float*)d_in[13];
    float* out = (float*)d_out;

    __half *x1, *x2, *q, *k, *uT, *s, *wqT, *wkT, *wvH, *woT, *w2T;
    float *rowpart, *inv, *c2;
    cudaGetSymbolAddress((void**)&x1, g_x1);
    cudaGetSymbolAddress((void**)&x2, g_x2);
    cudaGetSymbolAddress((void**)&q, g_q);
    cudaGetSymbolAddress((void**)&k, g_k);
    cudaGetSymbolAddress((void**)&uT, g_uT);
    cudaGetSymbolAddress((void**)&s, g_s);
    cudaGetSymbolAddress((void**)&wqT, g_wqT);
    cudaGetSymbolAddress((void**)&wkT, g_wkT);
    cudaGetSymbolAddress((void**)&wvH, g_wvH);
    cudaGetSymbolAddress((void**)&woT, g_woT);
    cudaGetSymbolAddress((void**)&w2T, g_w2T);
    cudaGetSymbolAddress((void**)&c2, g_c2);
    cudaGetSymbolAddress((void**)&rowpart, g_rowpart);
    cudaGetSymbolAddress((void**)&inv, g_inv);

    cudaFuncSetAttribute(gemm_mma, cudaFuncAttributeMaxDynamicSharedMemorySize, GSMEM);
    cudaFuncSetAttribute(gemm_fused3, cudaFuncAttributeMaxDynamicSharedMemorySize, GSMEM);

    const float scaling = 1.0f / 32.0f;   // E^-0.5

    // 0) weight transposes + Wv copy + c2  (3588 blocks)
    prep_kernel<<<3588, 256>>>(Wq, wqT, Wk, wkT, Wv, wvH, Wo, woT, bv, bo, c2);

    // 1) w2T[d1,d2] = (Wv@Wo)^T = woT @ wvH^T   (48 CTAs)
    gemm_mma<<<dim3(D2 / 128, D1 / 128), 128, GSMEM>>>(
        woT, wvH, nullptr, nullptr, w2T, EDIM, EDIM, EDIM, D2,
        1.f, 1, 0, 0, 0, 0, 0, 0, nullptr);

    // 2) both layernorms (32768 blocks)
    layernorm_fused<<<ROWS1 + ROWS2, 256>>>(modality1, ln1_g, ln1_b, x1,
                                            modality2, ln2_g, ln2_b, x2);

    // 3) fused {Q-proj, K-proj, uT}  <-- ncu-profiled launch index
    gemm_fused3<<<3072, 128, GSMEM>>>(x1, wqT, bq, q,
                                      x2, wkT, bk, k,
                                      w2T, uT);

    // 4) P = exp(scaling * Q @ K^T)  (batched; row-sum side-band -> rowpart)
    gemm_mma<<<dim3(L2 / 128, L1 / 128, BATCH), 128, GSMEM>>>(
        q, k, nullptr, nullptr, s, EDIM, EDIM, EDIM, L2, scaling, 1, 0,
        (long long)L1 * EDIM, (long long)L2 * EDIM, (long long)L1 * L2,
        0, 0, rowpart);

    // 5) inv[r] = 1 / rowsum
    rowsum_reduce<<<ROWS1 / 256, 256>>>(rowpart, inv);

    // 6) out = (P @ u) * inv[row] + c2[col]   (fp32 output)
    gemm_mma<<<dim3(D1 / 128, L1 / 128, BATCH), 128, GSMEM>>>(
        s, uT, inv, c2, out, L2, L2, L2, D1, 1.f, 0, 4,
        (long long)L1 * L2, (long long)D1 * L2, (long long)L1 * D1,
        0, 0, nullptr);
}

// round 17
// speedup vs baseline: 2.8643x; 1.0630x over previous
#include <cuda_runtime.h>
#include <cuda_fp16.h>
#include <math.h>
#include <stdint.h>

// ---------------- problem constants ----------------
#define BATCH 8
#define L1 2048
#define L2 2048
#define D1 1024
#define D2 768
#define EDIM 1024
#define ROWS1 (BATCH * L1)          // 16384
#define ROWS2 (BATCH * L2)          // 16384

// ---------------- scratch (device globals; no allocation) ----------------
__device__ __half g_x1[ROWS1 * D1];
__device__ __half g_x2[ROWS2 * D2];
__device__ __half g_q[ROWS1 * EDIM];
__device__ __half g_k[ROWS2 * EDIM];
__device__ __half g_uT[(size_t)BATCH * D1 * L2];   // [B][D1][L2] pitch 2048
__device__ __half g_s[(size_t)BATCH * L1 * L2];    // exp-scores (unnormalized)
__device__ __half g_wqT[EDIM * D1];
__device__ __half g_wkT[EDIM * D2];
__device__ __half g_wvH[D2 * EDIM];                // fp16 copy of Wv
__device__ __half g_woT[D1 * EDIM];
__device__ __half g_w2T[D1 * D2];                  // (Wv@Wo)^T
__device__ float g_c2[D1];                         // bv@Wo + bo
__device__ float g_rowpart[16 * ROWS1];

// ---------------- helpers ----------------
static __device__ __forceinline__ uint32_t smem_u32(const void* p) {
    uint32_t a;
    asm("{ .reg .u64 t; cvta.to.shared.u64 t, %1; cvt.u32.u64 %0, t; }" : "=r"(a) : "l"(p));
    return a;
}
static __device__ __forceinline__ void cp_async16(uint32_t saddr, const void* gptr) {
    asm volatile("cp.async.cg.shared.global [%0], [%1], 16;" :: "r"(saddr), "l"(gptr));
}
static __device__ __forceinline__ void cp_commit() {
    asm volatile("cp.async.commit_group;" ::: "memory");
}
template<int N>
static __device__ __forceinline__ void cp_wait() {
    asm volatile("cp.async.wait_group %0;" :: "n"(N) : "memory");
}
static __device__ __forceinline__ void ldsm_x4(uint32_t* r, uint32_t a) {
    asm volatile("ldmatrix.sync.aligned.m8n8.x4.shared.b16 {%0,%1,%2,%3}, [%4];"
                 : "=r"(r[0]), "=r"(r[1]), "=r"(r[2]), "=r"(r[3]) : "r"(a));
}

#define MMA_F16(d, a, b) \
    asm volatile("mma.sync.aligned.m16n8k16.row.col.f32.f16.f16.f32 " \
        "{%0,%1,%2,%3}, {%4,%5,%6,%7}, {%8,%9}, {%0,%1,%2,%3};" \
        : "+f"((d)[0]), "+f"((d)[1]), "+f"((d)[2]), "+f"((d)[3]) \
        : "r"((a)[0]), "r"((a)[1]), "r"((a)[2]), "r"((a)[3]), \
          "r"((b)[0]), "r"((b)[1]))

// ================= fp16 mma.sync GEMM body (R14 engine) =================
// C[M,N] = scale*(A[M,K] @ B[N,K]^T) + bias;  A,B fp16 K-major, pitches in halves.
// BM=128, BN=128, BK=64 halves. 128 threads = 4 warps (2x2), warp tile 64x64.
// 2-stage double buffer, 3 CTAs/SM, one barrier per K-chunk (4 k16-steps each).
// bias_mode: 0 none, 1 col bias, 2 row bias,
//            4 row MULTIPLIER computed inline from rowpart (bias=rowpart) + col
//              bias bias2[col]  (the attention-normalize epilogue).
// round_out: 1 -> C is __half, 0 -> C is float.
// rowpart != null: epilogue stores exp(scale*acc) as fp16 and per-CTA row sums.
#define ROWB 144                      // bytes per smem row
#define ASTG (128 * ROWB)             // bytes per A stage (18432)
#define STGB (2 * ASTG)               // bytes per stage (36864)
#define GSMEM (2 * STGB)              // 73728 bytes

static __device__ __forceinline__ void gemm_body(
    const __half* __restrict__ A, const __half* __restrict__ B,
    const float* __restrict__ bias, const float* __restrict__ bias2,
    void* __restrict__ Cv,
    int K, int ldA, int ldB, int ldC,
    float scale, int round_out, int bias_mode,
    int bx, int by, int bz,
    int cSeg, long long cSegStride, float* __restrict__ rowpart,
    uint32_t* sm) {
    const uint32_t sb = smem_u32(sm);
    const int tid = threadIdx.x;
    const int lane = tid & 31, warp = tid >> 5;
    const int g = lane >> 2, t = lane & 3;
    const int m0 = (warp >> 1) * 64;
    const int n0 = (warp & 1) * 64;

    A += (size_t)by * 128 * ldA;
    B += (size_t)bx * 128 * ldB;

    const int r_ld = tid >> 3;
    const int c16 = tid & 7;

    const int lsub = lane >> 3, lr = lane & 7;
    const uint32_t aoff = (uint32_t)((m0 + ((lsub & 1) << 3) + lr) * ROWB +
                                     ((lsub >> 1) << 4));
    const uint32_t boff = (uint32_t)(ASTG + (n0 + ((lsub >> 1) << 3) + lr) * ROWB +
                                     ((lsub & 1) << 4));

    float acc[4][8][4];
    #pragma unroll
    for (int i = 0; i < 4; i++)
        #pragma unroll
        for (int j = 0; j < 8; j++)
            #pragma unroll
            for (int e = 0; e < 4; e++) acc[i][j][e] = 0.f;

    const int nch = K >> 6;

    // prologue: chunk 0 -> stage 0
    #pragma unroll
    for (int f = 0; f < 8; f++) {
        int row = r_ld + f * 16;
        cp_async16(sb + row * ROWB + c16 * 16, A + (size_t)row * ldA + c16 * 8);
        cp_async16(sb + ASTG + row * ROWB + c16 * 16, B + (size_t)row * ldB + c16 * 8);
    }
    cp_commit();

    for (int i = 0; i < nch; i++) {
        cp_wait<0>();
        __syncthreads();
        {
            const int ic = i + 1;
            if (ic < nch) {
                const uint32_t stb = sb + (uint32_t)((ic & 1) * STGB);
                const int k0 = ic * 64;
                #pragma unroll
                for (int f = 0; f < 8; f++) {
                    int row = r_ld + f * 16;
                    cp_async16(stb + row * ROWB + c16 * 16,
                               A + (size_t)row * ldA + k0 + c16 * 8);
                    cp_async16(stb + ASTG + row * ROWB + c16 * 16,
                               B + (size_t)row * ldB + k0 + c16 * 8);
                }
            }
            cp_commit();
        }

        const uint32_t stBase = sb + (uint32_t)((i & 1) * STGB);
        #pragma unroll
        for (int ks = 0; ks < 4; ks++) {
            uint32_t af[4][4], bf[4][4];
            #pragma unroll
            for (int ii = 0; ii < 4; ii++)
                ldsm_x4(af[ii], stBase + aoff + ii * (16 * ROWB) + ks * 32);
            #pragma unroll
            for (int p = 0; p < 4; p++)
                ldsm_x4(bf[p], stBase + boff + p * (16 * ROWB) + ks * 32);
            #pragma unroll
            for (int ii = 0; ii < 4; ii++)
                #pragma unroll
                for (int jj = 0; jj < 8; jj++)
                    MMA_F16(acc[ii][jj], af[ii], &bf[jj >> 1][(jj & 1) * 2]);
        }
    }

    const int row_base = by * 128 + m0 + g;

    if (rowpart != nullptr) {
        // ---- exp epilogue with row-sum side-band (scores GEMM), fp16 out ----
        __half* C = (__half*)Cv;
        float rsum[8];
        #pragma unroll
        for (int e = 0; e < 8; e++) rsum[e] = 0.f;
        const int col_base = bx * 128 + n0 + t * 2;
        #pragma unroll
        for (int ii = 0; ii < 4; ii++) {
            const int r0 = row_base + ii * 16;
            #pragma unroll
            for (int jj = 0; jj < 8; jj++) {
                const int col = col_base + jj * 8;
                float e0 = __expf(acc[ii][jj][0] * scale);
                float e1 = __expf(acc[ii][jj][1] * scale);
                float e2 = __expf(acc[ii][jj][2] * scale);
                float e3 = __expf(acc[ii][jj][3] * scale);
                rsum[ii * 2 + 0] += e0 + e1;
                rsum[ii * 2 + 1] += e2 + e3;
                *(__half2*)(C + (size_t)r0 * ldC + col) = __floats2half2_rn(e0, e1);
                *(__half2*)(C + (size_t)(r0 + 8) * ldC + col) = __floats2half2_rn(e2, e3);
            }
        }
        #pragma unroll
        for (int e = 0; e < 8; e++) {
            rsum[e] += __shfl_xor_sync(0xffffffffu, rsum[e], 1);
            rsum[e] += __shfl_xor_sync(0xffffffffu, rsum[e], 2);
        }
        __syncthreads();
        float* smemRow = (float*)sm;
        smemRow[tid] = 0.f;
        __syncthreads();
        if (t == 0) {
            #pragma unroll
            for (int ii = 0; ii < 4; ii++) {
                atomicAdd(&smemRow[m0 + ii * 16 + g], rsum[ii * 2 + 0]);
                atomicAdd(&smemRow[m0 + ii * 16 + 8 + g], rsum[ii * 2 + 1]);
            }
        }
        __syncthreads();
        const size_t grow = (size_t)bz * L1 + by * 128 + tid;
        rowpart[(size_t)bx * ROWS1 + grow] = smemRow[tid];
        return;
    }

    // ---- bias_mode 4: compute per-row inv from rowpart (bias ptr) into smem ----
    float* smemInv = (float*)sm;
    if (bias_mode == 4) {
        __syncthreads();                 // all warps done with mainloop smem
        const size_t grow = (size_t)bz * L1 + by * 128 + tid;
        float ssum = 0.f;
        #pragma unroll
        for (int x = 0; x < 16; x++) ssum += bias[(size_t)x * ROWS1 + grow];
        smemInv[tid] = 1.0f / ssum;
        __syncthreads();
    }

    // ---- normal epilogue ----
    int colblk = bx * 128;
    __half* Ch = (__half*)Cv;
    float* Cf = (float*)Cv;
    if (cSeg > 0) {
        const int seg = colblk / cSeg;
        Ch += (long long)seg * cSegStride;
        colblk -= seg * cSeg;
    }
    const int col_base = colblk + n0 + t * 2;
    const int bcol_base = bx * 128 + n0 + t * 2;
    #pragma unroll
    for (int ii = 0; ii < 4; ii++) {
        const int r0 = row_base + ii * 16;
        float rb0 = 0.f, rb1 = 0.f;
        if (bias_mode == 2) { rb0 = __ldg(bias + r0); rb1 = __ldg(bias + r0 + 8); }
        if (bias_mode == 4) {
            rb0 = smemInv[m0 + ii * 16 + g];
            rb1 = smemInv[m0 + ii * 16 + 8 + g];
        }
        #pragma unroll
        for (int jj = 0; jj < 8; jj++) {
            const int col = col_base + jj * 8;
            float2 v0, v1;
            if (bias_mode == 4) {
                const int bc = bcol_base + jj * 8;
                float cb0 = __ldg(bias2 + bc);
                float cb1 = __ldg(bias2 + bc + 1);
                v0.x = acc[ii][jj][0] * rb0 + cb0;
                v0.y = acc[ii][jj][1] * rb0 + cb1;
                v1.x = acc[ii][jj][2] * rb1 + cb0;
                v1.y = acc[ii][jj][3] * rb1 + cb1;
            } else {
                float bx0, by0, bx1, by1;
                if (bias_mode == 1) {
                    const int bc = bcol_base + jj * 8;
                    float cb0 = __ldg(bias + bc), cb1 = __ldg(bias + bc + 1);
                    bx0 = cb0; by0 = cb1; bx1 = cb0; by1 = cb1;
                } else if (bias_mode == 2) {
                    bx0 = rb0; by0 = rb0; bx1 = rb1; by1 = rb1;
                } else {
                    bx0 = by0 = bx1 = by1 = 0.f;
                }
                v0.x = acc[ii][jj][0] * scale + bx0;
                v0.y = acc[ii][jj][1] * scale + by0;
                v1.x = acc[ii][jj][2] * scale + bx1;
                v1.y = acc[ii][jj][3] * scale + by1;
            }
            if (round_out) {
                *(__half2*)(Ch + (size_t)r0 * ldC + col) = __floats2half2_rn(v0.x, v0.y);
                *(__half2*)(Ch + (size_t)(r0 + 8) * ldC + col) = __floats2half2_rn(v1.x, v1.y);
            } else {
                *(float2*)(Cf + (size_t)r0 * ldC + col) = v0;
                *(float2*)(Cf + (size_t)(r0 + 8) * ldC + col) = v1;
            }
        }
    }
}

// ---- standalone GEMM (batched via blockIdx.z strides, element strides) ----
__global__ void __launch_bounds__(128, 3)
gemm_mma(const __half* __restrict__ A, const __half* __restrict__ B,
         const float* __restrict__ bias, const float* __restrict__ bias2,
         void* __restrict__ C,
         int K, int ldA, int ldB, int ldC,
         float scale, int round_out, int bias_mode,
         long long sA, long long sB, long long sC,
         int cSeg, long long cSegStride, float* __restrict__ rowpart) {
    extern __shared__ uint32_t sm[];
    void* Cz = round_out ? (void*)((__half*)C + (long long)blockIdx.z * sC)
                         : (void*)((float*)C + (long long)blockIdx.z * sC);
    gemm_body(A + (long long)blockIdx.z * sA, B + (long long)blockIdx.z * sB,
              bias, bias2, Cz, K, ldA, ldB, ldC, scale, round_out, bias_mode,
              blockIdx.x, blockIdx.y, blockIdx.z, cSeg, cSegStride, rowpart, sm);
}

// ---- fused {Q-proj, K-proj, uT} : 3072 CTAs, one tail wave ----
__global__ void __launch_bounds__(128, 3)
gemm_fused3(const __half* __restrict__ x1, const __half* __restrict__ wqT,
            const float* __restrict__ bq, __half* __restrict__ q,
            const __half* __restrict__ x2, const __half* __restrict__ wkT,
            const float* __restrict__ bk, __half* __restrict__ kk,
            const __half* __restrict__ w2T, __half* __restrict__ uT) {
    extern __shared__ uint32_t sm[];
    const int id = blockIdx.x >> 10;
    const int local = blockIdx.x & 1023;
    if (id == 0) {
        gemm_body(x1, wqT, bq, nullptr, q, D1, D1, D1, EDIM, 1.f, 1, 1,
                  local & 7, local >> 3, 0, 0, 0, nullptr, sm);
    } else if (id == 1) {
        gemm_body(x2, wkT, bk, nullptr, kk, D2, D2, D2, EDIM, 1.f, 1, 1,
                  local & 7, local >> 3, 0, 0, 0, nullptr, sm);
    } else {
        gemm_body(w2T, x2, nullptr, nullptr, uT, D2, D2, D2, L2, 1.f, 1, 0,
                  local & 127, local >> 7, 0, L2, (long long)D1 * L2, nullptr, sm);
    }
}

// ================= prep + layernorm, one launch =================
static __device__ __forceinline__ float blockReduceSum256(float v) {
    __shared__ float sh[8];
    int lane = threadIdx.x & 31, w = threadIdx.x >> 5;
    #pragma unroll
    for (int o = 16; o > 0; o >>= 1) v += __shfl_xor_sync(0xffffffffu, v, o);
    __syncthreads();
    if (lane == 0) sh[w] = v;
    __syncthreads();
    if (w == 0) {
        v = (lane < 8) ? sh[lane] : 0.f;
        #pragma unroll
        for (int o = 4; o > 0; o >>= 1) v += __shfl_xor_sync(0xffffffffu, v, o);
        if (lane == 0) sh[0] = v;
    }
    __syncthreads();
    return sh[0];
}

template<int NV>
static __device__ __forceinline__ void ln_body(
    const float* __restrict__ x, const float* __restrict__ g,
    const float* __restrict__ b, __half* __restrict__ y, int D, int row) {
    const float* xr = x + (size_t)row * D;
    __half*      yr = y + (size_t)row * D;
    float v[NV];
    float s = 0.f;
    #pragma unroll
    for (int j = 0; j < NV; j++) { v[j] = xr[threadIdx.x + j * 256]; s += v[j]; }
    const float mu = blockReduceSum256(s) * (1.f / (float)D);
    float sq = 0.f;
    #pragma unroll
    for (int j = 0; j < NV; j++) { float d = v[j] - mu; sq += d * d; }
    const float rstd = rsqrtf(blockReduceSum256(sq) * (1.f / (float)D) + 1e-5f);
    #pragma unroll
    for (int j = 0; j < NV; j++) {
        int idx = threadIdx.x + j * 256;
        yr[idx] = __float2half_rn((v[j] - mu) * rstd * g[idx] + b[idx]);
    }
}

static __device__ __forceinline__ void transpose_body(
    const float* __restrict__ in, __half* __restrict__ out,
    int R, int C, int bx, int by) {
    __shared__ float tb[32][33];
    const int r0 = by * 32, c0 = bx * 32;
    const int tx = threadIdx.x & 31, ty = threadIdx.x >> 5;
    #pragma unroll
    for (int k = 0; k < 32; k += 8)
        tb[ty + k][tx] = in[(size_t)(r0 + ty + k) * C + c0 + tx];
    __syncthreads();
    #pragma unroll
    for (int k = 0; k < 32; k += 8)
        out[(size_t)(c0 + ty + k) * R + r0 + tx] = __float2half_rn(tb[tx][ty + k]);
}

// blocks [0,3588): weight prep; [3588, 3588+32768): layernorms
__global__ __launch_bounds__(256)
void prep_ln_kernel(const float* __restrict__ Wq, __half* __restrict__ wqT,
                    const float* __restrict__ Wk, __half* __restrict__ wkT,
                    const float* __restrict__ Wv, __half* __restrict__ wvH,
                    const float* __restrict__ Wo, __half* __restrict__ woT,
                    const float* __restrict__ bv, const float* __restrict__ bo,
                    float* __restrict__ c2,
                    const float* __restrict__ m1, const float* __restrict__ g1,
                    const float* __restrict__ b1, __half* __restrict__ y1,
                    const float* __restrict__ m2, const float* __restrict__ g2,
                    const float* __restrict__ b2, __half* __restrict__ y2) {
    int b = blockIdx.x;
    if (b >= 3588) {
        b -= 3588;
        if (b < ROWS1) ln_body<4>(m1, g1, b1, y1, D1, b);
        else           ln_body<3>(m2, g2, b2, y2, D2, b - ROWS1);
        return;
    }
    if (b < 1024) {
        transpose_body(Wq, wqT, D1, EDIM, b & 31, b >> 5);
    } else if (b < 1792) {
        b -= 1024;
        transpose_body(Wk, wkT, D2, EDIM, b & 31, b >> 5);
    } else if (b < 2560) {
        b -= 1792;                            // copy Wv [768,1024] to fp16
        const int r0 = (b >> 5) * 32, c0 = (b & 31) * 32;
        const int tx = threadIdx.x & 31, ty = threadIdx.x >> 5;
        #pragma unroll
        for (int k = 0; k < 32; k += 8) {
            size_t idx = (size_t)(r0 + ty + k) * EDIM + c0 + tx;
            wvH[idx] = __float2half_rn(Wv[idx]);
        }
    } else if (b < 3584) {
        b -= 2560;
        transpose_body(Wo, woT, EDIM, D1, b & 31, b >> 5);
    } else {
        b -= 3584;                            // c2[j] = bo[j] + sum_e bv[e]*Wo[e,j]
        const int j = b * 256 + threadIdx.x;
        float s = bo[j];
        #pragma unroll 8
        for (int e = 0; e < EDIM; e++) s += bv[e] * Wo[(size_t)e * D1 + j];
        c2[j] = s;
    }
}

// ================= launch =================
// Order: launch index 3 (ncu-profiled) = scores GEMM.
extern "C" void kernel_launch(void* const* d_in, const int* in_sizes, int n_in,
                              void* d_out, int out_size) {
    const float* modality1 = (const float*)d_in[0];
    const float* modality2 = (const float*)d_in[1];
    const float* ln1_g = (const float*)d_in[2];
    const float* ln1_b = (const float*)d_in[3];
    const float* ln2_g = (const float*)d_in[4];
    const float* ln2_b = (const float*)d_in[5];
    const float* Wq = (const float*)d_in[6];
    const float* bq = (const float*)d_in[7];
    const float* Wk = (const float*)d_in[8];
    const float* bk = (const float*)d_in[9];
    const float* Wv = (const float*)d_in[10];
    const float* bv = (const float*)d_in[11];
    const float* Wo = (const float*)d_in[12];
    const float* bo = (const float*)d_in[13];
    float* out = (float*)d_out;

    __half *x1, *x2, *q, *k, *uT, *s, *wqT, *wkT, *wvH, *woT, *w2T;
    float *rowpart, *c2;
    cudaGetSymbolAddress((void**)&x1, g_x1);
    cudaGetSymbolAddress((void**)&x2, g_x2);
    cudaGetSymbolAddress((void**)&q, g_q);
    cudaGetSymbolAddress((void**)&k, g_k);
    cudaGetSymbolAddress((void**)&uT, g_uT);
    cudaGetSymbolAddress((void**)&s, g_s);
    cudaGetSymbolAddress((void**)&wqT, g_wqT);
    cudaGetSymbolAddress((void**)&wkT, g_wkT);
    cudaGetSymbolAddress((void**)&wvH, g_wvH);
    cudaGetSymbolAddress((void**)&woT, g_woT);
    cudaGetSymbolAddress((void**)&w2T, g_w2T);
    cudaGetSymbolAddress((void**)&c2, g_c2);
    cudaGetSymbolAddress((void**)&rowpart, g_rowpart);

    cudaFuncSetAttribute(gemm_mma, cudaFuncAttributeMaxDynamicSharedMemorySize, GSMEM);
    cudaFuncSetAttribute(gemm_fused3, cudaFuncAttributeMaxDynamicSharedMemorySize, GSMEM);

    const float scaling = 1.0f / 32.0f;   // E^-0.5

    // 0) weight prep + both layernorms (36356 blocks)
    prep_ln_kernel<<<3588 + ROWS1 + ROWS2, 256>>>(
        Wq, wqT, Wk, wkT, Wv, wvH, Wo, woT, bv, bo, c2,
        modality1, ln1_g, ln1_b, x1, modality2, ln2_g, ln2_b, x2);

    // 1) w2T[d1,d2] = (Wv@Wo)^T = woT @ wvH^T   (48 CTAs)
    gemm_mma<<<dim3(D2 / 128, D1 / 128), 128, GSMEM>>>(
        woT, wvH, nullptr, nullptr, w2T, EDIM, EDIM, EDIM, D2,
        1.f, 1, 0, 0, 0, 0, 0, 0, nullptr);

    // 2) fused {Q-proj, K-proj, uT}
    gemm_fused3<<<3072, 128, GSMEM>>>(x1, wqT, bq, q,
                                      x2, wkT, bk, k,
                                      w2T, uT);

    // 3) P = exp(scaling * Q @ K^T)  <-- ncu-profiled launch index
    gemm_mma<<<dim3(L2 / 128, L1 / 128, BATCH), 128, GSMEM>>>(
        q, k, nullptr, nullptr, s, EDIM, EDIM, EDIM, L2, scaling, 1, 0,
        (long long)L1 * EDIM, (long long)L2 * EDIM, (long long)L1 * L2,
        0, 0, rowpart);

    // 4) out = (P @ u) * inv[row] + c2[col]   (inv computed inline from rowpart)
    gemm_mma<<<dim3(D1 / 128, L1 / 128, BATCH), 128, GSMEM>>>(
        s, uT, rowpart, c2, out, L2, L2, L2, D1, 1.f, 0, 4,
        (long long)L1 * L2, (long long)D1 * L2, (long long)L1 * D1,
        0, 0, nullptr);
}